// round 1
// baseline (speedup 1.0000x reference)
#include <cuda_runtime.h>
#include <math.h>

#define SS 4096
#define DD 768
#define HH 12
#define DHH 64
#define NBB 64
#define BSS 64
#define RRR 3
#define FFF 3072
#define CCC 8

// ---------------- scratch (device globals; no allocation allowed) -----------
__device__ __align__(16) float g_h [SS*DD];
__device__ __align__(16) float g_q [SS*DD];
__device__ __align__(16) float g_k [SS*DD];
__device__ __align__(16) float g_v [SS*DD];
__device__ __align__(16) float g_t [SS*DD];   // attention concat output
__device__ __align__(16) float g_a [SS*DD];   // post-Wo / post-W2
__device__ __align__(16) float g_f1[SS*FFF];  // FFN intermediate

// ---------------- helpers ---------------------------------------------------
__device__ __forceinline__ void block_reduce2(float &s1v, float &s2v) {
    __shared__ float sa[8], sb[8];
    int lane = threadIdx.x & 31, w = threadIdx.x >> 5;
#pragma unroll
    for (int off = 16; off; off >>= 1) {
        s1v += __shfl_xor_sync(0xffffffffu, s1v, off);
        s2v += __shfl_xor_sync(0xffffffffu, s2v, off);
    }
    if (lane == 0) { sa[w] = s1v; sb[w] = s2v; }
    __syncthreads();
    if (w == 0) {
        s1v = (lane < 8) ? sa[lane] : 0.f;
        s2v = (lane < 8) ? sb[lane] : 0.f;
#pragma unroll
        for (int off = 4; off; off >>= 1) {
            s1v += __shfl_xor_sync(0xffffffffu, s1v, off);
            s2v += __shfl_xor_sync(0xffffffffu, s2v, off);
        }
        if (lane == 0) { sa[0] = s1v; sb[0] = s2v; }
    }
    __syncthreads();
    s1v = sa[0]; s2v = sb[0];
}

// ---------------- embedding + LN --------------------------------------------
__global__ __launch_bounds__(256) void embed_ln_kernel(
    const int* __restrict__ ids, const float* __restrict__ we,
    const float* __restrict__ pe, const float* __restrict__ w,
    const float* __restrict__ b, float* __restrict__ out)
{
    int row = blockIdx.x;
    int id = ids[row];
    float x[3], sum = 0.f, sq = 0.f;
#pragma unroll
    for (int r = 0; r < 3; r++) {
        int i = threadIdx.x + r * 256;
        x[r] = we[(long long)id * DD + i] + pe[row * DD + i];
        sum += x[r]; sq += x[r] * x[r];
    }
    block_reduce2(sum, sq);
    float mean = sum * (1.f / DD);
    float var  = sq  * (1.f / DD) - mean * mean;
    float inv  = rsqrtf(var + 1e-12f);
#pragma unroll
    for (int r = 0; r < 3; r++) {
        int i = threadIdx.x + r * 256;
        out[row * DD + i] = (x[r] - mean) * inv * w[i] + b[i];
    }
}

// ---------------- residual add + LN (in place into h) -----------------------
__global__ __launch_bounds__(256) void add_ln_kernel(
    float* __restrict__ h, const float* __restrict__ a,
    const float* __restrict__ w, const float* __restrict__ b)
{
    int row = blockIdx.x;
    float x[3], sum = 0.f, sq = 0.f;
#pragma unroll
    for (int r = 0; r < 3; r++) {
        int i = threadIdx.x + r * 256;
        x[r] = h[row * DD + i] + a[row * DD + i];
        sum += x[r]; sq += x[r] * x[r];
    }
    block_reduce2(sum, sq);
    float mean = sum * (1.f / DD);
    float var  = sq  * (1.f / DD) - mean * mean;
    float inv  = rsqrtf(var + 1e-12f);
#pragma unroll
    for (int r = 0; r < 3; r++) {
        int i = threadIdx.x + r * 256;
        h[row * DD + i] = (x[r] - mean) * inv * w[i] + b[i];
    }
}

// ---------------- SGEMM: C = A(MxK) * B(KxN) + bias [, gelu] ----------------
// BM=BN=128, BK=8, 256 threads, 8x8 per thread.
__global__ __launch_bounds__(256) void sgemm_bias(
    const float* __restrict__ A, const float* __restrict__ B,
    const float* __restrict__ bias, float* __restrict__ C,
    int M, int N, int K, int do_gelu)
{
    __shared__ __align__(16) float As[8][128];
    __shared__ __align__(16) float Bs[8][128];
    int tid = threadIdx.x;
    int tx = tid & 15, ty = tid >> 4;
    int row0 = blockIdx.y * 128, col0 = blockIdx.x * 128;
    int a_m = tid >> 1, a_k = (tid & 1) * 4;
    int b_k = tid >> 5, b_n = (tid & 31) * 4;
    const float* Aptr = A + (long long)(row0 + a_m) * K + a_k;
    const float* Bptr = B + (long long)b_k * N + col0 + b_n;

    float acc[8][8];
#pragma unroll
    for (int i = 0; i < 8; i++)
#pragma unroll
        for (int j = 0; j < 8; j++) acc[i][j] = 0.f;

    for (int k0 = 0; k0 < K; k0 += 8) {
        float4 av = *(const float4*)(Aptr + k0);
        As[a_k + 0][a_m] = av.x;
        As[a_k + 1][a_m] = av.y;
        As[a_k + 2][a_m] = av.z;
        As[a_k + 3][a_m] = av.w;
        *(float4*)&Bs[b_k][b_n] = *(const float4*)(Bptr + (long long)k0 * N);
        __syncthreads();
#pragma unroll
        for (int kk = 0; kk < 8; kk++) {
            float4 a0 = *(const float4*)&As[kk][ty * 8];
            float4 a1 = *(const float4*)&As[kk][ty * 8 + 4];
            float4 b0 = *(const float4*)&Bs[kk][tx * 8];
            float4 b1 = *(const float4*)&Bs[kk][tx * 8 + 4];
            float ar[8] = {a0.x, a0.y, a0.z, a0.w, a1.x, a1.y, a1.z, a1.w};
            float br[8] = {b0.x, b0.y, b0.z, b0.w, b1.x, b1.y, b1.z, b1.w};
#pragma unroll
            for (int i = 0; i < 8; i++)
#pragma unroll
                for (int j = 0; j < 8; j++)
                    acc[i][j] = fmaf(ar[i], br[j], acc[i][j]);
        }
        __syncthreads();
    }

#pragma unroll
    for (int i = 0; i < 8; i++) {
        int row = row0 + ty * 8 + i;
#pragma unroll
        for (int j = 0; j < 8; j++) {
            int col = col0 + tx * 8 + j;
            float val = acc[i][j] + bias[col];
            if (do_gelu) {
                float u = 0.7978845608028654f * (val + 0.044715f * val * val * val);
                val = 0.5f * val * (1.f + tanhf(u));
            }
            C[(long long)row * N + col] = val;
        }
    }
}

// ---------------- edge-block attention (blocks 0 and NB-1, full keys) -------
// grid: (H, 2, 8); 256 threads -> warp handles exactly one query.
__global__ __launch_bounds__(256) void attn_edge_kernel(
    const float* __restrict__ q, const float* __restrict__ k,
    const float* __restrict__ v, float* __restrict__ o)
{
    int h = blockIdx.x;
    int gb = blockIdx.y ? (NBB - 1) : 0;
    int warp = threadIdx.x >> 5, lane = threadIdx.x & 31;
    int qi = blockIdx.z * 8 + warp;
    int row = gb * BSS + qi;

    float2 qv = ((const float2*)(q + (long long)row * DD + h * DHH))[lane];
    float m = -1e30f, lsum = 0.f;
    float2 acc = make_float2(0.f, 0.f);

    for (int key = 0; key < SS; key++) {
        float2 kv = ((const float2*)(k + (long long)key * DD + h * DHH))[lane];
        float p = qv.x * kv.x + qv.y * kv.y;
#pragma unroll
        for (int off = 16; off; off >>= 1) p += __shfl_xor_sync(0xffffffffu, p, off);
        float s = p * 0.125f;
        float mn = fmaxf(m, s);
        float corr = __expf(m - mn);
        float pe   = __expf(s - mn);
        float2 vv = ((const float2*)(v + (long long)key * DD + h * DHH))[lane];
        lsum  = lsum * corr + pe;
        acc.x = acc.x * corr + pe * vv.x;
        acc.y = acc.y * corr + pe * vv.y;
        m = mn;
    }
    float inv = 1.f / lsum;
    ((float2*)(o + (long long)row * DD + h * DHH))[lane] = make_float2(acc.x * inv, acc.y * inv);
}

// ---------------- mid-block attention ---------------------------------------
// grid: (H, NB-2); 256 threads = 8 warps, each warp does 8 queries.
__global__ __launch_bounds__(256) void attn_mid_kernel(
    const float* __restrict__ q, const float* __restrict__ k,
    const float* __restrict__ v, const int* __restrict__ rnd,
    float* __restrict__ o)
{
    int h = blockIdx.x;
    int mb = blockIdx.y + 1;  // 1..NB-2
    int warp = threadIdx.x >> 5, lane = threadIdx.x & 31;

    int blk[8];
    blk[0] = 0; blk[1] = NBB - 1; blk[2] = mb - 1; blk[3] = mb; blk[4] = mb + 1;
    const int* rp = rnd + (h * NBB + mb) * RRR;
    blk[5] = rp[0]; blk[6] = rp[1]; blk[7] = rp[2];

    for (int qi = warp; qi < BSS; qi += 8) {
        int row = mb * BSS + qi;
        float2 qv = ((const float2*)(q + (long long)row * DD + h * DHH))[lane];
        float m = -1e30f, lsum = 0.f;
        float2 acc = make_float2(0.f, 0.f);
#pragma unroll 1
        for (int bi = 0; bi < 8; bi++) {
            const float* kb = k + (long long)(blk[bi] * BSS) * DD + h * DHH;
            const float* vb = v + (long long)(blk[bi] * BSS) * DD + h * DHH;
            for (int kk = 0; kk < BSS; kk++) {
                float2 kv = ((const float2*)(kb + (long long)kk * DD))[lane];
                float p = qv.x * kv.x + qv.y * kv.y;
#pragma unroll
                for (int off = 16; off; off >>= 1) p += __shfl_xor_sync(0xffffffffu, p, off);
                float s = p * 0.125f;
                float mn = fmaxf(m, s);
                float corr = __expf(m - mn);
                float pe   = __expf(s - mn);
                float2 vv = ((const float2*)(vb + (long long)kk * DD))[lane];
                lsum  = lsum * corr + pe;
                acc.x = acc.x * corr + pe * vv.x;
                acc.y = acc.y * corr + pe * vv.y;
                m = mn;
            }
        }
        float inv = 1.f / lsum;
        ((float2*)(o + (long long)row * DD + h * DHH))[lane] = make_float2(acc.x * inv, acc.y * inv);
    }
}

// ---------------- final classifier: out = h[last] @ Wc + bc -----------------
__global__ __launch_bounds__(256) void classifier_kernel(
    const float* __restrict__ h, const float* __restrict__ Wc,
    const float* __restrict__ bc, float* __restrict__ out)
{
    int warp = threadIdx.x >> 5, lane = threadIdx.x & 31;
    if (warp >= CCC) return;
    const float* hr = h + (long long)(SS - 1) * DD;
    float s = 0.f;
    for (int d = lane; d < DD; d += 32) s += hr[d] * Wc[d * CCC + warp];
#pragma unroll
    for (int off = 16; off; off >>= 1) s += __shfl_xor_sync(0xffffffffu, s, off);
    if (lane == 0) out[warp] = s + bc[warp];
}

// ---------------- launch -----------------------------------------------------
extern "C" void kernel_launch(void* const* d_in, const int* in_sizes, int n_in,
                              void* d_out, int out_size)
{
    (void)in_sizes; (void)n_in; (void)out_size;
    const int*   input_ids = (const int*)  d_in[0];
    const int*   rand_attn = (const int*)  d_in[1];
    const float* word_emb  = (const float*)d_in[2];
    const float* pos_emb   = (const float*)d_in[3];
    const float* eln_w     = (const float*)d_in[4];
    const float* eln_b     = (const float*)d_in[5];
    const float* Wq        = (const float*)d_in[6];
    const float* bq        = (const float*)d_in[7];
    const float* Wk        = (const float*)d_in[8];
    const float* bk        = (const float*)d_in[9];
    const float* Wv        = (const float*)d_in[10];
    const float* bv        = (const float*)d_in[11];
    const float* Wo        = (const float*)d_in[12];
    const float* bo        = (const float*)d_in[13];
    const float* ln1_w     = (const float*)d_in[14];
    const float* ln1_b     = (const float*)d_in[15];
    const float* W1        = (const float*)d_in[16];
    const float* b1        = (const float*)d_in[17];
    const float* W2        = (const float*)d_in[18];
    const float* b2        = (const float*)d_in[19];
    const float* ln2_w     = (const float*)d_in[20];
    const float* ln2_b     = (const float*)d_in[21];
    const float* Wc        = (const float*)d_in[22];
    const float* bc        = (const float*)d_in[23];
    float* out = (float*)d_out;

    float *h, *q, *k, *v, *t, *a, *f1;
    cudaGetSymbolAddress((void**)&h,  g_h);
    cudaGetSymbolAddress((void**)&q,  g_q);
    cudaGetSymbolAddress((void**)&k,  g_k);
    cudaGetSymbolAddress((void**)&v,  g_v);
    cudaGetSymbolAddress((void**)&t,  g_t);
    cudaGetSymbolAddress((void**)&a,  g_a);
    cudaGetSymbolAddress((void**)&f1, g_f1);

    embed_ln_kernel<<<SS, 256>>>(input_ids, word_emb, pos_emb, eln_w, eln_b, h);

    for (int l = 0; l < 2; l++) {
        long long wofs = (long long)l * DD * DD;
        sgemm_bias<<<dim3(DD/128, SS/128), 256>>>(h, Wq + wofs, bq + l*DD, q, SS, DD, DD, 0);
        sgemm_bias<<<dim3(DD/128, SS/128), 256>>>(h, Wk + wofs, bk + l*DD, k, SS, DD, DD, 0);
        sgemm_bias<<<dim3(DD/128, SS/128), 256>>>(h, Wv + wofs, bv + l*DD, v, SS, DD, DD, 0);

        attn_edge_kernel<<<dim3(HH, 2, 8), 256>>>(q, k, v, t);
        attn_mid_kernel<<<dim3(HH, NBB - 2), 256>>>(q, k, v, rand_attn + l*HH*NBB*RRR, t);

        sgemm_bias<<<dim3(DD/128, SS/128), 256>>>(t, Wo + wofs, bo + l*DD, a, SS, DD, DD, 0);
        add_ln_kernel<<<SS, 256>>>(h, a, ln1_w + l*DD, ln1_b + l*DD);

        sgemm_bias<<<dim3(FFF/128, SS/128), 256>>>(h, W1 + (long long)l*DD*FFF, b1 + l*FFF, f1, SS, FFF, DD, 1);
        sgemm_bias<<<dim3(DD/128, SS/128), 256>>>(f1, W2 + (long long)l*FFF*DD, b2 + l*DD, a, SS, DD, FFF, 0);
        add_ln_kernel<<<SS, 256>>>(h, a, ln2_w + l*DD, ln2_b + l*DD);
    }

    classifier_kernel<<<1, 256>>>(h, Wc, bc, out);
}

// round 3
// speedup vs baseline: 1.7082x; 1.7082x over previous
#include <cuda_runtime.h>
#include <cuda_bf16.h>
#include <math.h>
#include <stdint.h>

#define SS 4096
#define DD 768
#define HH 12
#define DHH 64
#define NBB 64
#define BSS 64
#define RRR 3
#define FFF 3072
#define CCC 8
#define NQKV 2304

// ---------------- scratch (device globals; no allocation allowed) -----------
__device__ __align__(16) float g_h  [SS*DD];
__device__ __align__(16) float g_a  [SS*DD];
__device__ __align__(16) float g_qkv[SS*NQKV];
__device__ __align__(16) __nv_bfloat16 g_ah[SS*FFF];
__device__ __align__(16) __nv_bfloat16 g_al[SS*FFF];
__device__ __align__(16) __nv_bfloat16 g_bh[SS*FFF];
__device__ __align__(16) __nv_bfloat16 g_bl[SS*FFF];
__device__ __align__(16) __nv_bfloat16 g_wh[FFF*DD];
__device__ __align__(16) __nv_bfloat16 g_wl[FFF*DD];
__device__ __align__(16) float g_bias3[NQKV];

// ---------------- PTX helpers ------------------------------------------------
__device__ __forceinline__ uint32_t smem_u32(const void* p) {
    uint32_t a;
    asm("{ .reg .u64 t; cvta.to.shared.u64 t, %1; cvt.u32.u64 %0, t; }" : "=r"(a) : "l"(p));
    return a;
}
__device__ __forceinline__ void ldsm_x4(uint32_t addr, uint32_t* r) {
    asm volatile("ldmatrix.sync.aligned.m8n8.x4.shared.b16 {%0,%1,%2,%3}, [%4];"
        : "=r"(r[0]), "=r"(r[1]), "=r"(r[2]), "=r"(r[3]) : "r"(addr));
}
__device__ __forceinline__ void mma_bf16(float* c, const uint32_t* a, const uint32_t* b) {
    asm volatile("mma.sync.aligned.m16n8k16.row.col.f32.bf16.bf16.f32 "
        "{%0,%1,%2,%3}, {%4,%5,%6,%7}, {%8,%9}, {%0,%1,%2,%3};"
        : "+f"(c[0]), "+f"(c[1]), "+f"(c[2]), "+f"(c[3])
        : "r"(a[0]), "r"(a[1]), "r"(a[2]), "r"(a[3]), "r"(b[0]), "r"(b[1]));
}
#define CP_ASYNC(dst, src) asm volatile("cp.async.cg.shared.global [%0], [%1], 16;" :: "r"(dst), "l"(src))
#define CP_COMMIT()        asm volatile("cp.async.commit_group;")
#define CP_WAIT(n)         asm volatile("cp.async.wait_group %0;" :: "n"(n))

// ---------------- bf16x3 GEMM via mma.sync -----------------------------------
// C[M,N] = (Ah+Al)[M,K] * ((Bh+Bl)[N,K])^T + bias. modes: 0 fp32, 1 gelu fp32,
// 2 gelu + split bf16 hi/lo output.
// BM=BN=128, BK=64, 256 threads (8 warps: 2m x 4n), double-buffered cp.async.
#define GEMM_SMEM 131072

__global__ void __launch_bounds__(256, 1)
gemm_mma(const __nv_bfloat16* __restrict__ Ah, const __nv_bfloat16* __restrict__ Al,
         const __nv_bfloat16* __restrict__ Bh, const __nv_bfloat16* __restrict__ Bl,
         const float* __restrict__ bias, float* __restrict__ C,
         __nv_bfloat16* __restrict__ Oh, __nv_bfloat16* __restrict__ Ol,
         int M, int N, int K, int mode)
{
    extern __shared__ __align__(128) char smem[];
    uint32_t sb = smem_u32(smem);
    int tid = threadIdx.x, lane = tid & 31, wid = tid >> 5;
    int wm = wid & 1, wn = wid >> 1;
    int n0 = blockIdx.x * 128, m0 = blockIdx.y * 128;
    const int KT = K >> 6;

    const __nv_bfloat16* s0 = Ah + (size_t)m0 * K;
    const __nv_bfloat16* s1 = Al + (size_t)m0 * K;
    const __nv_bfloat16* s2 = Bh + (size_t)n0 * K;
    const __nv_bfloat16* s3 = Bl + (size_t)n0 * K;

    float acc[4][4][4];
#pragma unroll
    for (int i = 0; i < 4; i++)
#pragma unroll
        for (int j = 0; j < 4; j++)
#pragma unroll
            for (int u = 0; u < 4; u++) acc[i][j][u] = 0.f;

#define LOAD_STAGE(S, KT_IDX) do {                                              \
    uint32_t sbase_ = sb + (S) * 65536;                                         \
    int ko_ = (KT_IDX) * 64;                                                    \
    _Pragma("unroll")                                                           \
    for (int t_ = 0; t_ < 4; t_++) {                                            \
        const __nv_bfloat16* sp_ = (t_ == 0) ? s0 : (t_ == 1) ? s1 : (t_ == 2) ? s2 : s3; \
        _Pragma("unroll")                                                       \
        for (int i_ = 0; i_ < 4; i_++) {                                        \
            int id_ = tid + i_ * 256;                                           \
            int row_ = id_ >> 3, c_ = id_ & 7;                                  \
            const __nv_bfloat16* src_ = sp_ + (size_t)row_ * K + ko_ + c_ * 8;  \
            uint32_t dst_ = sbase_ + t_ * 16384 + row_ * 128 + ((c_ ^ (row_ & 7)) << 4); \
            CP_ASYNC(dst_, src_);                                               \
        }                                                                       \
    }                                                                           \
    CP_COMMIT();                                                                \
} while (0)

    LOAD_STAGE(0, 0);

    for (int kt = 0; kt < KT; kt++) {
        if (kt + 1 < KT) { LOAD_STAGE((kt + 1) & 1, kt + 1); CP_WAIT(1); }
        else             { CP_WAIT(0); }
        __syncthreads();
        uint32_t st = sb + (kt & 1) * 65536;
#pragma unroll
        for (int ks = 0; ks < 4; ks++) {
            uint32_t ahf[4][4], alf[4][4], bhf[2][4], blf[2][4];
#pragma unroll
            for (int mt = 0; mt < 4; mt++) {
                int row = wm * 64 + mt * 16 + (lane & 15);
                int kc = ks * 2 + (lane >> 4);
                uint32_t off = row * 128 + ((kc ^ (row & 7)) << 4);
                ldsm_x4(st + off, ahf[mt]);
                ldsm_x4(st + 16384 + off, alf[mt]);
            }
#pragma unroll
            for (int np = 0; np < 2; np++) {
                int row = wn * 32 + np * 16 + ((lane & 7) | ((lane & 16) >> 1));
                int kc = ks * 2 + ((lane >> 3) & 1);
                uint32_t off = row * 128 + ((kc ^ (row & 7)) << 4);
                ldsm_x4(st + 32768 + off, bhf[np]);
                ldsm_x4(st + 49152 + off, blf[np]);
            }
#pragma unroll
            for (int mt = 0; mt < 4; mt++)
#pragma unroll
                for (int nt = 0; nt < 4; nt++) {
                    const uint32_t* bh_ = &bhf[nt >> 1][(nt & 1) * 2];
                    const uint32_t* bl_ = &blf[nt >> 1][(nt & 1) * 2];
                    mma_bf16(acc[mt][nt], ahf[mt], bh_);
                    mma_bf16(acc[mt][nt], ahf[mt], bl_);
                    mma_bf16(acc[mt][nt], alf[mt], bh_);
                }
        }
        __syncthreads();
    }

    // epilogue
#pragma unroll
    for (int mt = 0; mt < 4; mt++) {
        int mbase = m0 + wm * 64 + mt * 16 + (lane >> 2);
#pragma unroll
        for (int nt = 0; nt < 4; nt++) {
            int n = n0 + wn * 32 + nt * 8 + (lane & 3) * 2;
            float b0 = bias[n], b1 = bias[n + 1];
#pragma unroll
            for (int half = 0; half < 2; half++) {
                int m = mbase + half * 8;
                float v0 = acc[mt][nt][half * 2 + 0] + b0;
                float v1 = acc[mt][nt][half * 2 + 1] + b1;
                if (mode >= 1) {
                    float u0 = 0.7978845608028654f * (v0 + 0.044715f * v0 * v0 * v0);
                    v0 = 0.5f * v0 * (1.f + tanhf(u0));
                    float u1 = 0.7978845608028654f * (v1 + 0.044715f * v1 * v1 * v1);
                    v1 = 0.5f * v1 * (1.f + tanhf(u1));
                }
                if (mode == 2) {
                    __nv_bfloat16 h0 = __float2bfloat16(v0), h1 = __float2bfloat16(v1);
                    __nv_bfloat16 l0 = __float2bfloat16(v0 - __bfloat162float(h0));
                    __nv_bfloat16 l1 = __float2bfloat16(v1 - __bfloat162float(h1));
                    *(__nv_bfloat162*)(Oh + (size_t)m * N + n) = __nv_bfloat162(h0, h1);
                    *(__nv_bfloat162*)(Ol + (size_t)m * N + n) = __nv_bfloat162(l0, l1);
                } else {
                    float2 o; o.x = v0; o.y = v1;
                    *(float2*)(C + (size_t)m * N + n) = o;
                }
            }
        }
    }
}

// ---------------- W[K,N] fp32 -> Wt[N,K] bf16 hi/lo --------------------------
__global__ __launch_bounds__(256) void conv_wt(const float* __restrict__ W,
    __nv_bfloat16* __restrict__ th, __nv_bfloat16* __restrict__ tl, int K, int N)
{
    __shared__ float tile[32][33];
    int k0 = blockIdx.y * 32, n0 = blockIdx.x * 32;
    int tx = threadIdx.x & 31, ty = threadIdx.x >> 5;
#pragma unroll
    for (int r = ty; r < 32; r += 8)
        tile[r][tx] = W[(size_t)(k0 + r) * N + n0 + tx];
    __syncthreads();
#pragma unroll
    for (int r = ty; r < 32; r += 8) {
        float v = tile[tx][r];
        __nv_bfloat16 hh = __float2bfloat16(v);
        size_t o = (size_t)(n0 + r) * K + k0 + tx;
        th[o] = hh;
        tl[o] = __float2bfloat16(v - __bfloat162float(hh));
    }
}

__global__ __launch_bounds__(256) void concat3(const float* __restrict__ a,
    const float* __restrict__ b, const float* __restrict__ c, float* __restrict__ o)
{
    int i = blockIdx.x * 256 + threadIdx.x;
    if (i < DD) { o[i] = a[i]; o[DD + i] = b[i]; o[2 * DD + i] = c[i]; }
}

// ---------------- reductions -------------------------------------------------
__device__ __forceinline__ void block_reduce2(float &s1v, float &s2v) {
    __shared__ float sa[8], sb2[8];
    int lane = threadIdx.x & 31, w = threadIdx.x >> 5;
#pragma unroll
    for (int off = 16; off; off >>= 1) {
        s1v += __shfl_xor_sync(0xffffffffu, s1v, off);
        s2v += __shfl_xor_sync(0xffffffffu, s2v, off);
    }
    if (lane == 0) { sa[w] = s1v; sb2[w] = s2v; }
    __syncthreads();
    if (w == 0) {
        s1v = (lane < 8) ? sa[lane] : 0.f;
        s2v = (lane < 8) ? sb2[lane] : 0.f;
#pragma unroll
        for (int off = 4; off; off >>= 1) {
            s1v += __shfl_xor_sync(0xffffffffu, s1v, off);
            s2v += __shfl_xor_sync(0xffffffffu, s2v, off);
        }
        if (lane == 0) { sa[0] = s1v; sb2[0] = s2v; }
    }
    __syncthreads();
    s1v = sa[0]; s2v = sb2[0];
}

__device__ __forceinline__ void write_split(__nv_bfloat16* hi, __nv_bfloat16* lo,
                                            int idx, float v) {
    __nv_bfloat16 h = __float2bfloat16(v);
    hi[idx] = h;
    lo[idx] = __float2bfloat16(v - __bfloat162float(h));
}

// ---------------- embedding + LN (split out) ---------------------------------
__global__ __launch_bounds__(256) void embed_ln_split(
    const int* __restrict__ ids, const float* __restrict__ we,
    const float* __restrict__ pe, const float* __restrict__ w,
    const float* __restrict__ b, float* __restrict__ out,
    __nv_bfloat16* __restrict__ oh, __nv_bfloat16* __restrict__ ol)
{
    int row = blockIdx.x;
    int id = ids[row];
    float x[3], sum = 0.f, sq = 0.f;
#pragma unroll
    for (int r = 0; r < 3; r++) {
        int i = threadIdx.x + r * 256;
        x[r] = we[(long long)id * DD + i] + pe[row * DD + i];
        sum += x[r]; sq += x[r] * x[r];
    }
    block_reduce2(sum, sq);
    float mean = sum * (1.f / DD);
    float var  = sq * (1.f / DD) - mean * mean;
    float inv  = rsqrtf(var + 1e-12f);
#pragma unroll
    for (int r = 0; r < 3; r++) {
        int i = threadIdx.x + r * 256;
        float y = (x[r] - mean) * inv * w[i] + b[i];
        out[row * DD + i] = y;
        write_split(oh, ol, row * DD + i, y);
    }
}

// ---------------- residual add + LN (split out) -------------------------------
__global__ __launch_bounds__(256) void add_ln_split(
    float* __restrict__ h, const float* __restrict__ a,
    const float* __restrict__ w, const float* __restrict__ b,
    __nv_bfloat16* __restrict__ oh, __nv_bfloat16* __restrict__ ol)
{
    int row = blockIdx.x;
    float x[3], sum = 0.f, sq = 0.f;
#pragma unroll
    for (int r = 0; r < 3; r++) {
        int i = threadIdx.x + r * 256;
        x[r] = h[row * DD + i] + a[row * DD + i];
        sum += x[r]; sq += x[r] * x[r];
    }
    block_reduce2(sum, sq);
    float mean = sum * (1.f / DD);
    float var  = sq * (1.f / DD) - mean * mean;
    float inv  = rsqrtf(var + 1e-12f);
#pragma unroll
    for (int r = 0; r < 3; r++) {
        int i = threadIdx.x + r * 256;
        float y = (x[r] - mean) * inv * w[i] + b[i];
        h[row * DD + i] = y;
        write_split(oh, ol, row * DD + i, y);
    }
}

// ---------------- edge-block attention (blocks 0 and NB-1, full keys) --------
__global__ __launch_bounds__(256) void attn_edge_kernel(
    const float* __restrict__ qkv, __nv_bfloat16* __restrict__ th,
    __nv_bfloat16* __restrict__ tl)
{
    int hd = blockIdx.x;
    int gb = blockIdx.y ? (NBB - 1) : 0;
    int warp = threadIdx.x >> 5, lane = threadIdx.x & 31;
    int qi = blockIdx.z * 8 + warp;
    int row = gb * BSS + qi;

    const float* q = qkv;
    const float* k = qkv + DD;
    const float* v = qkv + 2 * DD;

    float2 qv = ((const float2*)(q + (long long)row * NQKV + hd * DHH))[lane];
    float m = -1e30f, lsum = 0.f;
    float2 acc = make_float2(0.f, 0.f);

    for (int key = 0; key < SS; key++) {
        float2 kv = ((const float2*)(k + (long long)key * NQKV + hd * DHH))[lane];
        float p = qv.x * kv.x + qv.y * kv.y;
#pragma unroll
        for (int off = 16; off; off >>= 1) p += __shfl_xor_sync(0xffffffffu, p, off);
        float s = p * 0.125f;
        float mn = fmaxf(m, s);
        float corr = __expf(m - mn);
        float pe   = __expf(s - mn);
        float2 vv = ((const float2*)(v + (long long)key * NQKV + hd * DHH))[lane];
        lsum  = lsum * corr + pe;
        acc.x = acc.x * corr + pe * vv.x;
        acc.y = acc.y * corr + pe * vv.y;
        m = mn;
    }
    float inv = 1.f / lsum;
    int oidx = row * DD + hd * DHH + lane * 2;
    write_split(th, tl, oidx,     acc.x * inv);
    write_split(th, tl, oidx + 1, acc.y * inv);
}

// ---------------- mid-block attention -----------------------------------------
__global__ __launch_bounds__(256) void attn_mid_kernel(
    const float* __restrict__ qkv, const int* __restrict__ rnd,
    __nv_bfloat16* __restrict__ th, __nv_bfloat16* __restrict__ tl)
{
    int hd = blockIdx.x;
    int mb = blockIdx.y + 1;
    int warp = threadIdx.x >> 5, lane = threadIdx.x & 31;

    const float* q = qkv;
    const float* k = qkv + DD;
    const float* v = qkv + 2 * DD;

    int blk[8];
    blk[0] = 0; blk[1] = NBB - 1; blk[2] = mb - 1; blk[3] = mb; blk[4] = mb + 1;
    const int* rp = rnd + (hd * NBB + mb) * RRR;
    blk[5] = rp[0]; blk[6] = rp[1]; blk[7] = rp[2];

    for (int qi = warp; qi < BSS; qi += 8) {
        int row = mb * BSS + qi;
        float2 qv = ((const float2*)(q + (long long)row * NQKV + hd * DHH))[lane];
        float m = -1e30f, lsum = 0.f;
        float2 acc = make_float2(0.f, 0.f);
#pragma unroll 1
        for (int bi = 0; bi < 8; bi++) {
            const float* kb = k + (long long)(blk[bi] * BSS) * NQKV + hd * DHH;
            const float* vb = v + (long long)(blk[bi] * BSS) * NQKV + hd * DHH;
            for (int kk = 0; kk < BSS; kk++) {
                float2 kv = ((const float2*)(kb + (long long)kk * NQKV))[lane];
                float p = qv.x * kv.x + qv.y * kv.y;
#pragma unroll
                for (int off = 16; off; off >>= 1) p += __shfl_xor_sync(0xffffffffu, p, off);
                float s = p * 0.125f;
                float mn = fmaxf(m, s);
                float corr = __expf(m - mn);
                float pe   = __expf(s - mn);
                float2 vv = ((const float2*)(vb + (long long)kk * NQKV))[lane];
                lsum  = lsum * corr + pe;
                acc.x = acc.x * corr + pe * vv.x;
                acc.y = acc.y * corr + pe * vv.y;
                m = mn;
            }
        }
        float inv = 1.f / lsum;
        int oidx = row * DD + hd * DHH + lane * 2;
        write_split(th, tl, oidx,     acc.x * inv);
        write_split(th, tl, oidx + 1, acc.y * inv);
    }
}

// ---------------- classifier --------------------------------------------------
__global__ __launch_bounds__(256) void classifier_kernel(
    const float* __restrict__ h, const float* __restrict__ Wc,
    const float* __restrict__ bc, float* __restrict__ out)
{
    int warp = threadIdx.x >> 5, lane = threadIdx.x & 31;
    if (warp >= CCC) return;
    const float* hr = h + (long long)(SS - 1) * DD;
    float s = 0.f;
    for (int d = lane; d < DD; d += 32) s += hr[d] * Wc[d * CCC + warp];
#pragma unroll
    for (int off = 16; off; off >>= 1) s += __shfl_xor_sync(0xffffffffu, s, off);
    if (lane == 0) out[warp] = s + bc[warp];
}

// ---------------- launch ------------------------------------------------------
extern "C" void kernel_launch(void* const* d_in, const int* in_sizes, int n_in,
                              void* d_out, int out_size)
{
    (void)in_sizes; (void)n_in; (void)out_size;
    const int*   input_ids = (const int*)  d_in[0];
    const int*   rand_attn = (const int*)  d_in[1];
    const float* word_emb  = (const float*)d_in[2];
    const float* pos_emb   = (const float*)d_in[3];
    const float* eln_w     = (const float*)d_in[4];
    const float* eln_b     = (const float*)d_in[5];
    const float* Wq        = (const float*)d_in[6];
    const float* bq        = (const float*)d_in[7];
    const float* Wk        = (const float*)d_in[8];
    const float* bk        = (const float*)d_in[9];
    const float* Wv        = (const float*)d_in[10];
    const float* bv        = (const float*)d_in[11];
    const float* Wo        = (const float*)d_in[12];
    const float* bo        = (const float*)d_in[13];
    const float* ln1_w     = (const float*)d_in[14];
    const float* ln1_b     = (const float*)d_in[15];
    const float* W1        = (const float*)d_in[16];
    const float* b1        = (const float*)d_in[17];
    const float* W2        = (const float*)d_in[18];
    const float* b2        = (const float*)d_in[19];
    const float* ln2_w     = (const float*)d_in[20];
    const float* ln2_b     = (const float*)d_in[21];
    const float* Wc        = (const float*)d_in[22];
    const float* bc        = (const float*)d_in[23];
    float* out = (float*)d_out;

    cudaFuncSetAttribute(gemm_mma, cudaFuncAttributeMaxDynamicSharedMemorySize, GEMM_SMEM);

    float *h, *a, *qkv, *bias3;
    __nv_bfloat16 *ah, *al, *bh, *bl, *wh, *wl;
    cudaGetSymbolAddress((void**)&h,    g_h);
    cudaGetSymbolAddress((void**)&a,    g_a);
    cudaGetSymbolAddress((void**)&qkv,  g_qkv);
    cudaGetSymbolAddress((void**)&ah,   g_ah);
    cudaGetSymbolAddress((void**)&al,   g_al);
    cudaGetSymbolAddress((void**)&bh,   g_bh);
    cudaGetSymbolAddress((void**)&bl,   g_bl);
    cudaGetSymbolAddress((void**)&wh,   g_wh);
    cudaGetSymbolAddress((void**)&wl,   g_wl);
    cudaGetSymbolAddress((void**)&bias3, g_bias3);

    embed_ln_split<<<SS, 256>>>(input_ids, word_emb, pos_emb, eln_w, eln_b, h, ah, al);

    for (int l = 0; l < 2; l++) {
        long long wofs = (long long)l * DD * DD;

        // ---- fused QKV projection ----
        conv_wt<<<dim3(DD/32, DD/32), 256>>>(Wq + wofs, wh,              wl,              DD, DD);
        conv_wt<<<dim3(DD/32, DD/32), 256>>>(Wk + wofs, wh + DD*DD,      wl + DD*DD,      DD, DD);
        conv_wt<<<dim3(DD/32, DD/32), 256>>>(Wv + wofs, wh + 2*DD*DD,    wl + 2*DD*DD,    DD, DD);
        concat3<<<3, 256>>>(bq + l*DD, bk + l*DD, bv + l*DD, bias3);
        gemm_mma<<<dim3(NQKV/128, SS/128), 256, GEMM_SMEM>>>(
            ah, al, wh, wl, bias3, qkv, nullptr, nullptr, SS, NQKV, DD, 0);

        // ---- attention (writes split bf16 into ah/al) ----
        attn_edge_kernel<<<dim3(HH, 2, 8), 256>>>(qkv, ah, al);
        attn_mid_kernel<<<dim3(HH, NBB - 2), 256>>>(qkv, rand_attn + l*HH*NBB*RRR, ah, al);

        // ---- O projection + LN ----
        conv_wt<<<dim3(DD/32, DD/32), 256>>>(Wo + wofs, wh, wl, DD, DD);
        gemm_mma<<<dim3(DD/128, SS/128), 256, GEMM_SMEM>>>(
            ah, al, wh, wl, bo + l*DD, a, nullptr, nullptr, SS, DD, DD, 0);
        add_ln_split<<<SS, 256>>>(h, a, ln1_w + l*DD, ln1_b + l*DD, ah, al);

        // ---- FFN ----
        conv_wt<<<dim3(FFF/32, DD/32), 256>>>(W1 + (long long)l*DD*FFF, wh, wl, DD, FFF);
        gemm_mma<<<dim3(FFF/128, SS/128), 256, GEMM_SMEM>>>(
            ah, al, wh, wl, b1 + l*FFF, nullptr, bh, bl, SS, FFF, DD, 2);
        conv_wt<<<dim3(DD/32, FFF/32), 256>>>(W2 + (long long)l*FFF*DD, wh, wl, FFF, DD);
        gemm_mma<<<dim3(DD/128, SS/128), 256, GEMM_SMEM>>>(
            bh, bl, wh, wl, b2 + l*DD, a, nullptr, nullptr, SS, DD, FFF, 0);
        add_ln_split<<<SS, 256>>>(h, a, ln2_w + l*DD, ln2_b + l*DD, ah, al);
    }

    classifier_kernel<<<1, 256>>>(h, Wc, bc, out);
}

// round 6
// speedup vs baseline: 4.3301x; 2.5349x over previous
#include <cuda_runtime.h>
#include <cuda_bf16.h>
#include <math.h>
#include <stdint.h>

#define SS 4096
#define DD 768
#define HH 12
#define DHH 64
#define NBB 64
#define BSS 64
#define RRR 3
#define FFF 3072
#define CCC 8
#define NQKV 2304

// ---------------- scratch (device globals; no allocation allowed) -----------
__device__ __align__(16) float g_h  [SS*DD];
__device__ __align__(16) float g_a  [SS*DD];
__device__ __align__(16) float g_qkv[SS*NQKV];
__device__ __align__(16) __nv_bfloat16 g_ah[SS*FFF];
__device__ __align__(16) __nv_bfloat16 g_al[SS*FFF];
__device__ __align__(16) __nv_bfloat16 g_bh[SS*FFF];
__device__ __align__(16) __nv_bfloat16 g_bl[SS*FFF];
__device__ __align__(16) __nv_bfloat16 g_wh[FFF*DD];
__device__ __align__(16) __nv_bfloat16 g_wl[FFF*DD];
__device__ __align__(16) float g_bias3[NQKV];
// edge-attention partials: 24 (h,e) x 8 chunks x 64 q x 64 d
__device__ __align__(16) float g_pO[24*8*64*64];
__device__ __align__(16) float g_pm[24*8*64];
__device__ __align__(16) float g_pl[24*8*64];

// ---------------- PTX helpers ------------------------------------------------
__device__ __forceinline__ uint32_t smem_u32(const void* p) {
    uint32_t a;
    asm("{ .reg .u64 t; cvta.to.shared.u64 t, %1; cvt.u32.u64 %0, t; }" : "=l"(*(uint64_t*)&a) : "l"(p));
    return a;
}
__device__ __forceinline__ uint32_t smem_addr(const void* p) {
    uint32_t a;
    asm("{ .reg .u64 t; cvta.to.shared.u64 t, %1; cvt.u32.u64 %0, t; }" : "=r"(a) : "l"(p));
    return a;
}
__device__ __forceinline__ void ldsm_x4(uint32_t addr, uint32_t* r) {
    asm volatile("ldmatrix.sync.aligned.m8n8.x4.shared.b16 {%0,%1,%2,%3}, [%4];"
        : "=r"(r[0]), "=r"(r[1]), "=r"(r[2]), "=r"(r[3]) : "r"(addr));
}
__device__ __forceinline__ void mma_bf16(float* c, const uint32_t* a, const uint32_t* b) {
    asm volatile("mma.sync.aligned.m16n8k16.row.col.f32.bf16.bf16.f32 "
        "{%0,%1,%2,%3}, {%4,%5,%6,%7}, {%8,%9}, {%0,%1,%2,%3};"
        : "+f"(c[0]), "+f"(c[1]), "+f"(c[2]), "+f"(c[3])
        : "r"(a[0]), "r"(a[1]), "r"(a[2]), "r"(a[3]), "r"(b[0]), "r"(b[1]));
}
#define CP_ASYNC(dst, src) asm volatile("cp.async.cg.shared.global [%0], [%1], 16;" :: "r"(dst), "l"(src))
#define CP_COMMIT()        asm volatile("cp.async.commit_group;")
#define CP_WAIT(n)         asm volatile("cp.async.wait_group %0;" :: "n"(n))

// ---------------- bf16x3 GEMM via mma.sync -----------------------------------
#define GEMM_SMEM 131072

__global__ void __launch_bounds__(256, 1)
gemm_mma(const __nv_bfloat16* __restrict__ Ah, const __nv_bfloat16* __restrict__ Al,
         const __nv_bfloat16* __restrict__ Bh, const __nv_bfloat16* __restrict__ Bl,
         const float* __restrict__ bias, float* __restrict__ C,
         __nv_bfloat16* __restrict__ Oh, __nv_bfloat16* __restrict__ Ol,
         int M, int N, int K, int mode)
{
    extern __shared__ __align__(128) char smem[];
    uint32_t sb = smem_addr(smem);
    int tid = threadIdx.x, lane = tid & 31, wid = tid >> 5;
    int wm = wid & 1, wn = wid >> 1;
    int n0 = blockIdx.x * 128, m0 = blockIdx.y * 128;
    const int KT = K >> 6;

    const __nv_bfloat16* s0 = Ah + (size_t)m0 * K;
    const __nv_bfloat16* s1 = Al + (size_t)m0 * K;
    const __nv_bfloat16* s2 = Bh + (size_t)n0 * K;
    const __nv_bfloat16* s3 = Bl + (size_t)n0 * K;

    float acc[4][4][4];
#pragma unroll
    for (int i = 0; i < 4; i++)
#pragma unroll
        for (int j = 0; j < 4; j++)
#pragma unroll
            for (int u = 0; u < 4; u++) acc[i][j][u] = 0.f;

#define LOAD_STAGE(S, KT_IDX) do {                                              \
    uint32_t sbase_ = sb + (S) * 65536;                                         \
    int ko_ = (KT_IDX) * 64;                                                    \
    _Pragma("unroll")                                                           \
    for (int t_ = 0; t_ < 4; t_++) {                                            \
        const __nv_bfloat16* sp_ = (t_ == 0) ? s0 : (t_ == 1) ? s1 : (t_ == 2) ? s2 : s3; \
        _Pragma("unroll")                                                       \
        for (int i_ = 0; i_ < 4; i_++) {                                        \
            int id_ = tid + i_ * 256;                                           \
            int row_ = id_ >> 3, c_ = id_ & 7;                                  \
            const __nv_bfloat16* src_ = sp_ + (size_t)row_ * K + ko_ + c_ * 8;  \
            uint32_t dst_ = sbase_ + t_ * 16384 + row_ * 128 + ((c_ ^ (row_ & 7)) << 4); \
            CP_ASYNC(dst_, src_);                                               \
        }                                                                       \
    }                                                                           \
    CP_COMMIT();                                                                \
} while (0)

    LOAD_STAGE(0, 0);

    for (int kt = 0; kt < KT; kt++) {
        if (kt + 1 < KT) { LOAD_STAGE((kt + 1) & 1, kt + 1); CP_WAIT(1); }
        else             { CP_WAIT(0); }
        __syncthreads();
        uint32_t st = sb + (kt & 1) * 65536;
#pragma unroll
        for (int ks = 0; ks < 4; ks++) {
            uint32_t ahf[4][4], alf[4][4], bhf[2][4], blf[2][4];
#pragma unroll
            for (int mt = 0; mt < 4; mt++) {
                int row = wm * 64 + mt * 16 + (lane & 15);
                int kc = ks * 2 + (lane >> 4);
                uint32_t off = row * 128 + ((kc ^ (row & 7)) << 4);
                ldsm_x4(st + off, ahf[mt]);
                ldsm_x4(st + 16384 + off, alf[mt]);
            }
#pragma unroll
            for (int np = 0; np < 2; np++) {
                int row = wn * 32 + np * 16 + ((lane & 7) | ((lane & 16) >> 1));
                int kc = ks * 2 + ((lane >> 3) & 1);
                uint32_t off = row * 128 + ((kc ^ (row & 7)) << 4);
                ldsm_x4(st + 32768 + off, bhf[np]);
                ldsm_x4(st + 49152 + off, blf[np]);
            }
#pragma unroll
            for (int mt = 0; mt < 4; mt++)
#pragma unroll
                for (int nt = 0; nt < 4; nt++) {
                    const uint32_t* bh_ = &bhf[nt >> 1][(nt & 1) * 2];
                    const uint32_t* bl_ = &blf[nt >> 1][(nt & 1) * 2];
                    mma_bf16(acc[mt][nt], ahf[mt], bh_);
                    mma_bf16(acc[mt][nt], ahf[mt], bl_);
                    mma_bf16(acc[mt][nt], alf[mt], bh_);
                }
        }
        __syncthreads();
    }

#pragma unroll
    for (int mt = 0; mt < 4; mt++) {
        int mbase = m0 + wm * 64 + mt * 16 + (lane >> 2);
#pragma unroll
        for (int nt = 0; nt < 4; nt++) {
            int n = n0 + wn * 32 + nt * 8 + (lane & 3) * 2;
            float b0 = bias[n], b1 = bias[n + 1];
#pragma unroll
            for (int half = 0; half < 2; half++) {
                int m = mbase + half * 8;
                float v0 = acc[mt][nt][half * 2 + 0] + b0;
                float v1 = acc[mt][nt][half * 2 + 1] + b1;
                if (mode >= 1) {
                    float u0 = 0.7978845608028654f * (v0 + 0.044715f * v0 * v0 * v0);
                    v0 = 0.5f * v0 * (1.f + tanhf(u0));
                    float u1 = 0.7978845608028654f * (v1 + 0.044715f * v1 * v1 * v1);
                    v1 = 0.5f * v1 * (1.f + tanhf(u1));
                }
                if (mode == 2) {
                    __nv_bfloat16 h0 = __float2bfloat16(v0), h1 = __float2bfloat16(v1);
                    __nv_bfloat16 l0 = __float2bfloat16(v0 - __bfloat162float(h0));
                    __nv_bfloat16 l1 = __float2bfloat16(v1 - __bfloat162float(h1));
                    *(__nv_bfloat162*)(Oh + (size_t)m * N + n) = __nv_bfloat162(h0, h1);
                    *(__nv_bfloat162*)(Ol + (size_t)m * N + n) = __nv_bfloat162(l0, l1);
                } else {
                    float2 o; o.x = v0; o.y = v1;
                    *(float2*)(C + (size_t)m * N + n) = o;
                }
            }
        }
    }
}

// ---------------- W[K,N] fp32 -> Wt[N,K] bf16 hi/lo --------------------------
__global__ __launch_bounds__(256) void conv_wt(const float* __restrict__ W,
    __nv_bfloat16* __restrict__ th, __nv_bfloat16* __restrict__ tl, int K, int N)
{
    __shared__ float tile[32][33];
    int k0 = blockIdx.y * 32, n0 = blockIdx.x * 32;
    int tx = threadIdx.x & 31, ty = threadIdx.x >> 5;
#pragma unroll
    for (int r = ty; r < 32; r += 8)
        tile[r][tx] = W[(size_t)(k0 + r) * N + n0 + tx];
    __syncthreads();
#pragma unroll
    for (int r = ty; r < 32; r += 8) {
        float v = tile[tx][r];
        __nv_bfloat16 hh = __float2bfloat16(v);
        size_t o = (size_t)(n0 + r) * K + k0 + tx;
        th[o] = hh;
        tl[o] = __float2bfloat16(v - __bfloat162float(hh));
    }
}

__global__ __launch_bounds__(256) void concat3(const float* __restrict__ a,
    const float* __restrict__ b, const float* __restrict__ c, float* __restrict__ o)
{
    int i = blockIdx.x * 256 + threadIdx.x;
    if (i < DD) { o[i] = a[i]; o[DD + i] = b[i]; o[2 * DD + i] = c[i]; }
}

// ---------------- reductions -------------------------------------------------
__device__ __forceinline__ void block_reduce2(float &s1v, float &s2v) {
    __shared__ float sa[8], sb2[8];
    int lane = threadIdx.x & 31, w = threadIdx.x >> 5;
#pragma unroll
    for (int off = 16; off; off >>= 1) {
        s1v += __shfl_xor_sync(0xffffffffu, s1v, off);
        s2v += __shfl_xor_sync(0xffffffffu, s2v, off);
    }
    if (lane == 0) { sa[w] = s1v; sb2[w] = s2v; }
    __syncthreads();
    if (w == 0) {
        s1v = (lane < 8) ? sa[lane] : 0.f;
        s2v = (lane < 8) ? sb2[lane] : 0.f;
#pragma unroll
        for (int off = 4; off; off >>= 1) {
            s1v += __shfl_xor_sync(0xffffffffu, s1v, off);
            s2v += __shfl_xor_sync(0xffffffffu, s2v, off);
        }
        if (lane == 0) { sa[0] = s1v; sb2[0] = s2v; }
    }
    __syncthreads();
    s1v = sa[0]; s2v = sb2[0];
}

__device__ __forceinline__ void write_split(__nv_bfloat16* hi, __nv_bfloat16* lo,
                                            int idx, float v) {
    __nv_bfloat16 h = __float2bfloat16(v);
    hi[idx] = h;
    lo[idx] = __float2bfloat16(v - __bfloat162float(h));
}

// ---------------- embedding + LN (split out) ---------------------------------
__global__ __launch_bounds__(256) void embed_ln_split(
    const int* __restrict__ ids, const float* __restrict__ we,
    const float* __restrict__ pe, const float* __restrict__ w,
    const float* __restrict__ b, float* __restrict__ out,
    __nv_bfloat16* __restrict__ oh, __nv_bfloat16* __restrict__ ol)
{
    int row = blockIdx.x;
    int id = ids[row];
    float x[3], sum = 0.f, sq = 0.f;
#pragma unroll
    for (int r = 0; r < 3; r++) {
        int i = threadIdx.x + r * 256;
        x[r] = we[(long long)id * DD + i] + pe[row * DD + i];
        sum += x[r]; sq += x[r] * x[r];
    }
    block_reduce2(sum, sq);
    float mean = sum * (1.f / DD);
    float var  = sq * (1.f / DD) - mean * mean;
    float inv  = rsqrtf(var + 1e-12f);
#pragma unroll
    for (int r = 0; r < 3; r++) {
        int i = threadIdx.x + r * 256;
        float y = (x[r] - mean) * inv * w[i] + b[i];
        out[row * DD + i] = y;
        write_split(oh, ol, row * DD + i, y);
    }
}

// ---------------- residual add + LN (split out) -------------------------------
__global__ __launch_bounds__(256) void add_ln_split(
    float* __restrict__ h, const float* __restrict__ a,
    const float* __restrict__ w, const float* __restrict__ b,
    __nv_bfloat16* __restrict__ oh, __nv_bfloat16* __restrict__ ol)
{
    int row = blockIdx.x;
    float x[3], sum = 0.f, sq = 0.f;
#pragma unroll
    for (int r = 0; r < 3; r++) {
        int i = threadIdx.x + r * 256;
        x[r] = h[row * DD + i] + a[row * DD + i];
        sum += x[r]; sq += x[r] * x[r];
    }
    block_reduce2(sum, sq);
    float mean = sum * (1.f / DD);
    float var  = sq * (1.f / DD) - mean * mean;
    float inv  = rsqrtf(var + 1e-12f);
#pragma unroll
    for (int r = 0; r < 3; r++) {
        int i = threadIdx.x + r * 256;
        float y = (x[r] - mean) * inv * w[i] + b[i];
        h[row * DD + i] = y;
        write_split(oh, ol, row * DD + i, y);
    }
}

// ---------------- tiled attention ---------------------------------------------
// grid (H, NBB, 8). Mid q-blocks use only z==0 (their 8-block window).
// Edge q-blocks (0, NBB-1): chunk z covers key-blocks z*8..z*8+7, partials out.
// 256 threads: tx = tid&15 (key/dim groups of 4), ty = tid>>4 (query groups of 4).
#define ATP 68
#define ATT_SMEM (4 * 64 * ATP * 4)

__global__ void __launch_bounds__(256)
attn_tile_kernel(const float* __restrict__ qkv, const int* __restrict__ rnd,
                 __nv_bfloat16* __restrict__ th, __nv_bfloat16* __restrict__ tl,
                 float* __restrict__ pO, float* __restrict__ pm, float* __restrict__ pl)
{
    extern __shared__ float sm[];
    float* Qt = sm;                 // [64 d][ATP] (d-major, q fast)
    float* Kt = sm + 64 * ATP;      // [64 d][ATP]
    float* Vs = sm + 2 * 64 * ATP;  // [64 k][ATP] (k-major, d fast)
    float* Pt = sm + 3 * 64 * ATP;  // [64 k][ATP] (k-major, q fast)

    int h = blockIdx.x, qb = blockIdx.y, z = blockIdx.z;
    bool edge = (qb == 0 || qb == NBB - 1);
    if (!edge && z != 0) return;

    int tid = threadIdx.x, tx = tid & 15, ty = tid >> 4;

    int blks[8];
    if (edge) {
#pragma unroll
        for (int i = 0; i < 8; i++) blks[i] = z * 8 + i;
    } else {
        blks[0] = 0; blks[1] = NBB - 1; blks[2] = qb - 1; blks[3] = qb; blks[4] = qb + 1;
        const int* rp = rnd + (h * NBB + qb) * RRR;
        blks[5] = rp[0]; blks[6] = rp[1]; blks[7] = rp[2];
    }

    const float* qptr = qkv + h * DHH;
    const float* kptr = qkv + DD + h * DHH;
    const float* vptr = qkv + 2 * DD + h * DHH;

    // load Q transposed (once)
#pragma unroll
    for (int f = 0; f < 4; f++) {
        int lin = tid + f * 256;
        int qr = lin >> 4, ds = lin & 15;
        float4 val = *(const float4*)(qptr + (size_t)(qb * BSS + qr) * NQKV + ds * 4);
        Qt[(ds * 4 + 0) * ATP + qr] = val.x;
        Qt[(ds * 4 + 1) * ATP + qr] = val.y;
        Qt[(ds * 4 + 2) * ATP + qr] = val.z;
        Qt[(ds * 4 + 3) * ATP + qr] = val.w;
    }

    float o[4][4];
    float m[4], l[4];
#pragma unroll
    for (int i = 0; i < 4; i++) {
        m[i] = -1e30f; l[i] = 0.f;
#pragma unroll
        for (int j = 0; j < 4; j++) o[i][j] = 0.f;
    }

    for (int b = 0; b < 8; b++) {
        int kb = blks[b];
        __syncthreads();  // protect Kt/Vs/Pt from prior readers
        // load K (transposed) and V (natural)
#pragma unroll
        for (int f = 0; f < 4; f++) {
            int lin = tid + f * 256;
            int kr = lin >> 4, ds = lin & 15;
            float4 kv = *(const float4*)(kptr + (size_t)(kb * BSS + kr) * NQKV + ds * 4);
            Kt[(ds * 4 + 0) * ATP + kr] = kv.x;
            Kt[(ds * 4 + 1) * ATP + kr] = kv.y;
            Kt[(ds * 4 + 2) * ATP + kr] = kv.z;
            Kt[(ds * 4 + 3) * ATP + kr] = kv.w;
            float4 vv = *(const float4*)(vptr + (size_t)(kb * BSS + kr) * NQKV + ds * 4);
            *(float4*)&Vs[kr * ATP + ds * 4] = vv;
        }
        __syncthreads();

        // S = Q K^T  (each thread: 4 q x 4 k)
        float s[4][4];
#pragma unroll
        for (int i = 0; i < 4; i++)
#pragma unroll
            for (int j = 0; j < 4; j++) s[i][j] = 0.f;
#pragma unroll 4
        for (int d = 0; d < 64; d++) {
            float4 qv = *(const float4*)&Qt[d * ATP + ty * 4];
            float4 kv = *(const float4*)&Kt[d * ATP + tx * 4];
            float qa[4] = {qv.x, qv.y, qv.z, qv.w};
            float ka[4] = {kv.x, kv.y, kv.z, kv.w};
#pragma unroll
            for (int i = 0; i < 4; i++)
#pragma unroll
                for (int j = 0; j < 4; j++)
                    s[i][j] = fmaf(qa[i], ka[j], s[i][j]);
        }

        // online softmax per q row (reduce across 16 tx lanes)
#pragma unroll
        for (int i = 0; i < 4; i++) {
            float rm = fmaxf(fmaxf(s[i][0], s[i][1]), fmaxf(s[i][2], s[i][3])) * 0.125f;
#pragma unroll
            for (int off = 1; off < 16; off <<= 1)
                rm = fmaxf(rm, __shfl_xor_sync(0xffffffffu, rm, off));
            float mn = fmaxf(m[i], rm);
            float corr = __expf(m[i] - mn);
            m[i] = mn;
            float rs = 0.f;
#pragma unroll
            for (int j = 0; j < 4; j++) {
                s[i][j] = __expf(s[i][j] * 0.125f - mn);
                rs += s[i][j];
            }
#pragma unroll
            for (int off = 1; off < 16; off <<= 1)
                rs += __shfl_xor_sync(0xffffffffu, rs, off);
            l[i] = l[i] * corr + rs;
#pragma unroll
            for (int j = 0; j < 4; j++) o[i][j] *= corr;
        }

        // write P transposed: Pt[k][q]
#pragma unroll
        for (int i = 0; i < 4; i++)
#pragma unroll
            for (int j = 0; j < 4; j++)
                Pt[(tx * 4 + j) * ATP + ty * 4 + i] = s[i][j];
        __syncthreads();

        // O += P V  (each thread: 4 q x 4 d)
#pragma unroll 4
        for (int k = 0; k < 64; k++) {
            float4 pv = *(const float4*)&Pt[k * ATP + ty * 4];
            float4 vv = *(const float4*)&Vs[k * ATP + tx * 4];
            float pa[4] = {pv.x, pv.y, pv.z, pv.w};
            float va[4] = {vv.x, vv.y, vv.z, vv.w};
#pragma unroll
            for (int i = 0; i < 4; i++)
#pragma unroll
                for (int j = 0; j < 4; j++)
                    o[i][j] = fmaf(pa[i], va[j], o[i][j]);
        }
    }

    if (!edge) {
#pragma unroll
        for (int i = 0; i < 4; i++) {
            float inv = 1.f / l[i];
            int row = qb * BSS + ty * 4 + i;
            int idx = row * DD + h * DHH + tx * 4;
#pragma unroll
            for (int j = 0; j < 4; j++)
                write_split(th, tl, idx + j, o[i][j] * inv);
        }
    } else {
        int e = qb ? 1 : 0;
        int cb = (h * 2 + e) * 8 + z;
        float* po = pO + (size_t)cb * 64 * 64;
#pragma unroll
        for (int i = 0; i < 4; i++) {
#pragma unroll
            for (int j = 0; j < 4; j++)
                po[(ty * 4 + i) * 64 + tx * 4 + j] = o[i][j];
            if (tx == 0) {
                pm[cb * 64 + ty * 4 + i] = m[i];
                pl[cb * 64 + ty * 4 + i] = l[i];
            }
        }
    }
}

// combine edge partials: grid (24, 64), 64 threads (d)
__global__ void __launch_bounds__(64)
attn_combine(const float* __restrict__ pO, const float* __restrict__ pm,
             const float* __restrict__ pl,
             __nv_bfloat16* __restrict__ th, __nv_bfloat16* __restrict__ tl)
{
    int he = blockIdx.x, q = blockIdx.y, d = threadIdx.x;
    int h = he >> 1, e = he & 1;
    float mv[8], M = -1e30f;
#pragma unroll
    for (int z = 0; z < 8; z++) {
        mv[z] = pm[(he * 8 + z) * 64 + q];
        M = fmaxf(M, mv[z]);
    }
    float L = 0.f, O = 0.f;
#pragma unroll
    for (int z = 0; z < 8; z++) {
        float w = __expf(mv[z] - M);
        L += w * pl[(he * 8 + z) * 64 + q];
        O += w * pO[((size_t)(he * 8 + z) * 64 + q) * 64 + d];
    }
    float r = O / L;
    int row = (e ? (NBB - 1) : 0) * BSS + q;
    write_split(th, tl, row * DD + h * DHH + d, r);
}

// ---------------- classifier --------------------------------------------------
__global__ __launch_bounds__(256) void classifier_kernel(
    const float* __restrict__ h, const float* __restrict__ Wc,
    const float* __restrict__ bc, float* __restrict__ out)
{
    int warp = threadIdx.x >> 5, lane = threadIdx.x & 31;
    if (warp >= CCC) return;
    const float* hr = h + (long long)(SS - 1) * DD;
    float s = 0.f;
    for (int d = lane; d < DD; d += 32) s += hr[d] * Wc[d * CCC + warp];
#pragma unroll
    for (int off = 16; off; off >>= 1) s += __shfl_xor_sync(0xffffffffu, s, off);
    if (lane == 0) out[warp] = s + bc[warp];
}

// ---------------- launch ------------------------------------------------------
extern "C" void kernel_launch(void* const* d_in, const int* in_sizes, int n_in,
                              void* d_out, int out_size)
{
    (void)in_sizes; (void)n_in; (void)out_size;
    const int*   input_ids = (const int*)  d_in[0];
    const int*   rand_attn = (const int*)  d_in[1];
    const float* word_emb  = (const float*)d_in[2];
    const float* pos_emb   = (const float*)d_in[3];
    const float* eln_w     = (const float*)d_in[4];
    const float* eln_b     = (const float*)d_in[5];
    const float* Wq        = (const float*)d_in[6];
    const float* bq        = (const float*)d_in[7];
    const float* Wk        = (const float*)d_in[8];
    const float* bk        = (const float*)d_in[9];
    const float* Wv        = (const float*)d_in[10];
    const float* bv        = (const float*)d_in[11];
    const float* Wo        = (const float*)d_in[12];
    const float* bo        = (const float*)d_in[13];
    const float* ln1_w     = (const float*)d_in[14];
    const float* ln1_b     = (const float*)d_in[15];
    const float* W1        = (const float*)d_in[16];
    const float* b1        = (const float*)d_in[17];
    const float* W2        = (const float*)d_in[18];
    const float* b2        = (const float*)d_in[19];
    const float* ln2_w     = (const float*)d_in[20];
    const float* ln2_b     = (const float*)d_in[21];
    const float* Wc        = (const float*)d_in[22];
    const float* bc        = (const float*)d_in[23];
    float* out = (float*)d_out;

    cudaFuncSetAttribute(gemm_mma, cudaFuncAttributeMaxDynamicSharedMemorySize, GEMM_SMEM);
    cudaFuncSetAttribute(attn_tile_kernel, cudaFuncAttributeMaxDynamicSharedMemorySize, ATT_SMEM);

    float *h, *a, *qkv, *bias3, *pO, *pm, *pl;
    __nv_bfloat16 *ah, *al, *bh, *bl, *wh, *wl;
    cudaGetSymbolAddress((void**)&h,    g_h);
    cudaGetSymbolAddress((void**)&a,    g_a);
    cudaGetSymbolAddress((void**)&qkv,  g_qkv);
    cudaGetSymbolAddress((void**)&ah,   g_ah);
    cudaGetSymbolAddress((void**)&al,   g_al);
    cudaGetSymbolAddress((void**)&bh,   g_bh);
    cudaGetSymbolAddress((void**)&bl,   g_bl);
    cudaGetSymbolAddress((void**)&wh,   g_wh);
    cudaGetSymbolAddress((void**)&wl,   g_wl);
    cudaGetSymbolAddress((void**)&bias3, g_bias3);
    cudaGetSymbolAddress((void**)&pO,   g_pO);
    cudaGetSymbolAddress((void**)&pm,   g_pm);
    cudaGetSymbolAddress((void**)&pl,   g_pl);

    embed_ln_split<<<SS, 256>>>(input_ids, word_emb, pos_emb, eln_w, eln_b, h, ah, al);

    for (int l = 0; l < 2; l++) {
        long long wofs = (long long)l * DD * DD;

        // ---- fused QKV projection ----
        conv_wt<<<dim3(DD/32, DD/32), 256>>>(Wq + wofs, wh,           wl,           DD, DD);
        conv_wt<<<dim3(DD/32, DD/32), 256>>>(Wk + wofs, wh + DD*DD,   wl + DD*DD,   DD, DD);
        conv_wt<<<dim3(DD/32, DD/32), 256>>>(Wv + wofs, wh + 2*DD*DD, wl + 2*DD*DD, DD, DD);
        concat3<<<3, 256>>>(bq + l*DD, bk + l*DD, bv + l*DD, bias3);
        gemm_mma<<<dim3(NQKV/128, SS/128), 256, GEMM_SMEM>>>(
            ah, al, wh, wl, bias3, qkv, nullptr, nullptr, SS, NQKV, DD, 0);

        // ---- attention (writes split bf16 into ah/al) ----
        attn_tile_kernel<<<dim3(HH, NBB, 8), 256, ATT_SMEM>>>(
            qkv, rand_attn + l*HH*NBB*RRR, ah, al, pO, pm, pl);
        attn_combine<<<dim3(24, 64), 64>>>(pO, pm, pl, ah, al);

        // ---- O projection + LN ----
        conv_wt<<<dim3(DD/32, DD/32), 256>>>(Wo + wofs, wh, wl, DD, DD);
        gemm_mma<<<dim3(DD/128, SS/128), 256, GEMM_SMEM>>>(
            ah, al, wh, wl, bo + l*DD, a, nullptr, nullptr, SS, DD, DD, 0);
        add_ln_split<<<SS, 256>>>(h, a, ln1_w + l*DD, ln1_b + l*DD, ah, al);

        // ---- FFN ----
        conv_wt<<<dim3(FFF/32, DD/32), 256>>>(W1 + (long long)l*DD*FFF, wh, wl, DD, FFF);
        gemm_mma<<<dim3(FFF/128, SS/128), 256, GEMM_SMEM>>>(
            ah, al, wh, wl, b1 + l*FFF, nullptr, bh, bl, SS, FFF, DD, 2);
        conv_wt<<<dim3(DD/32, FFF/32), 256>>>(W2 + (long long)l*FFF*DD, wh, wl, FFF, DD);
        gemm_mma<<<dim3(DD/128, SS/128), 256, GEMM_SMEM>>>(
            bh, bl, wh, wl, b2 + l*DD, a, nullptr, nullptr, SS, DD, FFF, 0);
        add_ln_split<<<SS, 256>>>(h, a, ln2_w + l*DD, ln2_b + l*DD, ah, al);
    }

    classifier_kernel<<<1, 256>>>(h, Wc, bc, out);
}

// round 8
// speedup vs baseline: 5.4965x; 1.2694x over previous
#include <cuda_runtime.h>
#include <cuda_bf16.h>
#include <math.h>
#include <stdint.h>

#define SS 4096
#define DD 768
#define HH 12
#define DHH 64
#define NBB 64
#define BSS 64
#define RRR 3
#define FFF 3072
#define CCC 8
#define NQKV 2304

// ---------------- scratch (device globals; no allocation allowed) -----------
__device__ __align__(16) float g_h  [SS*DD];
__device__ __align__(16) float g_a  [SS*DD];
__device__ __align__(16) __nv_bfloat16 g_ah[SS*FFF];
__device__ __align__(16) __nv_bfloat16 g_al[SS*FFF];
__device__ __align__(16) __nv_bfloat16 g_bh[SS*FFF];
__device__ __align__(16) __nv_bfloat16 g_bl[SS*FFF];
__device__ __align__(16) __nv_bfloat16 g_wh[FFF*DD];
__device__ __align__(16) __nv_bfloat16 g_wl[FFF*DD];
__device__ __align__(16) float g_bias3[NQKV];
// edge-attention partials: 24 (h,e) x 8 chunks x 64 q x 64 d
__device__ __align__(16) float g_pO[24*8*64*64];
__device__ __align__(16) float g_pm[24*8*64];
__device__ __align__(16) float g_pl[24*8*64];

// ---------------- PTX helpers ------------------------------------------------
__device__ __forceinline__ uint32_t smem_addr(const void* p) {
    uint32_t a;
    asm("{ .reg .u64 t; cvta.to.shared.u64 t, %1; cvt.u32.u64 %0, t; }" : "=r"(a) : "l"(p));
    return a;
}
__device__ __forceinline__ void ldsm_x4(uint32_t addr, uint32_t* r) {
    asm volatile("ldmatrix.sync.aligned.m8n8.x4.shared.b16 {%0,%1,%2,%3}, [%4];"
        : "=r"(r[0]), "=r"(r[1]), "=r"(r[2]), "=r"(r[3]) : "r"(addr));
}
__device__ __forceinline__ void ldsm_x4_t(uint32_t addr, uint32_t* r) {
    asm volatile("ldmatrix.sync.aligned.m8n8.x4.trans.shared.b16 {%0,%1,%2,%3}, [%4];"
        : "=r"(r[0]), "=r"(r[1]), "=r"(r[2]), "=r"(r[3]) : "r"(addr));
}
__device__ __forceinline__ void mma_bf16(float* c, const uint32_t* a, const uint32_t* b) {
    asm volatile("mma.sync.aligned.m16n8k16.row.col.f32.bf16.bf16.f32 "
        "{%0,%1,%2,%3}, {%4,%5,%6,%7}, {%8,%9}, {%0,%1,%2,%3};"
        : "+f"(c[0]), "+f"(c[1]), "+f"(c[2]), "+f"(c[3])
        : "r"(a[0]), "r"(a[1]), "r"(a[2]), "r"(a[3]), "r"(b[0]), "r"(b[1]));
}
__device__ __forceinline__ void mma4(float* c, const uint32_t* a, uint32_t b0, uint32_t b1) {
    uint32_t b[2] = {b0, b1};
    mma_bf16(c, a, b);
}
#define CP_ASYNC(dst, src) asm volatile("cp.async.cg.shared.global [%0], [%1], 16;" :: "r"(dst), "l"(src))
#define CP_COMMIT()        asm volatile("cp.async.commit_group;")
#define CP_WAIT(n)         asm volatile("cp.async.wait_group %0;" :: "n"(n))

__device__ __forceinline__ uint32_t pack_bf2(__nv_bfloat16 a, __nv_bfloat16 b) {
    __nv_bfloat162 t; t.x = a; t.y = b;
    return *(uint32_t*)&t;
}
__device__ __forceinline__ void split2(float a, float b, uint32_t& hi, uint32_t& lo) {
    __nv_bfloat16 ha = __float2bfloat16(a), hb = __float2bfloat16(b);
    __nv_bfloat16 la = __float2bfloat16(a - __bfloat162float(ha));
    __nv_bfloat16 lb = __float2bfloat16(b - __bfloat162float(hb));
    hi = pack_bf2(ha, hb);
    lo = pack_bf2(la, lb);
}

// ---------------- bf16x3 GEMM via mma.sync -----------------------------------
// modes: 0 fp32 out, 1 gelu fp32, 2 gelu + split bf16, 3 split bf16 (no gelu)
#define GEMM_SMEM 131072

__global__ void __launch_bounds__(256, 1)
gemm_mma(const __nv_bfloat16* __restrict__ Ah, const __nv_bfloat16* __restrict__ Al,
         const __nv_bfloat16* __restrict__ Bh, const __nv_bfloat16* __restrict__ Bl,
         const float* __restrict__ bias, float* __restrict__ C,
         __nv_bfloat16* __restrict__ Oh, __nv_bfloat16* __restrict__ Ol,
         int M, int N, int K, int mode)
{
    extern __shared__ __align__(128) char smem[];
    uint32_t sb = smem_addr(smem);
    int tid = threadIdx.x, lane = tid & 31, wid = tid >> 5;
    int wm = wid & 1, wn = wid >> 1;
    int n0 = blockIdx.x * 128, m0 = blockIdx.y * 128;
    const int KT = K >> 6;

    const __nv_bfloat16* s0 = Ah + (size_t)m0 * K;
    const __nv_bfloat16* s1 = Al + (size_t)m0 * K;
    const __nv_bfloat16* s2 = Bh + (size_t)n0 * K;
    const __nv_bfloat16* s3 = Bl + (size_t)n0 * K;

    float acc[4][4][4];
#pragma unroll
    for (int i = 0; i < 4; i++)
#pragma unroll
        for (int j = 0; j < 4; j++)
#pragma unroll
            for (int u = 0; u < 4; u++) acc[i][j][u] = 0.f;

#define LOAD_STAGE(S, KT_IDX) do {                                              \
    uint32_t sbase_ = sb + (S) * 65536;                                         \
    int ko_ = (KT_IDX) * 64;                                                    \
    _Pragma("unroll")                                                           \
    for (int t_ = 0; t_ < 4; t_++) {                                            \
        const __nv_bfloat16* sp_ = (t_ == 0) ? s0 : (t_ == 1) ? s1 : (t_ == 2) ? s2 : s3; \
        _Pragma("unroll")                                                       \
        for (int i_ = 0; i_ < 4; i_++) {                                        \
            int id_ = tid + i_ * 256;                                           \
            int row_ = id_ >> 3, c_ = id_ & 7;                                  \
            const __nv_bfloat16* src_ = sp_ + (size_t)row_ * K + ko_ + c_ * 8;  \
            uint32_t dst_ = sbase_ + t_ * 16384 + row_ * 128 + ((c_ ^ (row_ & 7)) << 4); \
            CP_ASYNC(dst_, src_);                                               \
        }                                                                       \
    }                                                                           \
    CP_COMMIT();                                                                \
} while (0)

    LOAD_STAGE(0, 0);

    for (int kt = 0; kt < KT; kt++) {
        if (kt + 1 < KT) { LOAD_STAGE((kt + 1) & 1, kt + 1); CP_WAIT(1); }
        else             { CP_WAIT(0); }
        __syncthreads();
        uint32_t st = sb + (kt & 1) * 65536;
#pragma unroll
        for (int ks = 0; ks < 4; ks++) {
            uint32_t ahf[4][4], alf[4][4], bhf[2][4], blf[2][4];
#pragma unroll
            for (int mt = 0; mt < 4; mt++) {
                int row = wm * 64 + mt * 16 + (lane & 15);
                int kc = ks * 2 + (lane >> 4);
                uint32_t off = row * 128 + ((kc ^ (row & 7)) << 4);
                ldsm_x4(st + off, ahf[mt]);
                ldsm_x4(st + 16384 + off, alf[mt]);
            }
#pragma unroll
            for (int np = 0; np < 2; np++) {
                int row = wn * 32 + np * 16 + ((lane & 7) | ((lane & 16) >> 1));
                int kc = ks * 2 + ((lane >> 3) & 1);
                uint32_t off = row * 128 + ((kc ^ (row & 7)) << 4);
                ldsm_x4(st + 32768 + off, bhf[np]);
                ldsm_x4(st + 49152 + off, blf[np]);
            }
#pragma unroll
            for (int mt = 0; mt < 4; mt++)
#pragma unroll
                for (int nt = 0; nt < 4; nt++) {
                    const uint32_t* bh_ = &bhf[nt >> 1][(nt & 1) * 2];
                    const uint32_t* bl_ = &blf[nt >> 1][(nt & 1) * 2];
                    mma_bf16(acc[mt][nt], ahf[mt], bh_);
                    mma_bf16(acc[mt][nt], ahf[mt], bl_);
                    mma_bf16(acc[mt][nt], alf[mt], bh_);
                }
        }
        __syncthreads();
    }

#pragma unroll
    for (int mt = 0; mt < 4; mt++) {
        int mbase = m0 + wm * 64 + mt * 16 + (lane >> 2);
#pragma unroll
        for (int nt = 0; nt < 4; nt++) {
            int n = n0 + wn * 32 + nt * 8 + (lane & 3) * 2;
            float b0 = bias[n], b1 = bias[n + 1];
#pragma unroll
            for (int half = 0; half < 2; half++) {
                int m = mbase + half * 8;
                float v0 = acc[mt][nt][half * 2 + 0] + b0;
                float v1 = acc[mt][nt][half * 2 + 1] + b1;
                if (mode == 1 || mode == 2) {
                    float u0 = 0.7978845608028654f * (v0 + 0.044715f * v0 * v0 * v0);
                    v0 = 0.5f * v0 * (1.f + tanhf(u0));
                    float u1 = 0.7978845608028654f * (v1 + 0.044715f * v1 * v1 * v1);
                    v1 = 0.5f * v1 * (1.f + tanhf(u1));
                }
                if (mode >= 2) {
                    uint32_t hi, lo;
                    split2(v0, v1, hi, lo);
                    *(uint32_t*)(Oh + (size_t)m * N + n) = hi;
                    *(uint32_t*)(Ol + (size_t)m * N + n) = lo;
                } else {
                    float2 o; o.x = v0; o.y = v1;
                    *(float2*)(C + (size_t)m * N + n) = o;
                }
            }
        }
    }
}

// ---------------- W[K,N] fp32 -> Wt[N,K] bf16 hi/lo --------------------------
__global__ __launch_bounds__(256) void conv_wt(const float* __restrict__ W,
    __nv_bfloat16* __restrict__ th, __nv_bfloat16* __restrict__ tl, int K, int N)
{
    __shared__ float tile[32][33];
    int k0 = blockIdx.y * 32, n0 = blockIdx.x * 32;
    int tx = threadIdx.x & 31, ty = threadIdx.x >> 5;
#pragma unroll
    for (int r = ty; r < 32; r += 8)
        tile[r][tx] = W[(size_t)(k0 + r) * N + n0 + tx];
    __syncthreads();
#pragma unroll
    for (int r = ty; r < 32; r += 8) {
        float v = tile[tx][r];
        __nv_bfloat16 hh = __float2bfloat16(v);
        size_t o = (size_t)(n0 + r) * K + k0 + tx;
        th[o] = hh;
        tl[o] = __float2bfloat16(v - __bfloat162float(hh));
    }
}

__global__ __launch_bounds__(256) void concat3(const float* __restrict__ a,
    const float* __restrict__ b, const float* __restrict__ c, float* __restrict__ o)
{
    int i = blockIdx.x * 256 + threadIdx.x;
    if (i < DD) { o[i] = a[i]; o[DD + i] = b[i]; o[2 * DD + i] = c[i]; }
}

// ---------------- reductions -------------------------------------------------
__device__ __forceinline__ void block_reduce2(float &s1v, float &s2v) {
    __shared__ float sa[8], sb2[8];
    int lane = threadIdx.x & 31, w = threadIdx.x >> 5;
#pragma unroll
    for (int off = 16; off; off >>= 1) {
        s1v += __shfl_xor_sync(0xffffffffu, s1v, off);
        s2v += __shfl_xor_sync(0xffffffffu, s2v, off);
    }
    if (lane == 0) { sa[w] = s1v; sb2[w] = s2v; }
    __syncthreads();
    if (w == 0) {
        s1v = (lane < 8) ? sa[lane] : 0.f;
        s2v = (lane < 8) ? sb2[lane] : 0.f;
#pragma unroll
        for (int off = 4; off; off >>= 1) {
            s1v += __shfl_xor_sync(0xffffffffu, s1v, off);
            s2v += __shfl_xor_sync(0xffffffffu, s2v, off);
        }
        if (lane == 0) { sa[0] = s1v; sb2[0] = s2v; }
    }
    __syncthreads();
    s1v = sa[0]; s2v = sb2[0];
}

__device__ __forceinline__ void write_split(__nv_bfloat16* hi, __nv_bfloat16* lo,
                                            int idx, float v) {
    __nv_bfloat16 h = __float2bfloat16(v);
    hi[idx] = h;
    lo[idx] = __float2bfloat16(v - __bfloat162float(h));
}

// ---------------- embedding + LN (split out) ---------------------------------
__global__ __launch_bounds__(256) void embed_ln_split(
    const int* __restrict__ ids, const float* __restrict__ we,
    const float* __restrict__ pe, const float* __restrict__ w,
    const float* __restrict__ b, float* __restrict__ out,
    __nv_bfloat16* __restrict__ oh, __nv_bfloat16* __restrict__ ol)
{
    int row = blockIdx.x;
    int id = ids[row];
    float x[3], sum = 0.f, sq = 0.f;
#pragma unroll
    for (int r = 0; r < 3; r++) {
        int i = threadIdx.x + r * 256;
        x[r] = we[(long long)id * DD + i] + pe[row * DD + i];
        sum += x[r]; sq += x[r] * x[r];
    }
    block_reduce2(sum, sq);
    float mean = sum * (1.f / DD);
    float var  = sq * (1.f / DD) - mean * mean;
    float inv  = rsqrtf(var + 1e-12f);
#pragma unroll
    for (int r = 0; r < 3; r++) {
        int i = threadIdx.x + r * 256;
        float y = (x[r] - mean) * inv * w[i] + b[i];
        out[row * DD + i] = y;
        write_split(oh, ol, row * DD + i, y);
    }
}

// ---------------- residual add + LN (split out) -------------------------------
__global__ __launch_bounds__(256) void add_ln_split(
    float* __restrict__ h, const float* __restrict__ a,
    const float* __restrict__ w, const float* __restrict__ b,
    __nv_bfloat16* __restrict__ oh, __nv_bfloat16* __restrict__ ol)
{
    int row = blockIdx.x;
    float x[3], sum = 0.f, sq = 0.f;
#pragma unroll
    for (int r = 0; r < 3; r++) {
        int i = threadIdx.x + r * 256;
        x[r] = h[row * DD + i] + a[row * DD + i];
        sum += x[r]; sq += x[r] * x[r];
    }
    block_reduce2(sum, sq);
    float mean = sum * (1.f / DD);
    float var  = sq * (1.f / DD) - mean * mean;
    float inv  = rsqrtf(var + 1e-12f);
#pragma unroll
    for (int r = 0; r < 3; r++) {
        int i = threadIdx.x + r * 256;
        float y = (x[r] - mean) * inv * w[i] + b[i];
        h[row * DD + i] = y;
        write_split(oh, ol, row * DD + i, y);
    }
}

// ---------------- MMA flash attention ----------------------------------------
// qh/ql: split bf16 QKV [S][NQKV]; Q at col h*64, K at DD+h*64, V at 2*DD+h*64.
// grid (HH, 78): y<62 -> mid q-block y+1; y>=62 -> edge t=y-62: e=t>>3, z=t&7.
// 128 threads = 4 warps, each warp 16 q rows. bf16x3 everywhere.
#define AS_QH 0
#define AS_QL 8192
#define AS_KV 16384
#define ATTN_SMEM (16384 + 2 * 32768)

__global__ void __launch_bounds__(128)
attn_mma_kernel(const __nv_bfloat16* __restrict__ qh, const __nv_bfloat16* __restrict__ ql,
                const int* __restrict__ rnd,
                __nv_bfloat16* __restrict__ th, __nv_bfloat16* __restrict__ tl,
                float* __restrict__ pO, float* __restrict__ pm, float* __restrict__ pl)
{
    extern __shared__ __align__(128) char smem[];
    uint32_t sb = smem_addr(smem);
    int h = blockIdx.x, y = blockIdx.y;
    int tid = threadIdx.x, lane = tid & 31, w = tid >> 5;

    int qb, e = 0, z = 0;
    bool edge;
    if (y < 62) { qb = y + 1; edge = false; }
    else        { int t = y - 62; e = t >> 3; z = t & 7; qb = e ? (NBB - 1) : 0; edge = true; }

    int blks[8];
    if (edge) {
#pragma unroll
        for (int i = 0; i < 8; i++) blks[i] = z * 8 + i;
    } else {
        blks[0] = 0; blks[1] = NBB - 1; blks[2] = qb - 1; blks[3] = qb; blks[4] = qb + 1;
        const int* rp = rnd + (h * NBB + qb) * RRR;
        blks[5] = rp[0]; blks[6] = rp[1]; blks[7] = rp[2];
    }

    // ---- prologue: Q tiles + first KV block via cp.async ----
    {
        int colq = h * DHH;
#pragma unroll
        for (int i = 0; i < 8; i++) {
            int idx = tid + i * 128;              // 0..1023
            int t = idx >> 9, rem = idx & 511;
            int row = rem >> 3, cu = rem & 7;
            const __nv_bfloat16* src = (t ? ql : qh) + (size_t)(qb * BSS + row) * NQKV + colq + cu * 8;
            uint32_t dst = sb + (t ? AS_QL : AS_QH) + row * 128 + ((cu ^ (row & 7)) << 4);
            CP_ASYNC(dst, src);
        }
    }
#define LOAD_KV(STG, KB) do {                                                   \
    uint32_t base_ = sb + AS_KV + (STG) * 32768;                                \
    _Pragma("unroll")                                                           \
    for (int i_ = 0; i_ < 16; i_++) {                                           \
        int idx_ = tid + i_ * 128;                                              \
        int t_ = idx_ >> 9, rem_ = idx_ & 511;                                  \
        int row_ = rem_ >> 3, cu_ = rem_ & 7;                                   \
        int col_ = ((t_ >> 1) + 1) * DD + h * DHH + cu_ * 8;                    \
        const __nv_bfloat16* src_ = ((t_ & 1) ? ql : qh) +                      \
            (size_t)((KB) * BSS + row_) * NQKV + col_;                          \
        uint32_t dst_ = base_ + t_ * 8192 + row_ * 128 + ((cu_ ^ (row_ & 7)) << 4); \
        CP_ASYNC(dst_, src_);                                                   \
    }                                                                           \
} while (0)

    LOAD_KV(0, blks[0]);
    CP_COMMIT();
    CP_WAIT(0);
    __syncthreads();

    // ---- Q fragments in registers (fixed across key blocks) ----
    uint32_t qfh[4][4], qfl[4][4];
#pragma unroll
    for (int ds = 0; ds < 4; ds++) {
        int row = w * 16 + (lane & 15);
        int cu = ds * 2 + (lane >> 4);
        uint32_t off = row * 128 + ((cu ^ (row & 7)) << 4);
        ldsm_x4(sb + AS_QH + off, qfh[ds]);
        ldsm_x4(sb + AS_QL + off, qfl[ds]);
    }

    float o[8][4];
    float m[2] = {-1e30f, -1e30f}, l[2] = {0.f, 0.f};
#pragma unroll
    for (int j = 0; j < 8; j++)
#pragma unroll
        for (int u = 0; u < 4; u++) o[j][u] = 0.f;

    const float sc = 0.125f;

    for (int b = 0; b < 8; b++) {
        if (b + 1 < 8) { LOAD_KV((b + 1) & 1, blks[b + 1]); CP_COMMIT(); }
        uint32_t st = sb + AS_KV + (b & 1) * 32768;

        // ---- S = Q K^T (bf16x3) ----
        float s[8][4];
#pragma unroll
        for (int j = 0; j < 8; j++)
#pragma unroll
            for (int u = 0; u < 4; u++) s[j][u] = 0.f;
#pragma unroll
        for (int kb = 0; kb < 4; kb++) {
#pragma unroll
            for (int ds = 0; ds < 4; ds++) {
                int row = kb * 16 + (lane & 15);
                int cu = ds * 2 + (lane >> 4);
                uint32_t off = st + row * 128 + ((cu ^ (row & 7)) << 4);
                uint32_t kh4[4], kl4[4];
                ldsm_x4(off, kh4);          // Kh
                ldsm_x4(off + 8192, kl4);   // Kl
                mma4(s[2 * kb],     qfh[ds], kh4[0], kh4[2]);
                mma4(s[2 * kb],     qfh[ds], kl4[0], kl4[2]);
                mma4(s[2 * kb],     qfl[ds], kh4[0], kh4[2]);
                mma4(s[2 * kb + 1], qfh[ds], kh4[1], kh4[3]);
                mma4(s[2 * kb + 1], qfh[ds], kl4[1], kl4[3]);
                mma4(s[2 * kb + 1], qfl[ds], kh4[1], kh4[3]);
            }
        }

        // ---- online softmax (rows g and g+8) ----
#pragma unroll
        for (int hf = 0; hf < 2; hf++) {
            float rm = -1e30f;
#pragma unroll
            for (int j = 0; j < 8; j++)
                rm = fmaxf(rm, fmaxf(s[j][hf * 2], s[j][hf * 2 + 1]));
            rm *= sc;
            rm = fmaxf(rm, __shfl_xor_sync(0xffffffffu, rm, 1));
            rm = fmaxf(rm, __shfl_xor_sync(0xffffffffu, rm, 2));
            float mn = fmaxf(m[hf], rm);
            float corr = __expf(m[hf] - mn);
            m[hf] = mn;
            float rs = 0.f;
#pragma unroll
            for (int j = 0; j < 8; j++) {
                s[j][hf * 2]     = __expf(s[j][hf * 2]     * sc - mn);
                s[j][hf * 2 + 1] = __expf(s[j][hf * 2 + 1] * sc - mn);
                rs += s[j][hf * 2] + s[j][hf * 2 + 1];
            }
            rs += __shfl_xor_sync(0xffffffffu, rs, 1);
            rs += __shfl_xor_sync(0xffffffffu, rs, 2);
            l[hf] = l[hf] * corr + rs;
#pragma unroll
            for (int j = 0; j < 8; j++) {
                o[j][hf * 2]     *= corr;
                o[j][hf * 2 + 1] *= corr;
            }
        }

        // ---- O += P V (bf16x3) ----
#pragma unroll
        for (int ks = 0; ks < 4; ks++) {
            uint32_t ph4[4], pl4[4];
            split2(s[2 * ks][0],     s[2 * ks][1],     ph4[0], pl4[0]);
            split2(s[2 * ks][2],     s[2 * ks][3],     ph4[1], pl4[1]);
            split2(s[2 * ks + 1][0], s[2 * ks + 1][1], ph4[2], pl4[2]);
            split2(s[2 * ks + 1][2], s[2 * ks + 1][3], ph4[3], pl4[3]);
#pragma unroll
            for (int dc = 0; dc < 4; dc++) {
                int row = ks * 16 + (lane & 15);
                int cu = dc * 2 + (lane >> 4);
                uint32_t off = st + 16384 + row * 128 + ((cu ^ (row & 7)) << 4);
                uint32_t vh4[4], vl4[4];
                ldsm_x4_t(off, vh4);          // Vh (transposed load)
                ldsm_x4_t(off + 8192, vl4);   // Vl
                mma4(o[2 * dc],     ph4, vh4[0], vh4[1]);
                mma4(o[2 * dc],     ph4, vl4[0], vl4[1]);
                mma4(o[2 * dc],     pl4, vh4[0], vh4[1]);
                mma4(o[2 * dc + 1], ph4, vh4[2], vh4[3]);
                mma4(o[2 * dc + 1], ph4, vl4[2], vl4[3]);
                mma4(o[2 * dc + 1], pl4, vh4[2], vh4[3]);
            }
        }

        if (b + 1 < 8) { CP_WAIT(0); __syncthreads(); }
    }

    // ---- epilogue ----
    int g = lane >> 2;
    if (!edge) {
#pragma unroll
        for (int hf = 0; hf < 2; hf++) {
            float inv = 1.f / l[hf];
            int row = qb * BSS + w * 16 + g + hf * 8;
#pragma unroll
            for (int j = 0; j < 8; j++) {
                int col = h * DHH + j * 8 + (lane & 3) * 2;
                uint32_t hi, lo;
                split2(o[j][hf * 2] * inv, o[j][hf * 2 + 1] * inv, hi, lo);
                *(uint32_t*)(th + (size_t)row * DD + col) = hi;
                *(uint32_t*)(tl + (size_t)row * DD + col) = lo;
            }
        }
    } else {
        int cb = (h * 2 + e) * 8 + z;
        float* po = pO + (size_t)cb * 64 * 64;
#pragma unroll
        for (int hf = 0; hf < 2; hf++) {
            int qr = w * 16 + g + hf * 8;
#pragma unroll
            for (int j = 0; j < 8; j++) {
                float2 val; val.x = o[j][hf * 2]; val.y = o[j][hf * 2 + 1];
                *(float2*)(po + qr * 64 + j * 8 + (lane & 3) * 2) = val;
            }
            if ((lane & 3) == 0) {
                pm[cb * 64 + qr] = m[hf];
                pl[cb * 64 + qr] = l[hf];
            }
        }
    }
}

// combine edge partials: grid (24, 64), 64 threads (d)
__global__ void __launch_bounds__(64)
attn_combine(const float* __restrict__ pO, const float* __restrict__ pm,
             const float* __restrict__ pl,
             __nv_bfloat16* __restrict__ th, __nv_bfloat16* __restrict__ tl)
{
    int he = blockIdx.x, q = blockIdx.y, d = threadIdx.x;
    int h = he >> 1, e = he & 1;
    float mv[8], M = -1e30f;
#pragma unroll
    for (int z = 0; z < 8; z++) {
        mv[z] = pm[(he * 8 + z) * 64 + q];
        M = fmaxf(M, mv[z]);
    }
    float L = 0.f, O = 0.f;
#pragma unroll
    for (int z = 0; z < 8; z++) {
        float w = __expf(mv[z] - M);
        L += w * pl[(he * 8 + z) * 64 + q];
        O += w * pO[((size_t)(he * 8 + z) * 64 + q) * 64 + d];
    }
    float r = O / L;
    int row = (e ? (NBB - 1) : 0) * BSS + q;
    write_split(th, tl, row * DD + h * DHH + d, r);
}

// ---------------- classifier --------------------------------------------------
__global__ __launch_bounds__(256) void classifier_kernel(
    const float* __restrict__ h, const float* __restrict__ Wc,
    const float* __restrict__ bc, float* __restrict__ out)
{
    int warp = threadIdx.x >> 5, lane = threadIdx.x & 31;
    if (warp >= CCC) return;
    const float* hr = h + (long long)(SS - 1) * DD;
    float s = 0.f;
    for (int d = lane; d < DD; d += 32) s += hr[d] * Wc[d * CCC + warp];
#pragma unroll
    for (int off = 16; off; off >>= 1) s += __shfl_xor_sync(0xffffffffu, s, off);
    if (lane == 0) out[warp] = s + bc[warp];
}

// ---------------- launch ------------------------------------------------------
extern "C" void kernel_launch(void* const* d_in, const int* in_sizes, int n_in,
                              void* d_out, int out_size)
{
    (void)in_sizes; (void)n_in; (void)out_size;
    const int*   input_ids = (const int*)  d_in[0];
    const int*   rand_attn = (const int*)  d_in[1];
    const float* word_emb  = (const float*)d_in[2];
    const float* pos_emb   = (const float*)d_in[3];
    const float* eln_w     = (const float*)d_in[4];
    const float* eln_b     = (const float*)d_in[5];
    const float* Wq        = (const float*)d_in[6];
    const float* bq        = (const float*)d_in[7];
    const float* Wk        = (const float*)d_in[8];
    const float* bk        = (const float*)d_in[9];
    const float* Wv        = (const float*)d_in[10];
    const float* bv        = (const float*)d_in[11];
    const float* Wo        = (const float*)d_in[12];
    const float* bo        = (const float*)d_in[13];
    const float* ln1_w     = (const float*)d_in[14];
    const float* ln1_b     = (const float*)d_in[15];
    const float* W1        = (const float*)d_in[16];
    const float* b1        = (const float*)d_in[17];
    const float* W2        = (const float*)d_in[18];
    const float* b2        = (const float*)d_in[19];
    const float* ln2_w     = (const float*)d_in[20];
    const float* ln2_b     = (const float*)d_in[21];
    const float* Wc        = (const float*)d_in[22];
    const float* bc        = (const float*)d_in[23];
    float* out = (float*)d_out;

    cudaFuncSetAttribute(gemm_mma, cudaFuncAttributeMaxDynamicSharedMemorySize, GEMM_SMEM);
    cudaFuncSetAttribute(attn_mma_kernel, cudaFuncAttributeMaxDynamicSharedMemorySize, ATTN_SMEM);

    float *h, *a, *bias3, *pO, *pm, *pl;
    __nv_bfloat16 *ah, *al, *bh, *bl, *wh, *wl;
    cudaGetSymbolAddress((void**)&h,    g_h);
    cudaGetSymbolAddress((void**)&a,    g_a);
    cudaGetSymbolAddress((void**)&ah,   g_ah);
    cudaGetSymbolAddress((void**)&al,   g_al);
    cudaGetSymbolAddress((void**)&bh,   g_bh);
    cudaGetSymbolAddress((void**)&bl,   g_bl);
    cudaGetSymbolAddress((void**)&wh,   g_wh);
    cudaGetSymbolAddress((void**)&wl,   g_wl);
    cudaGetSymbolAddress((void**)&bias3, g_bias3);
    cudaGetSymbolAddress((void**)&pO,   g_pO);
    cudaGetSymbolAddress((void**)&pm,   g_pm);
    cudaGetSymbolAddress((void**)&pl,   g_pl);

    embed_ln_split<<<SS, 256>>>(input_ids, word_emb, pos_emb, eln_w, eln_b, h, ah, al);

    for (int l = 0; l < 2; l++) {
        long long wofs = (long long)l * DD * DD;

        // ---- fused QKV projection -> split bf16 qkv in bh/bl ----
        conv_wt<<<dim3(DD/32, DD/32), 256>>>(Wq + wofs, wh,           wl,           DD, DD);
        conv_wt<<<dim3(DD/32, DD/32), 256>>>(Wk + wofs, wh + DD*DD,   wl + DD*DD,   DD, DD);
        conv_wt<<<dim3(DD/32, DD/32), 256>>>(Wv + wofs, wh + 2*DD*DD, wl + 2*DD*DD, DD, DD);
        concat3<<<3, 256>>>(bq + l*DD, bk + l*DD, bv + l*DD, bias3);
        gemm_mma<<<dim3(NQKV/128, SS/128), 256, GEMM_SMEM>>>(
            ah, al, wh, wl, bias3, nullptr, bh, bl, SS, NQKV, DD, 3);

        // ---- MMA flash attention (writes split bf16 into ah/al) ----
        attn_mma_kernel<<<dim3(HH, 78), 128, ATTN_SMEM>>>(
            bh, bl, rand_attn + l*HH*NBB*RRR, ah, al, pO, pm, pl);
        attn_combine<<<dim3(24, 64), 64>>>(pO, pm, pl, ah, al);

        // ---- O projection + LN ----
        conv_wt<<<dim3(DD/32, DD/32), 256>>>(Wo + wofs, wh, wl, DD, DD);
        gemm_mma<<<dim3(DD/128, SS/128), 256, GEMM_SMEM>>>(
            ah, al, wh, wl, bo + l*DD, a, nullptr, nullptr, SS, DD, DD, 0);
        add_ln_split<<<SS, 256>>>(h, a, ln1_w + l*DD, ln1_b + l*DD, ah, al);

        // ---- FFN ----
        conv_wt<<<dim3(FFF/32, DD/32), 256>>>(W1 + (long long)l*DD*FFF, wh, wl, DD, FFF);
        gemm_mma<<<dim3(FFF/128, SS/128), 256, GEMM_SMEM>>>(
            ah, al, wh, wl, b1 + l*FFF, nullptr, bh, bl, SS, FFF, DD, 2);
        conv_wt<<<dim3(DD/32, FFF/32), 256>>>(W2 + (long long)l*FFF*DD, wh, wl, FFF, DD);
        gemm_mma<<<dim3(DD/128, SS/128), 256, GEMM_SMEM>>>(
            bh, bl, wh, wl, b2 + l*DD, a, nullptr, nullptr, SS, DD, FFF, 0);
        add_ln_split<<<SS, 256>>>(h, a, ln2_w + l*DD, ln2_b + l*DD, ah, al);
    }

    classifier_kernel<<<1, 256>>>(h, Wc, bc, out);
}

// round 9
// speedup vs baseline: 6.7805x; 1.2336x over previous
#include <cuda_runtime.h>
#include <cuda_fp16.h>
#include <math.h>
#include <stdint.h>

#define SS 4096
#define DD 768
#define HH 12
#define DHH 64
#define NBB 64
#define BSS 64
#define RRR 3
#define FFF 3072
#define CCC 8
#define NQKV 2304

// ---------------- scratch (device globals; no allocation allowed) -----------
__device__ __align__(16) float g_h  [SS*DD];
__device__ __align__(16) float g_a  [SS*DD];
__device__ __align__(16) __half g_ah[SS*FFF];
__device__ __align__(16) __half g_al[SS*FFF];
__device__ __align__(16) __half g_bh[SS*FFF];
__device__ __align__(16) __half g_bl[SS*FFF];
__device__ __align__(16) __half g_wh[FFF*DD];
__device__ __align__(16) __half g_wl[FFF*DD];
__device__ __align__(16) float g_bias3[NQKV];
// edge-attention partials: 24 (h,e) x 8 chunks x 64 q x 64 d
__device__ __align__(16) float g_pO[24*8*64*64];
__device__ __align__(16) float g_pm[24*8*64];
__device__ __align__(16) float g_pl[24*8*64];

// ---------------- PTX helpers ------------------------------------------------
__device__ __forceinline__ uint32_t smem_addr(const void* p) {
    uint32_t a;
    asm("{ .reg .u64 t; cvta.to.shared.u64 t, %1; cvt.u32.u64 %0, t; }" : "=r"(a) : "l"(p));
    return a;
}
__device__ __forceinline__ void ldsm_x4(uint32_t addr, uint32_t* r) {
    asm volatile("ldmatrix.sync.aligned.m8n8.x4.shared.b16 {%0,%1,%2,%3}, [%4];"
        : "=r"(r[0]), "=r"(r[1]), "=r"(r[2]), "=r"(r[3]) : "r"(addr));
}
__device__ __forceinline__ void ldsm_x4_t(uint32_t addr, uint32_t* r) {
    asm volatile("ldmatrix.sync.aligned.m8n8.x4.trans.shared.b16 {%0,%1,%2,%3}, [%4];"
        : "=r"(r[0]), "=r"(r[1]), "=r"(r[2]), "=r"(r[3]) : "r"(addr));
}
__device__ __forceinline__ void mma_f16(float* c, const uint32_t* a, const uint32_t* b) {
    asm volatile("mma.sync.aligned.m16n8k16.row.col.f32.f16.f16.f32 "
        "{%0,%1,%2,%3}, {%4,%5,%6,%7}, {%8,%9}, {%0,%1,%2,%3};"
        : "+f"(c[0]), "+f"(c[1]), "+f"(c[2]), "+f"(c[3])
        : "r"(a[0]), "r"(a[1]), "r"(a[2]), "r"(a[3]), "r"(b[0]), "r"(b[1]));
}
__device__ __forceinline__ void mma4(float* c, const uint32_t* a, uint32_t b0, uint32_t b1) {
    uint32_t b[2] = {b0, b1};
    mma_f16(c, a, b);
}
#define CP_ASYNC(dst, src) asm volatile("cp.async.cg.shared.global [%0], [%1], 16;" :: "r"(dst), "l"(src))
#define CP_COMMIT()        asm volatile("cp.async.commit_group;")
#define CP_WAIT(n)         asm volatile("cp.async.wait_group %0;" :: "n"(n))

__device__ __forceinline__ uint32_t pack_h2(__half a, __half b) {
    __half2 t; t.x = a; t.y = b;
    return *(uint32_t*)&t;
}
__device__ __forceinline__ void split2h(float a, float b, uint32_t& hi, uint32_t& lo) {
    __half ha = __float2half_rn(a), hb = __float2half_rn(b);
    __half la = __float2half_rn(a - __half2float(ha));
    __half lb = __float2half_rn(b - __half2float(hb));
    hi = pack_h2(ha, hb);
    lo = pack_h2(la, lb);
}
__device__ __forceinline__ void write_splith(__half* hi, __half* lo, int idx, float v) {
    __half h = __float2half_rn(v);
    hi[idx] = h;
    lo[idx] = __float2half_rn(v - __half2float(h));
}

// ---------------- fp16 multi-pass GEMM via mma.sync ---------------------------
// C[M,N] = (Ah+Al)[M,K] * B[N,K]^T + bias.
// NPASS=2: B = Bh only        (passes Ah*Bh + Al*Bh)
// NPASS=3: B = Bh+Bl          (passes Ah*Bh + Ah*Bl + Al*Bh)
// modes: 0 fp32 out, 2 gelu + split fp16 out, 3 split fp16 out (no gelu)
#define GEMM_SMEM 131072

template<int NPASS>
__global__ void __launch_bounds__(256, 1)
gemm_mma(const __half* __restrict__ Ah, const __half* __restrict__ Al,
         const __half* __restrict__ Bh, const __half* __restrict__ Bl,
         const float* __restrict__ bias, float* __restrict__ C,
         __half* __restrict__ Oh, __half* __restrict__ Ol,
         int M, int N, int K, int mode)
{
    extern __shared__ __align__(128) char smem[];
    uint32_t sb = smem_addr(smem);
    int tid = threadIdx.x, lane = tid & 31, wid = tid >> 5;
    int wm = wid & 1, wn = wid >> 1;
    int n0 = blockIdx.x * 128, m0 = blockIdx.y * 128;
    const int KT = K >> 6;
    const int NT = (NPASS == 3) ? 4 : 3;

    const __half* srcs[4];
    srcs[0] = Ah + (size_t)m0 * K;
    srcs[1] = Al + (size_t)m0 * K;
    srcs[2] = Bh + (size_t)n0 * K;
    srcs[3] = (NPASS == 3) ? (Bl + (size_t)n0 * K) : srcs[2];

    float acc[4][4][4];
#pragma unroll
    for (int i = 0; i < 4; i++)
#pragma unroll
        for (int j = 0; j < 4; j++)
#pragma unroll
            for (int u = 0; u < 4; u++) acc[i][j][u] = 0.f;

#define LOAD_STAGE(S, KT_IDX) do {                                              \
    uint32_t sbase_ = sb + (S) * 65536;                                         \
    int ko_ = (KT_IDX) * 64;                                                    \
    _Pragma("unroll")                                                           \
    for (int t_ = 0; t_ < NT; t_++) {                                           \
        const __half* sp_ = srcs[t_];                                           \
        _Pragma("unroll")                                                       \
        for (int i_ = 0; i_ < 4; i_++) {                                        \
            int id_ = tid + i_ * 256;                                           \
            int row_ = id_ >> 3, c_ = id_ & 7;                                  \
            const __half* src_ = sp_ + (size_t)row_ * K + ko_ + c_ * 8;         \
            uint32_t dst_ = sbase_ + t_ * 16384 + row_ * 128 + ((c_ ^ (row_ & 7)) << 4); \
            CP_ASYNC(dst_, src_);                                               \
        }                                                                       \
    }                                                                           \
    CP_COMMIT();                                                                \
} while (0)

    LOAD_STAGE(0, 0);

    for (int kt = 0; kt < KT; kt++) {
        if (kt + 1 < KT) { LOAD_STAGE((kt + 1) & 1, kt + 1); CP_WAIT(1); }
        else             { CP_WAIT(0); }
        __syncthreads();
        uint32_t st = sb + (kt & 1) * 65536;
#pragma unroll
        for (int ks = 0; ks < 4; ks++) {
            uint32_t ahf[4][4], alf[4][4], bhf[2][4], blf[2][4];
#pragma unroll
            for (int mt = 0; mt < 4; mt++) {
                int row = wm * 64 + mt * 16 + (lane & 15);
                int kc = ks * 2 + (lane >> 4);
                uint32_t off = row * 128 + ((kc ^ (row & 7)) << 4);
                ldsm_x4(st + off, ahf[mt]);
                ldsm_x4(st + 16384 + off, alf[mt]);
            }
#pragma unroll
            for (int np = 0; np < 2; np++) {
                int row = wn * 32 + np * 16 + ((lane & 7) | ((lane & 16) >> 1));
                int kc = ks * 2 + ((lane >> 3) & 1);
                uint32_t off = row * 128 + ((kc ^ (row & 7)) << 4);
                ldsm_x4(st + 32768 + off, bhf[np]);
                if (NPASS == 3) ldsm_x4(st + 49152 + off, blf[np]);
            }
#pragma unroll
            for (int mt = 0; mt < 4; mt++)
#pragma unroll
                for (int nt = 0; nt < 4; nt++) {
                    const uint32_t* bh_ = &bhf[nt >> 1][(nt & 1) * 2];
                    mma_f16(acc[mt][nt], ahf[mt], bh_);
                    mma_f16(acc[mt][nt], alf[mt], bh_);
                    if (NPASS == 3) {
                        const uint32_t* bl_ = &blf[nt >> 1][(nt & 1) * 2];
                        mma_f16(acc[mt][nt], ahf[mt], bl_);
                    }
                }
        }
        __syncthreads();
    }

#pragma unroll
    for (int mt = 0; mt < 4; mt++) {
        int mbase = m0 + wm * 64 + mt * 16 + (lane >> 2);
#pragma unroll
        for (int nt = 0; nt < 4; nt++) {
            int n = n0 + wn * 32 + nt * 8 + (lane & 3) * 2;
            float b0 = bias[n], b1 = bias[n + 1];
#pragma unroll
            for (int half = 0; half < 2; half++) {
                int m = mbase + half * 8;
                float v0 = acc[mt][nt][half * 2 + 0] + b0;
                float v1 = acc[mt][nt][half * 2 + 1] + b1;
                if (mode == 2) {
                    float u0 = 0.7978845608028654f * (v0 + 0.044715f * v0 * v0 * v0);
                    v0 = 0.5f * v0 * (1.f + tanhf(u0));
                    float u1 = 0.7978845608028654f * (v1 + 0.044715f * v1 * v1 * v1);
                    v1 = 0.5f * v1 * (1.f + tanhf(u1));
                }
                if (mode >= 2) {
                    uint32_t hi, lo;
                    split2h(v0, v1, hi, lo);
                    *(uint32_t*)(Oh + (size_t)m * N + n) = hi;
                    *(uint32_t*)(Ol + (size_t)m * N + n) = lo;
                } else {
                    float2 o; o.x = v0; o.y = v1;
                    *(float2*)(C + (size_t)m * N + n) = o;
                }
            }
        }
    }
}

// ---------------- W[K,N] fp32 -> Wt[N,K] fp16 hi (+lo) ------------------------
__global__ __launch_bounds__(256) void conv_wt(const float* __restrict__ W,
    __half* __restrict__ th, __half* __restrict__ tl, int K, int N)
{
    __shared__ float tile[32][33];
    int k0 = blockIdx.y * 32, n0 = blockIdx.x * 32;
    int tx = threadIdx.x & 31, ty = threadIdx.x >> 5;
#pragma unroll
    for (int r = ty; r < 32; r += 8)
        tile[r][tx] = W[(size_t)(k0 + r) * N + n0 + tx];
    __syncthreads();
#pragma unroll
    for (int r = ty; r < 32; r += 8) {
        float v = tile[tx][r];
        __half hh = __float2half_rn(v);
        size_t o = (size_t)(n0 + r) * K + k0 + tx;
        th[o] = hh;
        if (tl) tl[o] = __float2half_rn(v - __half2float(hh));
    }
}

__global__ __launch_bounds__(256) void concat3(const float* __restrict__ a,
    const float* __restrict__ b, const float* __restrict__ c, float* __restrict__ o)
{
    int i = blockIdx.x * 256 + threadIdx.x;
    if (i < DD) { o[i] = a[i]; o[DD + i] = b[i]; o[2 * DD + i] = c[i]; }
}

// ---------------- reductions -------------------------------------------------
__device__ __forceinline__ void block_reduce2(float &s1v, float &s2v) {
    __shared__ float sa[8], sb2[8];
    int lane = threadIdx.x & 31, w = threadIdx.x >> 5;
#pragma unroll
    for (int off = 16; off; off >>= 1) {
        s1v += __shfl_xor_sync(0xffffffffu, s1v, off);
        s2v += __shfl_xor_sync(0xffffffffu, s2v, off);
    }
    if (lane == 0) { sa[w] = s1v; sb2[w] = s2v; }
    __syncthreads();
    if (w == 0) {
        s1v = (lane < 8) ? sa[lane] : 0.f;
        s2v = (lane < 8) ? sb2[lane] : 0.f;
#pragma unroll
        for (int off = 4; off; off >>= 1) {
            s1v += __shfl_xor_sync(0xffffffffu, s1v, off);
            s2v += __shfl_xor_sync(0xffffffffu, s2v, off);
        }
        if (lane == 0) { sa[0] = s1v; sb2[0] = s2v; }
    }
    __syncthreads();
    s1v = sa[0]; s2v = sb2[0];
}

// ---------------- embedding + LN (split out) ---------------------------------
__global__ __launch_bounds__(256) void embed_ln_split(
    const int* __restrict__ ids, const float* __restrict__ we,
    const float* __restrict__ pe, const float* __restrict__ w,
    const float* __restrict__ b, float* __restrict__ out,
    __half* __restrict__ oh, __half* __restrict__ ol)
{
    int row = blockIdx.x;
    int id = ids[row];
    float x[3], sum = 0.f, sq = 0.f;
#pragma unroll
    for (int r = 0; r < 3; r++) {
        int i = threadIdx.x + r * 256;
        x[r] = we[(long long)id * DD + i] + pe[row * DD + i];
        sum += x[r]; sq += x[r] * x[r];
    }
    block_reduce2(sum, sq);
    float mean = sum * (1.f / DD);
    float var  = sq * (1.f / DD) - mean * mean;
    float inv  = rsqrtf(var + 1e-12f);
#pragma unroll
    for (int r = 0; r < 3; r++) {
        int i = threadIdx.x + r * 256;
        float y = (x[r] - mean) * inv * w[i] + b[i];
        out[row * DD + i] = y;
        write_splith(oh, ol, row * DD + i, y);
    }
}

// ---------------- residual add + LN (split out) -------------------------------
__global__ __launch_bounds__(256) void add_ln_split(
    float* __restrict__ h, const float* __restrict__ a,
    const float* __restrict__ w, const float* __restrict__ b,
    __half* __restrict__ oh, __half* __restrict__ ol)
{
    int row = blockIdx.x;
    float x[3], sum = 0.f, sq = 0.f;
#pragma unroll
    for (int r = 0; r < 3; r++) {
        int i = threadIdx.x + r * 256;
        x[r] = h[row * DD + i] + a[row * DD + i];
        sum += x[r]; sq += x[r] * x[r];
    }
    block_reduce2(sum, sq);
    float mean = sum * (1.f / DD);
    float var  = sq * (1.f / DD) - mean * mean;
    float inv  = rsqrtf(var + 1e-12f);
#pragma unroll
    for (int r = 0; r < 3; r++) {
        int i = threadIdx.x + r * 256;
        float y = (x[r] - mean) * inv * w[i] + b[i];
        h[row * DD + i] = y;
        write_splith(oh, ol, row * DD + i, y);
    }
}

// ---------------- MMA flash attention (fp16) ----------------------------------
// sh/sl: split fp16 QKV [S][NQKV]; Q at col h*64, K at DD+h*64, V at 2*DD+h*64.
// S = Qh*Kh + Qh*Kl + Ql*Kh (3-pass); O = Ph*Vh + Pl*Vh (2-pass, V hi only).
// grid (HH, 78): y<62 -> mid q-block y+1; y>=62 -> edge t=y-62: e=t>>3, z=t&7.
#define AS_QH 0
#define AS_QL 8192
#define AS_KV 16384
#define KV_STAGE 24576
#define ATTN_SMEM (16384 + 2 * KV_STAGE)

__global__ void __launch_bounds__(128)
attn_mma_kernel(const __half* __restrict__ sh, const __half* __restrict__ sl,
                const int* __restrict__ rnd,
                __half* __restrict__ th, __half* __restrict__ tl,
                float* __restrict__ pO, float* __restrict__ pm, float* __restrict__ pl)
{
    extern __shared__ __align__(128) char smem[];
    uint32_t sb = smem_addr(smem);
    int h = blockIdx.x, y = blockIdx.y;
    int tid = threadIdx.x, lane = tid & 31, w = tid >> 5;

    int qb, e = 0, z = 0;
    bool edge;
    if (y < 62) { qb = y + 1; edge = false; }
    else        { int t = y - 62; e = t >> 3; z = t & 7; qb = e ? (NBB - 1) : 0; edge = true; }

    int blks[8];
    if (edge) {
#pragma unroll
        for (int i = 0; i < 8; i++) blks[i] = z * 8 + i;
    } else {
        blks[0] = 0; blks[1] = NBB - 1; blks[2] = qb - 1; blks[3] = qb; blks[4] = qb + 1;
        const int* rp = rnd + (h * NBB + qb) * RRR;
        blks[5] = rp[0]; blks[6] = rp[1]; blks[7] = rp[2];
    }

    // ---- prologue: Q tiles (hi+lo) via cp.async ----
    {
        int colq = h * DHH;
#pragma unroll
        for (int i = 0; i < 8; i++) {
            int idx = tid + i * 128;              // 0..1023
            int t = idx >> 9, rem = idx & 511;
            int row = rem >> 3, cu = rem & 7;
            const __half* src = (t ? sl : sh) + (size_t)(qb * BSS + row) * NQKV + colq + cu * 8;
            uint32_t dst = sb + (t ? AS_QL : AS_QH) + row * 128 + ((cu ^ (row & 7)) << 4);
            CP_ASYNC(dst, src);
        }
    }
    // KV stage tiles: t0 = Kh, t1 = Kl, t2 = Vh (24KB per stage)
#define LOAD_KV(STG, KB) do {                                                   \
    uint32_t base_ = sb + AS_KV + (STG) * KV_STAGE;                             \
    _Pragma("unroll")                                                           \
    for (int i_ = 0; i_ < 12; i_++) {                                           \
        int idx_ = tid + i_ * 128;                                              \
        int t_ = idx_ >> 9, rem_ = idx_ & 511;                                  \
        int row_ = rem_ >> 3, cu_ = rem_ & 7;                                   \
        const __half* arr_ = (t_ == 1) ? sl : sh;                               \
        int col_ = ((t_ == 2) ? 2 : 1) * DD + h * DHH + cu_ * 8;                \
        const __half* src_ = arr_ + (size_t)((KB) * BSS + row_) * NQKV + col_;  \
        uint32_t dst_ = base_ + t_ * 8192 + row_ * 128 + ((cu_ ^ (row_ & 7)) << 4); \
        CP_ASYNC(dst_, src_);                                                   \
    }                                                                           \
} while (0)

    LOAD_KV(0, blks[0]);
    CP_COMMIT();
    CP_WAIT(0);
    __syncthreads();

    // ---- Q fragments in registers (fixed across key blocks) ----
    uint32_t qfh[4][4], qfl[4][4];
#pragma unroll
    for (int ds = 0; ds < 4; ds++) {
        int row = w * 16 + (lane & 15);
        int cu = ds * 2 + (lane >> 4);
        uint32_t off = row * 128 + ((cu ^ (row & 7)) << 4);
        ldsm_x4(sb + AS_QH + off, qfh[ds]);
        ldsm_x4(sb + AS_QL + off, qfl[ds]);
    }

    float o[8][4];
    float m[2] = {-1e30f, -1e30f}, l[2] = {0.f, 0.f};
#pragma unroll
    for (int j = 0; j < 8; j++)
#pragma unroll
        for (int u = 0; u < 4; u++) o[j][u] = 0.f;

    const float sc = 0.125f;

    for (int b = 0; b < 8; b++) {
        if (b + 1 < 8) { LOAD_KV((b + 1) & 1, blks[b + 1]); CP_COMMIT(); }
        uint32_t st = sb + AS_KV + (b & 1) * KV_STAGE;

        // ---- S = Q K^T (3-pass fp16) ----
        float s[8][4];
#pragma unroll
        for (int j = 0; j < 8; j++)
#pragma unroll
            for (int u = 0; u < 4; u++) s[j][u] = 0.f;
#pragma unroll
        for (int kb = 0; kb < 4; kb++) {
#pragma unroll
            for (int ds = 0; ds < 4; ds++) {
                int row = kb * 16 + (lane & 15);
                int cu = ds * 2 + (lane >> 4);
                uint32_t off = st + row * 128 + ((cu ^ (row & 7)) << 4);
                uint32_t kh4[4], kl4[4];
                ldsm_x4(off, kh4);          // Kh
                ldsm_x4(off + 8192, kl4);   // Kl
                mma4(s[2 * kb],     qfh[ds], kh4[0], kh4[2]);
                mma4(s[2 * kb],     qfh[ds], kl4[0], kl4[2]);
                mma4(s[2 * kb],     qfl[ds], kh4[0], kh4[2]);
                mma4(s[2 * kb + 1], qfh[ds], kh4[1], kh4[3]);
                mma4(s[2 * kb + 1], qfh[ds], kl4[1], kl4[3]);
                mma4(s[2 * kb + 1], qfl[ds], kh4[1], kh4[3]);
            }
        }

        // ---- online softmax (rows g and g+8) ----
#pragma unroll
        for (int hf = 0; hf < 2; hf++) {
            float rm = -1e30f;
#pragma unroll
            for (int j = 0; j < 8; j++)
                rm = fmaxf(rm, fmaxf(s[j][hf * 2], s[j][hf * 2 + 1]));
            rm *= sc;
            rm = fmaxf(rm, __shfl_xor_sync(0xffffffffu, rm, 1));
            rm = fmaxf(rm, __shfl_xor_sync(0xffffffffu, rm, 2));
            float mn = fmaxf(m[hf], rm);
            float corr = __expf(m[hf] - mn);
            m[hf] = mn;
            float rs = 0.f;
#pragma unroll
            for (int j = 0; j < 8; j++) {
                s[j][hf * 2]     = __expf(s[j][hf * 2]     * sc - mn);
                s[j][hf * 2 + 1] = __expf(s[j][hf * 2 + 1] * sc - mn);
                rs += s[j][hf * 2] + s[j][hf * 2 + 1];
            }
            rs += __shfl_xor_sync(0xffffffffu, rs, 1);
            rs += __shfl_xor_sync(0xffffffffu, rs, 2);
            l[hf] = l[hf] * corr + rs;
#pragma unroll
            for (int j = 0; j < 8; j++) {
                o[j][hf * 2]     *= corr;
                o[j][hf * 2 + 1] *= corr;
            }
        }

        // ---- O += P V (2-pass fp16: P split, V hi) ----
#pragma unroll
        for (int ks = 0; ks < 4; ks++) {
            uint32_t ph4[4], pl4[4];
            split2h(s[2 * ks][0],     s[2 * ks][1],     ph4[0], pl4[0]);
            split2h(s[2 * ks][2],     s[2 * ks][3],     ph4[1], pl4[1]);
            split2h(s[2 * ks + 1][0], s[2 * ks + 1][1], ph4[2], pl4[2]);
            split2h(s[2 * ks + 1][2], s[2 * ks + 1][3], ph4[3], pl4[3]);
#pragma unroll
            for (int dc = 0; dc < 4; dc++) {
                int row = ks * 16 + (lane & 15);
                int cu = dc * 2 + (lane >> 4);
                uint32_t off = st + 16384 + row * 128 + ((cu ^ (row & 7)) << 4);
                uint32_t vh4[4];
                ldsm_x4_t(off, vh4);          // Vh (transposed load)
                mma4(o[2 * dc],     ph4, vh4[0], vh4[1]);
                mma4(o[2 * dc],     pl4, vh4[0], vh4[1]);
                mma4(o[2 * dc + 1], ph4, vh4[2], vh4[3]);
                mma4(o[2 * dc + 1], pl4, vh4[2], vh4[3]);
            }
        }

        if (b + 1 < 8) { CP_WAIT(0); __syncthreads(); }
    }

    // ---- epilogue ----
    int g = lane >> 2;
    if (!edge) {
#pragma unroll
        for (int hf = 0; hf < 2; hf++) {
            float inv = 1.f / l[hf];
            int row = qb * BSS + w * 16 + g + hf * 8;
#pragma unroll
            for (int j = 0; j < 8; j++) {
                int col = h * DHH + j * 8 + (lane & 3) * 2;
                uint32_t hi, lo;
                split2h(o[j][hf * 2] * inv, o[j][hf * 2 + 1] * inv, hi, lo);
                *(uint32_t*)(th + (size_t)row * DD + col) = hi;
                *(uint32_t*)(tl + (size_t)row * DD + col) = lo;
            }
        }
    } else {
        int cb = (h * 2 + e) * 8 + z;
        float* po = pO + (size_t)cb * 64 * 64;
#pragma unroll
        for (int hf = 0; hf < 2; hf++) {
            int qr = w * 16 + g + hf * 8;
#pragma unroll
            for (int j = 0; j < 8; j++) {
                float2 val; val.x = o[j][hf * 2]; val.y = o[j][hf * 2 + 1];
                *(float2*)(po + qr * 64 + j * 8 + (lane & 3) * 2) = val;
            }
            if ((lane & 3) == 0) {
                pm[cb * 64 + qr] = m[hf];
                pl[cb * 64 + qr] = l[hf];
            }
        }
    }
}

// combine edge partials: grid (24, 64), 64 threads (d)
__global__ void __launch_bounds__(64)
attn_combine(const float* __restrict__ pO, const float* __restrict__ pm,
             const float* __restrict__ pl,
             __half* __restrict__ th, __half* __restrict__ tl)
{
    int he = blockIdx.x, q = blockIdx.y, d = threadIdx.x;
    int h = he >> 1, e = he & 1;
    float mv[8], M = -1e30f;
#pragma unroll
    for (int z = 0; z < 8; z++) {
        mv[z] = pm[(he * 8 + z) * 64 + q];
        M = fmaxf(M, mv[z]);
    }
    float L = 0.f, O = 0.f;
#pragma unroll
    for (int z = 0; z < 8; z++) {
        float w = __expf(mv[z] - M);
        L += w * pl[(he * 8 + z) * 64 + q];
        O += w * pO[((size_t)(he * 8 + z) * 64 + q) * 64 + d];
    }
    float r = O / L;
    int row = (e ? (NBB - 1) : 0) * BSS + q;
    write_splith(th, tl, row * DD + h * DHH + d, r);
}

// ---------------- classifier --------------------------------------------------
__global__ __launch_bounds__(256) void classifier_kernel(
    const float* __restrict__ h, const float* __restrict__ Wc,
    const float* __restrict__ bc, float* __restrict__ out)
{
    int warp = threadIdx.x >> 5, lane = threadIdx.x & 31;
    if (warp >= CCC) return;
    const float* hr = h + (long long)(SS - 1) * DD;
    float s = 0.f;
    for (int d = lane; d < DD; d += 32) s += hr[d] * Wc[d * CCC + warp];
#pragma unroll
    for (int off = 16; off; off >>= 1) s += __shfl_xor_sync(0xffffffffu, s, off);
    if (lane == 0) out[warp] = s + bc[warp];
}

// ---------------- launch ------------------------------------------------------
extern "C" void kernel_launch(void* const* d_in, const int* in_sizes, int n_in,
                              void* d_out, int out_size)
{
    (void)in_sizes; (void)n_in; (void)out_size;
    const int*   input_ids = (const int*)  d_in[0];
    const int*   rand_attn = (const int*)  d_in[1];
    const float* word_emb  = (const float*)d_in[2];
    const float* pos_emb   = (const float*)d_in[3];
    const float* eln_w     = (const float*)d_in[4];
    const float* eln_b     = (const float*)d_in[5];
    const float* Wq        = (const float*)d_in[6];
    const float* bq        = (const float*)d_in[7];
    const float* Wk        = (const float*)d_in[8];
    const float* bk        = (const float*)d_in[9];
    const float* Wv        = (const float*)d_in[10];
    const float* bv        = (const float*)d_in[11];
    const float* Wo        = (const float*)d_in[12];
    const float* bo        = (const float*)d_in[13];
    const float* ln1_w     = (const float*)d_in[14];
    const float* ln1_b     = (const float*)d_in[15];
    const float* W1        = (const float*)d_in[16];
    const float* b1        = (const float*)d_in[17];
    const float* W2        = (const float*)d_in[18];
    const float* b2        = (const float*)d_in[19];
    const float* ln2_w     = (const float*)d_in[20];
    const float* ln2_b     = (const float*)d_in[21];
    const float* Wc        = (const float*)d_in[22];
    const float* bc        = (const float*)d_in[23];
    float* out = (float*)d_out;

    cudaFuncSetAttribute(gemm_mma<2>, cudaFuncAttributeMaxDynamicSharedMemorySize, GEMM_SMEM);
    cudaFuncSetAttribute(gemm_mma<3>, cudaFuncAttributeMaxDynamicSharedMemorySize, GEMM_SMEM);
    cudaFuncSetAttribute(attn_mma_kernel, cudaFuncAttributeMaxDynamicSharedMemorySize, ATTN_SMEM);

    float *h, *a, *bias3, *pO, *pm, *pl;
    __half *ah, *al, *bh, *bl, *wh, *wl;
    cudaGetSymbolAddress((void**)&h,    g_h);
    cudaGetSymbolAddress((void**)&a,    g_a);
    cudaGetSymbolAddress((void**)&ah,   g_ah);
    cudaGetSymbolAddress((void**)&al,   g_al);
    cudaGetSymbolAddress((void**)&bh,   g_bh);
    cudaGetSymbolAddress((void**)&bl,   g_bl);
    cudaGetSymbolAddress((void**)&wh,   g_wh);
    cudaGetSymbolAddress((void**)&wl,   g_wl);
    cudaGetSymbolAddress((void**)&bias3, g_bias3);
    cudaGetSymbolAddress((void**)&pO,   g_pO);
    cudaGetSymbolAddress((void**)&pm,   g_pm);
    cudaGetSymbolAddress((void**)&pl,   g_pl);

    embed_ln_split<<<SS, 256>>>(input_ids, word_emb, pos_emb, eln_w, eln_b, h, ah, al);

    for (int l = 0; l < 2; l++) {
        long long wofs = (long long)l * DD * DD;

        // ---- fused QKV projection (3-pass, split weights) -> split fp16 in bh/bl
        conv_wt<<<dim3(DD/32, DD/32), 256>>>(Wq + wofs, wh,           wl,           DD, DD);
        conv_wt<<<dim3(DD/32, DD/32), 256>>>(Wk + wofs, wh + DD*DD,   wl + DD*DD,   DD, DD);
        conv_wt<<<dim3(DD/32, DD/32), 256>>>(Wv + wofs, wh + 2*DD*DD, wl + 2*DD*DD, DD, DD);
        concat3<<<3, 256>>>(bq + l*DD, bk + l*DD, bv + l*DD, bias3);
        gemm_mma<3><<<dim3(NQKV/128, SS/128), 256, GEMM_SMEM>>>(
            ah, al, wh, wl, bias3, nullptr, bh, bl, SS, NQKV, DD, 3);

        // ---- MMA flash attention (writes split fp16 into ah/al) ----
        attn_mma_kernel<<<dim3(HH, 78), 128, ATTN_SMEM>>>(
            bh, bl, rand_attn + l*HH*NBB*RRR, ah, al, pO, pm, pl);
        attn_combine<<<dim3(24, 64), 64>>>(pO, pm, pl, ah, al);

        // ---- O projection (2-pass, weights hi only) + LN ----
        conv_wt<<<dim3(DD/32, DD/32), 256>>>(Wo + wofs, wh, nullptr, DD, DD);
        gemm_mma<2><<<dim3(DD/128, SS/128), 256, GEMM_SMEM>>>(
            ah, al, wh, wh, bo + l*DD, a, nullptr, nullptr, SS, DD, DD, 0);
        add_ln_split<<<SS, 256>>>(h, a, ln1_w + l*DD, ln1_b + l*DD, ah, al);

        // ---- FFN (2-pass GEMMs) ----
        conv_wt<<<dim3(FFF/32, DD/32), 256>>>(W1 + (long long)l*DD*FFF, wh, nullptr, DD, FFF);
        gemm_mma<2><<<dim3(FFF/128, SS/128), 256, GEMM_SMEM>>>(
            ah, al, wh, wh, b1 + l*FFF, nullptr, bh, bl, SS, FFF, DD, 2);
        conv_wt<<<dim3(DD/32, FFF/32), 256>>>(W2 + (long long)l*FFF*DD, wh, nullptr, FFF, DD);
        gemm_mma<2><<<dim3(DD/128, SS/128), 256, GEMM_SMEM>>>(
            bh, bl, wh, wh, b2 + l*DD, a, nullptr, nullptr, SS, DD, FFF, 0);
        add_ln_split<<<SS, 256>>>(h, a, ln2_w + l*DD, ln2_b + l*DD, ah, al);
    }

    classifier_kernel<<<1, 256>>>(h, Wc, bc, out);
}

// round 10
// speedup vs baseline: 7.7027x; 1.1360x over previous
#include <cuda_runtime.h>
#include <cuda_fp16.h>
#include <math.h>
#include <stdint.h>

#define SS 4096
#define DD 768
#define HH 12
#define DHH 64
#define NBB 64
#define BSS 64
#define RRR 3
#define FFF 3072
#define CCC 8
#define NQKV 2304

// ---------------- scratch (device globals; no allocation allowed) -----------
__device__ __align__(16) float g_h  [SS*DD];
__device__ __align__(16) float g_a  [SS*DD];
__device__ __align__(16) float g_a2 [SS*DD];
__device__ __align__(16) __half g_ah[SS*FFF];
__device__ __align__(16) __half g_al[SS*FFF];
__device__ __align__(16) __half g_bh[SS*FFF];
__device__ __align__(16) __half g_bl[SS*FFF];
// per-layer fp16 weights (hi only; all GEMMs are 2-pass)
__device__ __align__(16) __half g_wqkv[2][3*DD*DD];
__device__ __align__(16) __half g_wo  [2][DD*DD];
__device__ __align__(16) __half g_w1  [2][DD*FFF];
__device__ __align__(16) __half g_w2  [2][FFF*DD];
__device__ __align__(16) float  g_bias3[2][NQKV];
// edge-attention partials: 24 (h,e) x 8 chunks x 64 q x 64 d
__device__ __align__(16) float g_pO[24*8*64*64];
__device__ __align__(16) float g_pm[24*8*64];
__device__ __align__(16) float g_pl[24*8*64];

// ---------------- PTX helpers ------------------------------------------------
__device__ __forceinline__ uint32_t smem_addr(const void* p) {
    uint32_t a;
    asm("{ .reg .u64 t; cvta.to.shared.u64 t, %1; cvt.u32.u64 %0, t; }" : "=r"(a) : "l"(p));
    return a;
}
__device__ __forceinline__ void ldsm_x4(uint32_t addr, uint32_t* r) {
    asm volatile("ldmatrix.sync.aligned.m8n8.x4.shared.b16 {%0,%1,%2,%3}, [%4];"
        : "=r"(r[0]), "=r"(r[1]), "=r"(r[2]), "=r"(r[3]) : "r"(addr));
}
__device__ __forceinline__ void ldsm_x4_t(uint32_t addr, uint32_t* r) {
    asm volatile("ldmatrix.sync.aligned.m8n8.x4.trans.shared.b16 {%0,%1,%2,%3}, [%4];"
        : "=r"(r[0]), "=r"(r[1]), "=r"(r[2]), "=r"(r[3]) : "r"(addr));
}
__device__ __forceinline__ void mma_f16(float* c, const uint32_t* a, const uint32_t* b) {
    asm volatile("mma.sync.aligned.m16n8k16.row.col.f32.f16.f16.f32 "
        "{%0,%1,%2,%3}, {%4,%5,%6,%7}, {%8,%9}, {%0,%1,%2,%3};"
        : "+f"(c[0]), "+f"(c[1]), "+f"(c[2]), "+f"(c[3])
        : "r"(a[0]), "r"(a[1]), "r"(a[2]), "r"(a[3]), "r"(b[0]), "r"(b[1]));
}
__device__ __forceinline__ void mma4(float* c, const uint32_t* a, uint32_t b0, uint32_t b1) {
    uint32_t b[2] = {b0, b1};
    mma_f16(c, a, b);
}
#define CP_ASYNC(dst, src) asm volatile("cp.async.cg.shared.global [%0], [%1], 16;" :: "r"(dst), "l"(src))
#define CP_COMMIT()        asm volatile("cp.async.commit_group;")
#define CP_WAIT(n)         asm volatile("cp.async.wait_group %0;" :: "n"(n))

__device__ __forceinline__ uint32_t pack_h2(__half a, __half b) {
    __half2 t; t.x = a; t.y = b;
    return *(uint32_t*)&t;
}
__device__ __forceinline__ void split2h(float a, float b, uint32_t& hi, uint32_t& lo) {
    __half ha = __float2half_rn(a), hb = __float2half_rn(b);
    __half la = __float2half_rn(a - __half2float(ha));
    __half lb = __float2half_rn(b - __half2float(hb));
    hi = pack_h2(ha, hb);
    lo = pack_h2(la, lb);
}
__device__ __forceinline__ void write_splith(__half* hi, __half* lo, int idx, float v) {
    __half h = __float2half_rn(v);
    hi[idx] = h;
    lo[idx] = __float2half_rn(v - __half2float(h));
}

// ---------------- fp16 2-pass GEMM via mma.sync -------------------------------
// C[M,N] = (Ah+Al)[M,K] * Bh[N,K]^T + bias  (passes Ah*Bh + Al*Bh).
// Split-K via blockIdx.z/gridDim.z: z=0 -> C (+bias), z=1 -> C2 (no bias).
// modes: 0 fp32 out, 2 gelu + split fp16 out, 3 split fp16 out (no gelu)
#define GEMM_STAGE 49152
#define GEMM_SMEM  (2 * GEMM_STAGE)

__global__ void __launch_bounds__(256, 1)
gemm_mma(const __half* __restrict__ Ah, const __half* __restrict__ Al,
         const __half* __restrict__ Bh,
         const float* __restrict__ bias, float* __restrict__ C, float* __restrict__ C2,
         __half* __restrict__ Oh, __half* __restrict__ Ol,
         int M, int N, int K, int mode)
{
    extern __shared__ __align__(128) char smem[];
    uint32_t sb = smem_addr(smem);
    int tid = threadIdx.x, lane = tid & 31, wid = tid >> 5;
    int wm = wid & 1, wn = wid >> 1;
    int n0 = blockIdx.x * 128, m0 = blockIdx.y * 128;
    int kz = blockIdx.z, nz = gridDim.z;
    const int KT = (K >> 6) / nz;
    const int kbase = kz * KT;
    float* Cout = (kz == 0) ? C : C2;
    float bsc = (kz == 0) ? 1.f : 0.f;

    const __half* srcs[3];
    srcs[0] = Ah + (size_t)m0 * K;
    srcs[1] = Al + (size_t)m0 * K;
    srcs[2] = Bh + (size_t)n0 * K;

    float acc[4][4][4];
#pragma unroll
    for (int i = 0; i < 4; i++)
#pragma unroll
        for (int j = 0; j < 4; j++)
#pragma unroll
            for (int u = 0; u < 4; u++) acc[i][j][u] = 0.f;

#define LOAD_STAGE(S, KT_IDX) do {                                              \
    uint32_t sbase_ = sb + (S) * GEMM_STAGE;                                    \
    int ko_ = (kbase + (KT_IDX)) * 64;                                          \
    _Pragma("unroll")                                                           \
    for (int t_ = 0; t_ < 3; t_++) {                                            \
        const __half* sp_ = srcs[t_];                                           \
        _Pragma("unroll")                                                       \
        for (int i_ = 0; i_ < 4; i_++) {                                        \
            int id_ = tid + i_ * 256;                                           \
            int row_ = id_ >> 3, c_ = id_ & 7;                                  \
            const __half* src_ = sp_ + (size_t)row_ * K + ko_ + c_ * 8;         \
            uint32_t dst_ = sbase_ + t_ * 16384 + row_ * 128 + ((c_ ^ (row_ & 7)) << 4); \
            CP_ASYNC(dst_, src_);                                               \
        }                                                                       \
    }                                                                           \
    CP_COMMIT();                                                                \
} while (0)

    LOAD_STAGE(0, 0);

    for (int kt = 0; kt < KT; kt++) {
        if (kt + 1 < KT) { LOAD_STAGE((kt + 1) & 1, kt + 1); CP_WAIT(1); }
        else             { CP_WAIT(0); }
        __syncthreads();
        uint32_t st = sb + (kt & 1) * GEMM_STAGE;
#pragma unroll
        for (int ks = 0; ks < 4; ks++) {
            uint32_t ahf[4][4], alf[4][4], bhf[2][4];
#pragma unroll
            for (int mt = 0; mt < 4; mt++) {
                int row = wm * 64 + mt * 16 + (lane & 15);
                int kc = ks * 2 + (lane >> 4);
                uint32_t off = row * 128 + ((kc ^ (row & 7)) << 4);
                ldsm_x4(st + off, ahf[mt]);
                ldsm_x4(st + 16384 + off, alf[mt]);
            }
#pragma unroll
            for (int np = 0; np < 2; np++) {
                int row = wn * 32 + np * 16 + ((lane & 7) | ((lane & 16) >> 1));
                int kc = ks * 2 + ((lane >> 3) & 1);
                uint32_t off = row * 128 + ((kc ^ (row & 7)) << 4);
                ldsm_x4(st + 32768 + off, bhf[np]);
            }
#pragma unroll
            for (int mt = 0; mt < 4; mt++)
#pragma unroll
                for (int nt = 0; nt < 4; nt++) {
                    const uint32_t* bh_ = &bhf[nt >> 1][(nt & 1) * 2];
                    mma_f16(acc[mt][nt], ahf[mt], bh_);
                    mma_f16(acc[mt][nt], alf[mt], bh_);
                }
        }
        __syncthreads();
    }

#pragma unroll
    for (int mt = 0; mt < 4; mt++) {
        int mbase = m0 + wm * 64 + mt * 16 + (lane >> 2);
#pragma unroll
        for (int nt = 0; nt < 4; nt++) {
            int n = n0 + wn * 32 + nt * 8 + (lane & 3) * 2;
            float b0 = bias[n] * bsc, b1 = bias[n + 1] * bsc;
#pragma unroll
            for (int half = 0; half < 2; half++) {
                int m = mbase + half * 8;
                float v0 = acc[mt][nt][half * 2 + 0] + b0;
                float v1 = acc[mt][nt][half * 2 + 1] + b1;
                if (mode == 2) {
                    float u0 = 0.7978845608028654f * (v0 + 0.044715f * v0 * v0 * v0);
                    v0 = 0.5f * v0 * (1.f + tanhf(u0));
                    float u1 = 0.7978845608028654f * (v1 + 0.044715f * v1 * v1 * v1);
                    v1 = 0.5f * v1 * (1.f + tanhf(u1));
                }
                if (mode >= 2) {
                    uint32_t hi, lo;
                    split2h(v0, v1, hi, lo);
                    *(uint32_t*)(Oh + (size_t)m * N + n) = hi;
                    *(uint32_t*)(Ol + (size_t)m * N + n) = lo;
                } else {
                    float2 o; o.x = v0; o.y = v1;
                    *(float2*)(Cout + (size_t)m * N + n) = o;
                }
            }
        }
    }
}

// ---------------- W[K,N] fp32 -> Wt[N,K] fp16 hi ------------------------------
__global__ __launch_bounds__(256) void conv_wt(const float* __restrict__ W,
    __half* __restrict__ th, int K, int N)
{
    __shared__ float tile[32][33];
    int k0 = blockIdx.y * 32, n0 = blockIdx.x * 32;
    int tx = threadIdx.x & 31, ty = threadIdx.x >> 5;
#pragma unroll
    for (int r = ty; r < 32; r += 8)
        tile[r][tx] = W[(size_t)(k0 + r) * N + n0 + tx];
    __syncthreads();
#pragma unroll
    for (int r = ty; r < 32; r += 8) {
        float v = tile[tx][r];
        th[(size_t)(n0 + r) * K + k0 + tx] = __float2half_rn(v);
    }
}

__global__ __launch_bounds__(256) void concat3(const float* __restrict__ a,
    const float* __restrict__ b, const float* __restrict__ c, float* __restrict__ o)
{
    int i = blockIdx.x * 256 + threadIdx.x;
    if (i < DD) { o[i] = a[i]; o[DD + i] = b[i]; o[2 * DD + i] = c[i]; }
}

// ---------------- reductions -------------------------------------------------
__device__ __forceinline__ void block_reduce2(float &s1v, float &s2v) {
    __shared__ float sa[8], sb2[8];
    int lane = threadIdx.x & 31, w = threadIdx.x >> 5;
#pragma unroll
    for (int off = 16; off; off >>= 1) {
        s1v += __shfl_xor_sync(0xffffffffu, s1v, off);
        s2v += __shfl_xor_sync(0xffffffffu, s2v, off);
    }
    if (lane == 0) { sa[w] = s1v; sb2[w] = s2v; }
    __syncthreads();
    if (w == 0) {
        s1v = (lane < 8) ? sa[lane] : 0.f;
        s2v = (lane < 8) ? sb2[lane] : 0.f;
#pragma unroll
        for (int off = 4; off; off >>= 1) {
            s1v += __shfl_xor_sync(0xffffffffu, s1v, off);
            s2v += __shfl_xor_sync(0xffffffffu, s2v, off);
        }
        if (lane == 0) { sa[0] = s1v; sb2[0] = s2v; }
    }
    __syncthreads();
    s1v = sa[0]; s2v = sb2[0];
}

// ---------------- embedding + LN (split out) ---------------------------------
__global__ __launch_bounds__(256) void embed_ln_split(
    const int* __restrict__ ids, const float* __restrict__ we,
    const float* __restrict__ pe, const float* __restrict__ w,
    const float* __restrict__ b, float* __restrict__ out,
    __half* __restrict__ oh, __half* __restrict__ ol)
{
    int row = blockIdx.x;
    int id = ids[row];
    float x[3], sum = 0.f, sq = 0.f;
#pragma unroll
    for (int r = 0; r < 3; r++) {
        int i = threadIdx.x + r * 256;
        x[r] = we[(long long)id * DD + i] + pe[row * DD + i];
        sum += x[r]; sq += x[r] * x[r];
    }
    block_reduce2(sum, sq);
    float mean = sum * (1.f / DD);
    float var  = sq * (1.f / DD) - mean * mean;
    float inv  = rsqrtf(var + 1e-12f);
#pragma unroll
    for (int r = 0; r < 3; r++) {
        int i = threadIdx.x + r * 256;
        float y = (x[r] - mean) * inv * w[i] + b[i];
        out[row * DD + i] = y;
        write_splith(oh, ol, row * DD + i, y);
    }
}

// ---------------- residual (h + a + a2) + LN (split out) ----------------------
__global__ __launch_bounds__(256) void add_ln3(
    float* __restrict__ h, const float* __restrict__ a, const float* __restrict__ a2,
    const float* __restrict__ w, const float* __restrict__ b,
    __half* __restrict__ oh, __half* __restrict__ ol)
{
    int row = blockIdx.x;
    float x[3], sum = 0.f, sq = 0.f;
#pragma unroll
    for (int r = 0; r < 3; r++) {
        int i = threadIdx.x + r * 256;
        x[r] = h[row * DD + i] + a[row * DD + i] + a2[row * DD + i];
        sum += x[r]; sq += x[r] * x[r];
    }
    block_reduce2(sum, sq);
    float mean = sum * (1.f / DD);
    float var  = sq * (1.f / DD) - mean * mean;
    float inv  = rsqrtf(var + 1e-12f);
#pragma unroll
    for (int r = 0; r < 3; r++) {
        int i = threadIdx.x + r * 256;
        float y = (x[r] - mean) * inv * w[i] + b[i];
        h[row * DD + i] = y;
        write_splith(oh, ol, row * DD + i, y);
    }
}

// ---------------- MMA flash attention (fp16) ----------------------------------
// sh/sl: split fp16 QKV [S][NQKV]; Q at col h*64, K at DD+h*64, V at 2*DD+h*64.
// S = Qh*Kh + Qh*Kl + Ql*Kh (3-pass); O = Ph*Vh + Pl*Vh (2-pass, V hi only).
#define AS_QH 0
#define AS_QL 8192
#define AS_KV 16384
#define KV_STAGE 24576
#define ATTN_SMEM (16384 + 2 * KV_STAGE)

__global__ void __launch_bounds__(128)
attn_mma_kernel(const __half* __restrict__ sh, const __half* __restrict__ sl,
                const int* __restrict__ rnd,
                __half* __restrict__ th, __half* __restrict__ tl,
                float* __restrict__ pO, float* __restrict__ pm, float* __restrict__ pl)
{
    extern __shared__ __align__(128) char smem[];
    uint32_t sb = smem_addr(smem);
    int h = blockIdx.x, y = blockIdx.y;
    int tid = threadIdx.x, lane = tid & 31, w = tid >> 5;

    int qb, e = 0, z = 0;
    bool edge;
    if (y < 62) { qb = y + 1; edge = false; }
    else        { int t = y - 62; e = t >> 3; z = t & 7; qb = e ? (NBB - 1) : 0; edge = true; }

    int blks[8];
    if (edge) {
#pragma unroll
        for (int i = 0; i < 8; i++) blks[i] = z * 8 + i;
    } else {
        blks[0] = 0; blks[1] = NBB - 1; blks[2] = qb - 1; blks[3] = qb; blks[4] = qb + 1;
        const int* rp = rnd + (h * NBB + qb) * RRR;
        blks[5] = rp[0]; blks[6] = rp[1]; blks[7] = rp[2];
    }

    {
        int colq = h * DHH;
#pragma unroll
        for (int i = 0; i < 8; i++) {
            int idx = tid + i * 128;
            int t = idx >> 9, rem = idx & 511;
            int row = rem >> 3, cu = rem & 7;
            const __half* src = (t ? sl : sh) + (size_t)(qb * BSS + row) * NQKV + colq + cu * 8;
            uint32_t dst = sb + (t ? AS_QL : AS_QH) + row * 128 + ((cu ^ (row & 7)) << 4);
            CP_ASYNC(dst, src);
        }
    }
#define LOAD_KV(STG, KB) do {                                                   \
    uint32_t base_ = sb + AS_KV + (STG) * KV_STAGE;                             \
    _Pragma("unroll")                                                           \
    for (int i_ = 0; i_ < 12; i_++) {                                           \
        int idx_ = tid + i_ * 128;                                              \
        int t_ = idx_ >> 9, rem_ = idx_ & 511;                                  \
        int row_ = rem_ >> 3, cu_ = rem_ & 7;                                   \
        const __half* arr_ = (t_ == 1) ? sl : sh;                               \
        int col_ = ((t_ == 2) ? 2 : 1) * DD + h * DHH + cu_ * 8;                \
        const __half* src_ = arr_ + (size_t)((KB) * BSS + row_) * NQKV + col_;  \
        uint32_t dst_ = base_ + t_ * 8192 + row_ * 128 + ((cu_ ^ (row_ & 7)) << 4); \
        CP_ASYNC(dst_, src_);                                                   \
    }                                                                           \
} while (0)

    LOAD_KV(0, blks[0]);
    CP_COMMIT();
    CP_WAIT(0);
    __syncthreads();

    uint32_t qfh[4][4], qfl[4][4];
#pragma unroll
    for (int ds = 0; ds < 4; ds++) {
        int row = w * 16 + (lane & 15);
        int cu = ds * 2 + (lane >> 4);
        uint32_t off = row * 128 + ((cu ^ (row & 7)) << 4);
        ldsm_x4(sb + AS_QH + off, qfh[ds]);
        ldsm_x4(sb + AS_QL + off, qfl[ds]);
    }

    float o[8][4];
    float m[2] = {-1e30f, -1e30f}, l[2] = {0.f, 0.f};
#pragma unroll
    for (int j = 0; j < 8; j++)
#pragma unroll
        for (int u = 0; u < 4; u++) o[j][u] = 0.f;

    const float sc = 0.125f;

    for (int b = 0; b < 8; b++) {
        if (b + 1 < 8) { LOAD_KV((b + 1) & 1, blks[b + 1]); CP_COMMIT(); }
        uint32_t st = sb + AS_KV + (b & 1) * KV_STAGE;

        float s[8][4];
#pragma unroll
        for (int j = 0; j < 8; j++)
#pragma unroll
            for (int u = 0; u < 4; u++) s[j][u] = 0.f;
#pragma unroll
        for (int kb = 0; kb < 4; kb++) {
#pragma unroll
            for (int ds = 0; ds < 4; ds++) {
                int row = kb * 16 + (lane & 15);
                int cu = ds * 2 + (lane >> 4);
                uint32_t off = st + row * 128 + ((cu ^ (row & 7)) << 4);
                uint32_t kh4[4], kl4[4];
                ldsm_x4(off, kh4);
                ldsm_x4(off + 8192, kl4);
                mma4(s[2 * kb],     qfh[ds], kh4[0], kh4[2]);
                mma4(s[2 * kb],     qfh[ds], kl4[0], kl4[2]);
                mma4(s[2 * kb],     qfl[ds], kh4[0], kh4[2]);
                mma4(s[2 * kb + 1], qfh[ds], kh4[1], kh4[3]);
                mma4(s[2 * kb + 1], qfh[ds], kl4[1], kl4[3]);
                mma4(s[2 * kb + 1], qfl[ds], kh4[1], kh4[3]);
            }
        }

#pragma unroll
        for (int hf = 0; hf < 2; hf++) {
            float rm = -1e30f;
#pragma unroll
            for (int j = 0; j < 8; j++)
                rm = fmaxf(rm, fmaxf(s[j][hf * 2], s[j][hf * 2 + 1]));
            rm *= sc;
            rm = fmaxf(rm, __shfl_xor_sync(0xffffffffu, rm, 1));
            rm = fmaxf(rm, __shfl_xor_sync(0xffffffffu, rm, 2));
            float mn = fmaxf(m[hf], rm);
            float corr = __expf(m[hf] - mn);
            m[hf] = mn;
            float rs = 0.f;
#pragma unroll
            for (int j = 0; j < 8; j++) {
                s[j][hf * 2]     = __expf(s[j][hf * 2]     * sc - mn);
                s[j][hf * 2 + 1] = __expf(s[j][hf * 2 + 1] * sc - mn);
                rs += s[j][hf * 2] + s[j][hf * 2 + 1];
            }
            rs += __shfl_xor_sync(0xffffffffu, rs, 1);
            rs += __shfl_xor_sync(0xffffffffu, rs, 2);
            l[hf] = l[hf] * corr + rs;
#pragma unroll
            for (int j = 0; j < 8; j++) {
                o[j][hf * 2]     *= corr;
                o[j][hf * 2 + 1] *= corr;
            }
        }

#pragma unroll
        for (int ks = 0; ks < 4; ks++) {
            uint32_t ph4[4], pl4[4];
            split2h(s[2 * ks][0],     s[2 * ks][1],     ph4[0], pl4[0]);
            split2h(s[2 * ks][2],     s[2 * ks][3],     ph4[1], pl4[1]);
            split2h(s[2 * ks + 1][0], s[2 * ks + 1][1], ph4[2], pl4[2]);
            split2h(s[2 * ks + 1][2], s[2 * ks + 1][3], ph4[3], pl4[3]);
#pragma unroll
            for (int dc = 0; dc < 4; dc++) {
                int row = ks * 16 + (lane & 15);
                int cu = dc * 2 + (lane >> 4);
                uint32_t off = st + 16384 + row * 128 + ((cu ^ (row & 7)) << 4);
                uint32_t vh4[4];
                ldsm_x4_t(off, vh4);
                mma4(o[2 * dc],     ph4, vh4[0], vh4[1]);
                mma4(o[2 * dc],     pl4, vh4[0], vh4[1]);
                mma4(o[2 * dc + 1], ph4, vh4[2], vh4[3]);
                mma4(o[2 * dc + 1], pl4, vh4[2], vh4[3]);
            }
        }

        if (b + 1 < 8) { CP_WAIT(0); __syncthreads(); }
    }

    int g = lane >> 2;
    if (!edge) {
#pragma unroll
        for (int hf = 0; hf < 2; hf++) {
            float inv = 1.f / l[hf];
            int row = qb * BSS + w * 16 + g + hf * 8;
#pragma unroll
            for (int j = 0; j < 8; j++) {
                int col = h * DHH + j * 8 + (lane & 3) * 2;
                uint32_t hi, lo;
                split2h(o[j][hf * 2] * inv, o[j][hf * 2 + 1] * inv, hi, lo);
                *(uint32_t*)(th + (size_t)row * DD + col) = hi;
                *(uint32_t*)(tl + (size_t)row * DD + col) = lo;
            }
        }
    } else {
        int cb = (h * 2 + e) * 8 + z;
        float* po = pO + (size_t)cb * 64 * 64;
#pragma unroll
        for (int hf = 0; hf < 2; hf++) {
            int qr = w * 16 + g + hf * 8;
#pragma unroll
            for (int j = 0; j < 8; j++) {
                float2 val; val.x = o[j][hf * 2]; val.y = o[j][hf * 2 + 1];
                *(float2*)(po + qr * 64 + j * 8 + (lane & 3) * 2) = val;
            }
            if ((lane & 3) == 0) {
                pm[cb * 64 + qr] = m[hf];
                pl[cb * 64 + qr] = l[hf];
            }
        }
    }
}

// combine edge partials: grid (24, 64), 64 threads (d)
__global__ void __launch_bounds__(64)
attn_combine(const float* __restrict__ pO, const float* __restrict__ pm,
             const float* __restrict__ pl,
             __half* __restrict__ th, __half* __restrict__ tl)
{
    int he = blockIdx.x, q = blockIdx.y, d = threadIdx.x;
    int h = he >> 1, e = he & 1;
    float mv[8], M = -1e30f;
#pragma unroll
    for (int z = 0; z < 8; z++) {
        mv[z] = pm[(he * 8 + z) * 64 + q];
        M = fmaxf(M, mv[z]);
    }
    float L = 0.f, O = 0.f;
#pragma unroll
    for (int z = 0; z < 8; z++) {
        float w = __expf(mv[z] - M);
        L += w * pl[(he * 8 + z) * 64 + q];
        O += w * pO[((size_t)(he * 8 + z) * 64 + q) * 64 + d];
    }
    float r = O / L;
    int row = (e ? (NBB - 1) : 0) * BSS + q;
    write_splith(th, tl, row * DD + h * DHH + d, r);
}

// ---------------- classifier --------------------------------------------------
__global__ __launch_bounds__(256) void classifier_kernel(
    const float* __restrict__ h, const float* __restrict__ Wc,
    const float* __restrict__ bc, float* __restrict__ out)
{
    int warp = threadIdx.x >> 5, lane = threadIdx.x & 31;
    if (warp >= CCC) return;
    const float* hr = h + (long long)(SS - 1) * DD;
    float s = 0.f;
    for (int d = lane; d < DD; d += 32) s += hr[d] * Wc[d * CCC + warp];
#pragma unroll
    for (int off = 16; off; off >>= 1) s += __shfl_xor_sync(0xffffffffu, s, off);
    if (lane == 0) out[warp] = s + bc[warp];
}

// ---------------- launch ------------------------------------------------------
extern "C" void kernel_launch(void* const* d_in, const int* in_sizes, int n_in,
                              void* d_out, int out_size)
{
    (void)in_sizes; (void)n_in; (void)out_size;
    const int*   input_ids = (const int*)  d_in[0];
    const int*   rand_attn = (const int*)  d_in[1];
    const float* word_emb  = (const float*)d_in[2];
    const float* pos_emb   = (const float*)d_in[3];
    const float* eln_w     = (const float*)d_in[4];
    const float* eln_b     = (const float*)d_in[5];
    const float* Wq        = (const float*)d_in[6];
    const float* bq        = (const float*)d_in[7];
    const float* Wk        = (const float*)d_in[8];
    const float* bk        = (const float*)d_in[9];
    const float* Wv        = (const float*)d_in[10];
    const float* bv        = (const float*)d_in[11];
    const float* Wo        = (const float*)d_in[12];
    const float* bo        = (const float*)d_in[13];
    const float* ln1_w     = (const float*)d_in[14];
    const float* ln1_b     = (const float*)d_in[15];
    const float* W1        = (const float*)d_in[16];
    const float* b1        = (const float*)d_in[17];
    const float* W2        = (const float*)d_in[18];
    const float* b2        = (const float*)d_in[19];
    const float* ln2_w     = (const float*)d_in[20];
    const float* ln2_b     = (const float*)d_in[21];
    const float* Wc        = (const float*)d_in[22];
    const float* bc        = (const float*)d_in[23];
    float* out = (float*)d_out;

    cudaFuncSetAttribute(gemm_mma, cudaFuncAttributeMaxDynamicSharedMemorySize, GEMM_SMEM);
    cudaFuncSetAttribute(attn_mma_kernel, cudaFuncAttributeMaxDynamicSharedMemorySize, ATTN_SMEM);

    float *h, *a, *a2, *pO, *pm, *pl;
    __half *ah, *al, *bh, *bl;
    __half *wqkv[2], *wo[2], *w1[2], *w2[2];
    float  *bias3[2];
    cudaGetSymbolAddress((void**)&h,  g_h);
    cudaGetSymbolAddress((void**)&a,  g_a);
    cudaGetSymbolAddress((void**)&a2, g_a2);
    cudaGetSymbolAddress((void**)&ah, g_ah);
    cudaGetSymbolAddress((void**)&al, g_al);
    cudaGetSymbolAddress((void**)&bh, g_bh);
    cudaGetSymbolAddress((void**)&bl, g_bl);
    cudaGetSymbolAddress((void**)&pO, g_pO);
    cudaGetSymbolAddress((void**)&pm, g_pm);
    cudaGetSymbolAddress((void**)&pl, g_pl);
    {
        __half *p0, *p1, *p2, *p3; float* p4;
        cudaGetSymbolAddress((void**)&p0, g_wqkv);
        cudaGetSymbolAddress((void**)&p1, g_wo);
        cudaGetSymbolAddress((void**)&p2, g_w1);
        cudaGetSymbolAddress((void**)&p3, g_w2);
        cudaGetSymbolAddress((void**)&p4, g_bias3);
        for (int l = 0; l < 2; l++) {
            wqkv[l] = p0 + (size_t)l * 3 * DD * DD;
            wo[l]   = p1 + (size_t)l * DD * DD;
            w1[l]   = p2 + (size_t)l * DD * FFF;
            w2[l]   = p3 + (size_t)l * FFF * DD;
            bias3[l] = p4 + (size_t)l * NQKV;
        }
    }

    // ---- side stream for weight conversion (event-linked for graph capture) --
    static cudaStream_t s2 = nullptr;
    static cudaEvent_t evF, evQ[2], evO[2], ev1[2], ev2[2];
    if (!s2) {
        cudaStreamCreateWithFlags(&s2, cudaStreamNonBlocking);
        cudaEventCreateWithFlags(&evF, cudaEventDisableTiming);
        for (int l = 0; l < 2; l++) {
            cudaEventCreateWithFlags(&evQ[l], cudaEventDisableTiming);
            cudaEventCreateWithFlags(&evO[l], cudaEventDisableTiming);
            cudaEventCreateWithFlags(&ev1[l], cudaEventDisableTiming);
            cudaEventCreateWithFlags(&ev2[l], cudaEventDisableTiming);
        }
    }

    cudaEventRecord(evF, 0);
    cudaStreamWaitEvent(s2, evF, 0);
    for (int l = 0; l < 2; l++) {
        long long wofs = (long long)l * DD * DD;
        conv_wt<<<dim3(DD/32, DD/32), 256, 0, s2>>>(Wq + wofs, wqkv[l],            DD, DD);
        conv_wt<<<dim3(DD/32, DD/32), 256, 0, s2>>>(Wk + wofs, wqkv[l] + DD*DD,    DD, DD);
        conv_wt<<<dim3(DD/32, DD/32), 256, 0, s2>>>(Wv + wofs, wqkv[l] + 2*DD*DD,  DD, DD);
        concat3<<<3, 256, 0, s2>>>(bq + l*DD, bk + l*DD, bv + l*DD, bias3[l]);
        cudaEventRecord(evQ[l], s2);
        conv_wt<<<dim3(DD/32, DD/32), 256, 0, s2>>>(Wo + wofs, wo[l], DD, DD);
        cudaEventRecord(evO[l], s2);
        conv_wt<<<dim3(FFF/32, DD/32), 256, 0, s2>>>(W1 + (long long)l*DD*FFF, w1[l], DD, FFF);
        cudaEventRecord(ev1[l], s2);
        conv_wt<<<dim3(DD/32, FFF/32), 256, 0, s2>>>(W2 + (long long)l*FFF*DD, w2[l], FFF, DD);
        cudaEventRecord(ev2[l], s2);
    }

    embed_ln_split<<<SS, 256>>>(input_ids, word_emb, pos_emb, eln_w, eln_b, h, ah, al);

    for (int l = 0; l < 2; l++) {
        // ---- fused QKV projection (2-pass) -> split fp16 qkv in bh/bl ----
        cudaStreamWaitEvent(0, evQ[l], 0);
        gemm_mma<<<dim3(NQKV/128, SS/128, 1), 256, GEMM_SMEM>>>(
            ah, al, wqkv[l], bias3[l], nullptr, nullptr, bh, bl, SS, NQKV, DD, 3);

        // ---- MMA flash attention (writes split fp16 into ah/al) ----
        attn_mma_kernel<<<dim3(HH, 78), 128, ATTN_SMEM>>>(
            bh, bl, rand_attn + l*HH*NBB*RRR, ah, al, pO, pm, pl);
        attn_combine<<<dim3(24, 64), 64>>>(pO, pm, pl, ah, al);

        // ---- O projection (2-pass, split-K=2) + LN ----
        cudaStreamWaitEvent(0, evO[l], 0);
        gemm_mma<<<dim3(DD/128, SS/128, 2), 256, GEMM_SMEM>>>(
            ah, al, wo[l], bo + l*DD, a, a2, nullptr, nullptr, SS, DD, DD, 0);
        add_ln3<<<SS, 256>>>(h, a, a2, ln1_w + l*DD, ln1_b + l*DD, ah, al);

        // ---- FFN ----
        cudaStreamWaitEvent(0, ev1[l], 0);
        gemm_mma<<<dim3(FFF/128, SS/128, 1), 256, GEMM_SMEM>>>(
            ah, al, w1[l], b1 + l*FFF, nullptr, nullptr, bh, bl, SS, FFF, DD, 2);
        cudaStreamWaitEvent(0, ev2[l], 0);
        gemm_mma<<<dim3(DD/128, SS/128, 2), 256, GEMM_SMEM>>>(
            bh, bl, w2[l], b2 + l*DD, a, a2, nullptr, nullptr, SS, DD, FFF, 0);
        add_ln3<<<SS, 256>>>(h, a, a2, ln2_w + l*DD, ln2_b + l*DD, ah, al);
    }

    classifier_kernel<<<1, 256>>>(h, Wc, bc, out);
}

// round 11
// speedup vs baseline: 9.3844x; 1.2183x over previous
#include <cuda_runtime.h>
#include <cuda_fp16.h>
#include <math.h>
#include <stdint.h>

#define SS 4096
#define DD 768
#define HH 12
#define DHH 64
#define NBB 64
#define BSS 64
#define RRR 3
#define FFF 3072
#define CCC 8
#define NQKV 2304

// ---------------- scratch (device globals; no allocation allowed) -----------
__device__ __align__(16) float g_h  [SS*DD];
__device__ __align__(16) float g_a  [SS*DD];
__device__ __align__(16) float g_a2 [SS*DD];
__device__ __align__(16) __half g_ah[SS*FFF];
__device__ __align__(16) __half g_al[SS*FFF];
__device__ __align__(16) __half g_bh[SS*FFF];
__device__ __align__(16) __half g_bl[SS*FFF];
// per-layer fp16 weights (hi only)
__device__ __align__(16) __half g_wqkv[2][3*DD*DD];
__device__ __align__(16) __half g_wo  [2][DD*DD];
__device__ __align__(16) __half g_w1  [2][DD*FFF];
__device__ __align__(16) __half g_w2  [2][FFF*DD];
__device__ __align__(16) float  g_bias3[2][NQKV];
// edge-attention partials: 24 (h,e) x 8 chunks x 64 q x 64 d
__device__ __align__(16) float g_pO[24*8*64*64];
__device__ __align__(16) float g_pm[24*8*64];
__device__ __align__(16) float g_pl[24*8*64];

// ---------------- PTX helpers ------------------------------------------------
__device__ __forceinline__ uint32_t smem_addr(const void* p) {
    uint32_t a;
    asm("{ .reg .u64 t; cvta.to.shared.u64 t, %1; cvt.u32.u64 %0, t; }" : "=r"(a) : "l"(p));
    return a;
}
__device__ __forceinline__ void ldsm_x4(uint32_t addr, uint32_t* r) {
    asm volatile("ldmatrix.sync.aligned.m8n8.x4.shared.b16 {%0,%1,%2,%3}, [%4];"
        : "=r"(r[0]), "=r"(r[1]), "=r"(r[2]), "=r"(r[3]) : "r"(addr));
}
__device__ __forceinline__ void ldsm_x4_t(uint32_t addr, uint32_t* r) {
    asm volatile("ldmatrix.sync.aligned.m8n8.x4.trans.shared.b16 {%0,%1,%2,%3}, [%4];"
        : "=r"(r[0]), "=r"(r[1]), "=r"(r[2]), "=r"(r[3]) : "r"(addr));
}
__device__ __forceinline__ void mma_f16(float* c, const uint32_t* a, const uint32_t* b) {
    asm volatile("mma.sync.aligned.m16n8k16.row.col.f32.f16.f16.f32 "
        "{%0,%1,%2,%3}, {%4,%5,%6,%7}, {%8,%9}, {%0,%1,%2,%3};"
        : "+f"(c[0]), "+f"(c[1]), "+f"(c[2]), "+f"(c[3])
        : "r"(a[0]), "r"(a[1]), "r"(a[2]), "r"(a[3]), "r"(b[0]), "r"(b[1]));
}
__device__ __forceinline__ void mma4(float* c, const uint32_t* a, uint32_t b0, uint32_t b1) {
    uint32_t b[2] = {b0, b1};
    mma_f16(c, a, b);
}
#define CP_ASYNC(dst, src) asm volatile("cp.async.cg.shared.global [%0], [%1], 16;" :: "r"(dst), "l"(src))
#define CP_COMMIT()        asm volatile("cp.async.commit_group;")
#define CP_WAIT(n)         asm volatile("cp.async.wait_group %0;" :: "n"(n))

__device__ __forceinline__ uint32_t pack_h2(__half a, __half b) {
    __half2 t; t.x = a; t.y = b;
    return *(uint32_t*)&t;
}
__device__ __forceinline__ void split2h(float a, float b, uint32_t& hi, uint32_t& lo) {
    __half ha = __float2half_rn(a), hb = __float2half_rn(b);
    __half la = __float2half_rn(a - __half2float(ha));
    __half lb = __float2half_rn(b - __half2float(hb));
    hi = pack_h2(ha, hb);
    lo = pack_h2(la, lb);
}
__device__ __forceinline__ void write_splith(__half* hi, __half* lo, int idx, float v) {
    __half h = __float2half_rn(v);
    hi[idx] = h;
    lo[idx] = __float2half_rn(v - __half2float(h));
}

// ---------------- fp16 GEMM via mma.sync --------------------------------------
// NPASS=2: C = (Ah+Al)*Bh^T + bias (2 MMA passes, 3 tiles/stage, NS stages)
// NPASS=1: C = Ah*Bh^T + bias       (1 MMA pass, 2 tiles/stage)
// Split-K via blockIdx.z/gridDim.z: z=0 -> C (+bias), z=1 -> C2 (no bias).
// modes: 0 fp32 out, 2 gelu + split fp16 out, 3 split fp16 out, 4 gelu + fp16 hi only
#define GEMM_SMEM 98304

template<int NPASS, int NS>
__global__ void __launch_bounds__(256, 1)
gemm_mma(const __half* __restrict__ Ah, const __half* __restrict__ Al,
         const __half* __restrict__ Bh,
         const float* __restrict__ bias, float* __restrict__ C, float* __restrict__ C2,
         __half* __restrict__ Oh, __half* __restrict__ Ol,
         int M, int N, int K, int mode)
{
    constexpr int NT = NPASS + 1;          // tiles per stage (Ah,[Al],Bh)
    constexpr int STAGE = NT * 16384;
    extern __shared__ __align__(128) char smem[];
    uint32_t sb = smem_addr(smem);
    int tid = threadIdx.x, lane = tid & 31, wid = tid >> 5;
    int wm = wid & 1, wn = wid >> 1;
    int n0 = blockIdx.x * 128, m0 = blockIdx.y * 128;
    int kz = blockIdx.z, nz = gridDim.z;
    const int KT = (K >> 6) / nz;
    const int kbase = kz * KT;
    float* Cout = (kz == 0) ? C : C2;
    float bsc = (kz == 0) ? 1.f : 0.f;

    const __half* srcs[NT];
    srcs[0] = Ah + (size_t)m0 * K;
    if (NPASS == 2) srcs[1] = Al + (size_t)m0 * K;
    srcs[NT - 1] = Bh + (size_t)n0 * K;

    float acc[4][4][4];
#pragma unroll
    for (int i = 0; i < 4; i++)
#pragma unroll
        for (int j = 0; j < 4; j++)
#pragma unroll
            for (int u = 0; u < 4; u++) acc[i][j][u] = 0.f;

    auto load_stage = [&](int S, int ktIdx) {
        uint32_t sbase = sb + S * STAGE;
        int ko = (kbase + ktIdx) * 64;
#pragma unroll
        for (int t = 0; t < NT; t++) {
            const __half* sp = srcs[t];
#pragma unroll
            for (int i = 0; i < 4; i++) {
                int id = tid + i * 256;
                int row = id >> 3, c = id & 7;
                const __half* src = sp + (size_t)row * K + ko + c * 8;
                uint32_t dst = sbase + t * 16384 + row * 128 + ((c ^ (row & 7)) << 4);
                CP_ASYNC(dst, src);
            }
        }
        CP_COMMIT();
    };

#pragma unroll
    for (int s = 0; s < NS - 1; s++)
        if (s < KT) load_stage(s, s);

    for (int kt = 0; kt < KT; kt++) {
        if (kt + NS - 1 < KT) { load_stage((kt + NS - 1) % NS, kt + NS - 1); CP_WAIT(NS - 1); }
        else                  { CP_WAIT(0); }
        __syncthreads();
        uint32_t st = sb + (kt % NS) * STAGE;
#pragma unroll
        for (int ks = 0; ks < 4; ks++) {
            uint32_t ahf[4][4], alf[4][4], bhf[2][4];
#pragma unroll
            for (int mt = 0; mt < 4; mt++) {
                int row = wm * 64 + mt * 16 + (lane & 15);
                int kc = ks * 2 + (lane >> 4);
                uint32_t off = row * 128 + ((kc ^ (row & 7)) << 4);
                ldsm_x4(st + off, ahf[mt]);
                if (NPASS == 2) ldsm_x4(st + 16384 + off, alf[mt]);
            }
#pragma unroll
            for (int np = 0; np < 2; np++) {
                int row = wn * 32 + np * 16 + ((lane & 7) | ((lane & 16) >> 1));
                int kc = ks * 2 + ((lane >> 3) & 1);
                uint32_t off = row * 128 + ((kc ^ (row & 7)) << 4);
                ldsm_x4(st + (NT - 1) * 16384 + off, bhf[np]);
            }
#pragma unroll
            for (int mt = 0; mt < 4; mt++)
#pragma unroll
                for (int nt = 0; nt < 4; nt++) {
                    const uint32_t* bh_ = &bhf[nt >> 1][(nt & 1) * 2];
                    mma_f16(acc[mt][nt], ahf[mt], bh_);
                    if (NPASS == 2) mma_f16(acc[mt][nt], alf[mt], bh_);
                }
        }
        __syncthreads();
    }

#pragma unroll
    for (int mt = 0; mt < 4; mt++) {
        int mbase = m0 + wm * 64 + mt * 16 + (lane >> 2);
#pragma unroll
        for (int nt = 0; nt < 4; nt++) {
            int n = n0 + wn * 32 + nt * 8 + (lane & 3) * 2;
            float b0 = bias[n] * bsc, b1 = bias[n + 1] * bsc;
#pragma unroll
            for (int half = 0; half < 2; half++) {
                int m = mbase + half * 8;
                float v0 = acc[mt][nt][half * 2 + 0] + b0;
                float v1 = acc[mt][nt][half * 2 + 1] + b1;
                if (mode == 2 || mode == 4) {
                    float u0 = 0.7978845608028654f * (v0 + 0.044715f * v0 * v0 * v0);
                    v0 = 0.5f * v0 * (1.f + tanhf(u0));
                    float u1 = 0.7978845608028654f * (v1 + 0.044715f * v1 * v1 * v1);
                    v1 = 0.5f * v1 * (1.f + tanhf(u1));
                }
                if (mode == 2 || mode == 3) {
                    uint32_t hi, lo;
                    split2h(v0, v1, hi, lo);
                    *(uint32_t*)(Oh + (size_t)m * N + n) = hi;
                    *(uint32_t*)(Ol + (size_t)m * N + n) = lo;
                } else if (mode == 4) {
                    *(uint32_t*)(Oh + (size_t)m * N + n) = pack_h2(__float2half_rn(v0), __float2half_rn(v1));
                } else {
                    float2 o; o.x = v0; o.y = v1;
                    *(float2*)(Cout + (size_t)m * N + n) = o;
                }
            }
        }
    }
}

// ---------------- W[K,N] fp32 -> Wt[N,K] fp16 hi ------------------------------
__global__ __launch_bounds__(256) void conv_wt(const float* __restrict__ W,
    __half* __restrict__ th, int K, int N)
{
    __shared__ float tile[32][33];
    int k0 = blockIdx.y * 32, n0 = blockIdx.x * 32;
    int tx = threadIdx.x & 31, ty = threadIdx.x >> 5;
#pragma unroll
    for (int r = ty; r < 32; r += 8)
        tile[r][tx] = W[(size_t)(k0 + r) * N + n0 + tx];
    __syncthreads();
#pragma unroll
    for (int r = ty; r < 32; r += 8) {
        float v = tile[tx][r];
        th[(size_t)(n0 + r) * K + k0 + tx] = __float2half_rn(v);
    }
}

__global__ __launch_bounds__(256) void concat3(const float* __restrict__ a,
    const float* __restrict__ b, const float* __restrict__ c, float* __restrict__ o)
{
    int i = blockIdx.x * 256 + threadIdx.x;
    if (i < DD) { o[i] = a[i]; o[DD + i] = b[i]; o[2 * DD + i] = c[i]; }
}

// ---------------- reductions -------------------------------------------------
__device__ __forceinline__ void block_reduce2(float &s1v, float &s2v) {
    __shared__ float sa[8], sb2[8];
    int lane = threadIdx.x & 31, w = threadIdx.x >> 5;
#pragma unroll
    for (int off = 16; off; off >>= 1) {
        s1v += __shfl_xor_sync(0xffffffffu, s1v, off);
        s2v += __shfl_xor_sync(0xffffffffu, s2v, off);
    }
    if (lane == 0) { sa[w] = s1v; sb2[w] = s2v; }
    __syncthreads();
    if (w == 0) {
        s1v = (lane < 8) ? sa[lane] : 0.f;
        s2v = (lane < 8) ? sb2[lane] : 0.f;
#pragma unroll
        for (int off = 4; off; off >>= 1) {
            s1v += __shfl_xor_sync(0xffffffffu, s1v, off);
            s2v += __shfl_xor_sync(0xffffffffu, s2v, off);
        }
        if (lane == 0) { sa[0] = s1v; sb2[0] = s2v; }
    }
    __syncthreads();
    s1v = sa[0]; s2v = sb2[0];
}

// ---------------- embedding + LN (split out) ---------------------------------
__global__ __launch_bounds__(256) void embed_ln_split(
    const int* __restrict__ ids, const float* __restrict__ we,
    const float* __restrict__ pe, const float* __restrict__ w,
    const float* __restrict__ b, float* __restrict__ out,
    __half* __restrict__ oh, __half* __restrict__ ol)
{
    int row = blockIdx.x;
    int id = ids[row];
    float x[3], sum = 0.f, sq = 0.f;
#pragma unroll
    for (int r = 0; r < 3; r++) {
        int i = threadIdx.x + r * 256;
        x[r] = we[(long long)id * DD + i] + pe[row * DD + i];
        sum += x[r]; sq += x[r] * x[r];
    }
    block_reduce2(sum, sq);
    float mean = sum * (1.f / DD);
    float var  = sq * (1.f / DD) - mean * mean;
    float inv  = rsqrtf(var + 1e-12f);
#pragma unroll
    for (int r = 0; r < 3; r++) {
        int i = threadIdx.x + r * 256;
        float y = (x[r] - mean) * inv * w[i] + b[i];
        out[row * DD + i] = y;
        write_splith(oh, ol, row * DD + i, y);
    }
}

// ---------------- residual (h + a + a2) + LN (split out) ----------------------
__global__ __launch_bounds__(256) void add_ln3(
    float* __restrict__ h, const float* __restrict__ a, const float* __restrict__ a2,
    const float* __restrict__ w, const float* __restrict__ b,
    __half* __restrict__ oh, __half* __restrict__ ol)
{
    int row = blockIdx.x;
    float x[3], sum = 0.f, sq = 0.f;
#pragma unroll
    for (int r = 0; r < 3; r++) {
        int i = threadIdx.x + r * 256;
        x[r] = h[row * DD + i] + a[row * DD + i] + a2[row * DD + i];
        sum += x[r]; sq += x[r] * x[r];
    }
    block_reduce2(sum, sq);
    float mean = sum * (1.f / DD);
    float var  = sq * (1.f / DD) - mean * mean;
    float inv  = rsqrtf(var + 1e-12f);
#pragma unroll
    for (int r = 0; r < 3; r++) {
        int i = threadIdx.x + r * 256;
        float y = (x[r] - mean) * inv * w[i] + b[i];
        h[row * DD + i] = y;
        write_splith(oh, ol, row * DD + i, y);
    }
}

// ---------------- MMA flash attention (fp16) ----------------------------------
#define AS_QH 0
#define AS_QL 8192
#define AS_KV 16384
#define KV_STAGE 24576
#define ATTN_SMEM (16384 + 2 * KV_STAGE)

__global__ void __launch_bounds__(128)
attn_mma_kernel(const __half* __restrict__ sh, const __half* __restrict__ sl,
                const int* __restrict__ rnd,
                __half* __restrict__ th, __half* __restrict__ tl,
                float* __restrict__ pO, float* __restrict__ pm, float* __restrict__ pl)
{
    extern __shared__ __align__(128) char smem[];
    uint32_t sb = smem_addr(smem);
    int h = blockIdx.x, y = blockIdx.y;
    int tid = threadIdx.x, lane = tid & 31, w = tid >> 5;

    int qb, e = 0, z = 0;
    bool edge;
    if (y < 62) { qb = y + 1; edge = false; }
    else        { int t = y - 62; e = t >> 3; z = t & 7; qb = e ? (NBB - 1) : 0; edge = true; }

    int blks[8];
    if (edge) {
#pragma unroll
        for (int i = 0; i < 8; i++) blks[i] = z * 8 + i;
    } else {
        blks[0] = 0; blks[1] = NBB - 1; blks[2] = qb - 1; blks[3] = qb; blks[4] = qb + 1;
        const int* rp = rnd + (h * NBB + qb) * RRR;
        blks[5] = rp[0]; blks[6] = rp[1]; blks[7] = rp[2];
    }

    {
        int colq = h * DHH;
#pragma unroll
        for (int i = 0; i < 8; i++) {
            int idx = tid + i * 128;
            int t = idx >> 9, rem = idx & 511;
            int row = rem >> 3, cu = rem & 7;
            const __half* src = (t ? sl : sh) + (size_t)(qb * BSS + row) * NQKV + colq + cu * 8;
            uint32_t dst = sb + (t ? AS_QL : AS_QH) + row * 128 + ((cu ^ (row & 7)) << 4);
            CP_ASYNC(dst, src);
        }
    }
#define LOAD_KV(STG, KB) do {                                                   \
    uint32_t base_ = sb + AS_KV + (STG) * KV_STAGE;                             \
    _Pragma("unroll")                                                           \
    for (int i_ = 0; i_ < 12; i_++) {                                           \
        int idx_ = tid + i_ * 128;                                              \
        int t_ = idx_ >> 9, rem_ = idx_ & 511;                                  \
        int row_ = rem_ >> 3, cu_ = rem_ & 7;                                   \
        const __half* arr_ = (t_ == 1) ? sl : sh;                               \
        int col_ = ((t_ == 2) ? 2 : 1) * DD + h * DHH + cu_ * 8;                \
        const __half* src_ = arr_ + (size_t)((KB) * BSS + row_) * NQKV + col_;  \
        uint32_t dst_ = base_ + t_ * 8192 + row_ * 128 + ((cu_ ^ (row_ & 7)) << 4); \
        CP_ASYNC(dst_, src_);                                                   \
    }                                                                           \
} while (0)

    LOAD_KV(0, blks[0]);
    CP_COMMIT();
    CP_WAIT(0);
    __syncthreads();

    uint32_t qfh[4][4], qfl[4][4];
#pragma unroll
    for (int ds = 0; ds < 4; ds++) {
        int row = w * 16 + (lane & 15);
        int cu = ds * 2 + (lane >> 4);
        uint32_t off = row * 128 + ((cu ^ (row & 7)) << 4);
        ldsm_x4(sb + AS_QH + off, qfh[ds]);
        ldsm_x4(sb + AS_QL + off, qfl[ds]);
    }

    float o[8][4];
    float m[2] = {-1e30f, -1e30f}, l[2] = {0.f, 0.f};
#pragma unroll
    for (int j = 0; j < 8; j++)
#pragma unroll
        for (int u = 0; u < 4; u++) o[j][u] = 0.f;

    const float sc = 0.125f;

    for (int b = 0; b < 8; b++) {
        if (b + 1 < 8) { LOAD_KV((b + 1) & 1, blks[b + 1]); CP_COMMIT(); }
        uint32_t st = sb + AS_KV + (b & 1) * KV_STAGE;

        float s[8][4];
#pragma unroll
        for (int j = 0; j < 8; j++)
#pragma unroll
            for (int u = 0; u < 4; u++) s[j][u] = 0.f;
#pragma unroll
        for (int kb = 0; kb < 4; kb++) {
#pragma unroll
            for (int ds = 0; ds < 4; ds++) {
                int row = kb * 16 + (lane & 15);
                int cu = ds * 2 + (lane >> 4);
                uint32_t off = st + row * 128 + ((cu ^ (row & 7)) << 4);
                uint32_t kh4[4], kl4[4];
                ldsm_x4(off, kh4);
                ldsm_x4(off + 8192, kl4);
                mma4(s[2 * kb],     qfh[ds], kh4[0], kh4[2]);
                mma4(s[2 * kb],     qfh[ds], kl4[0], kl4[2]);
                mma4(s[2 * kb],     qfl[ds], kh4[0], kh4[2]);
                mma4(s[2 * kb + 1], qfh[ds], kh4[1], kh4[3]);
                mma4(s[2 * kb + 1], qfh[ds], kl4[1], kl4[3]);
                mma4(s[2 * kb + 1], qfl[ds], kh4[1], kh4[3]);
            }
        }

#pragma unroll
        for (int hf = 0; hf < 2; hf++) {
            float rm = -1e30f;
#pragma unroll
            for (int j = 0; j < 8; j++)
                rm = fmaxf(rm, fmaxf(s[j][hf * 2], s[j][hf * 2 + 1]));
            rm *= sc;
            rm = fmaxf(rm, __shfl_xor_sync(0xffffffffu, rm, 1));
            rm = fmaxf(rm, __shfl_xor_sync(0xffffffffu, rm, 2));
            float mn = fmaxf(m[hf], rm);
            float corr = __expf(m[hf] - mn);
            m[hf] = mn;
            float rs = 0.f;
#pragma unroll
            for (int j = 0; j < 8; j++) {
                s[j][hf * 2]     = __expf(s[j][hf * 2]     * sc - mn);
                s[j][hf * 2 + 1] = __expf(s[j][hf * 2 + 1] * sc - mn);
                rs += s[j][hf * 2] + s[j][hf * 2 + 1];
            }
            rs += __shfl_xor_sync(0xffffffffu, rs, 1);
            rs += __shfl_xor_sync(0xffffffffu, rs, 2);
            l[hf] = l[hf] * corr + rs;
#pragma unroll
            for (int j = 0; j < 8; j++) {
                o[j][hf * 2]     *= corr;
                o[j][hf * 2 + 1] *= corr;
            }
        }

#pragma unroll
        for (int ks = 0; ks < 4; ks++) {
            uint32_t ph4[4], pl4[4];
            split2h(s[2 * ks][0],     s[2 * ks][1],     ph4[0], pl4[0]);
            split2h(s[2 * ks][2],     s[2 * ks][3],     ph4[1], pl4[1]);
            split2h(s[2 * ks + 1][0], s[2 * ks + 1][1], ph4[2], pl4[2]);
            split2h(s[2 * ks + 1][2], s[2 * ks + 1][3], ph4[3], pl4[3]);
#pragma unroll
            for (int dc = 0; dc < 4; dc++) {
                int row = ks * 16 + (lane & 15);
                int cu = dc * 2 + (lane >> 4);
                uint32_t off = st + 16384 + row * 128 + ((cu ^ (row & 7)) << 4);
                uint32_t vh4[4];
                ldsm_x4_t(off, vh4);
                mma4(o[2 * dc],     ph4, vh4[0], vh4[1]);
                mma4(o[2 * dc],     pl4, vh4[0], vh4[1]);
                mma4(o[2 * dc + 1], ph4, vh4[2], vh4[3]);
                mma4(o[2 * dc + 1], pl4, vh4[2], vh4[3]);
            }
        }

        if (b + 1 < 8) { CP_WAIT(0); __syncthreads(); }
    }

    int g = lane >> 2;
    if (!edge) {
#pragma unroll
        for (int hf = 0; hf < 2; hf++) {
            float inv = 1.f / l[hf];
            int row = qb * BSS + w * 16 + g + hf * 8;
#pragma unroll
            for (int j = 0; j < 8; j++) {
                int col = h * DHH + j * 8 + (lane & 3) * 2;
                uint32_t hi, lo;
                split2h(o[j][hf * 2] * inv, o[j][hf * 2 + 1] * inv, hi, lo);
                *(uint32_t*)(th + (size_t)row * DD + col) = hi;
                *(uint32_t*)(tl + (size_t)row * DD + col) = lo;
            }
        }
    } else {
        int cb = (h * 2 + e) * 8 + z;
        float* po = pO + (size_t)cb * 64 * 64;
#pragma unroll
        for (int hf = 0; hf < 2; hf++) {
            int qr = w * 16 + g + hf * 8;
#pragma unroll
            for (int j = 0; j < 8; j++) {
                float2 val; val.x = o[j][hf * 2]; val.y = o[j][hf * 2 + 1];
                *(float2*)(po + qr * 64 + j * 8 + (lane & 3) * 2) = val;
            }
            if ((lane & 3) == 0) {
                pm[cb * 64 + qr] = m[hf];
                pl[cb * 64 + qr] = l[hf];
            }
        }
    }
}

// combine edge partials: grid (24, 64), 64 threads (d)
__global__ void __launch_bounds__(64)
attn_combine(const float* __restrict__ pO, const float* __restrict__ pm,
             const float* __restrict__ pl,
             __half* __restrict__ th, __half* __restrict__ tl)
{
    int he = blockIdx.x, q = blockIdx.y, d = threadIdx.x;
    int h = he >> 1, e = he & 1;
    float mv[8], M = -1e30f;
#pragma unroll
    for (int z = 0; z < 8; z++) {
        mv[z] = pm[(he * 8 + z) * 64 + q];
        M = fmaxf(M, mv[z]);
    }
    float L = 0.f, O = 0.f;
#pragma unroll
    for (int z = 0; z < 8; z++) {
        float w = __expf(mv[z] - M);
        L += w * pl[(he * 8 + z) * 64 + q];
        O += w * pO[((size_t)(he * 8 + z) * 64 + q) * 64 + d];
    }
    float r = O / L;
    int row = (e ? (NBB - 1) : 0) * BSS + q;
    write_splith(th, tl, row * DD + h * DHH + d, r);
}

// ---------------- classifier --------------------------------------------------
__global__ __launch_bounds__(256) void classifier_kernel(
    const float* __restrict__ h, const float* __restrict__ Wc,
    const float* __restrict__ bc, float* __restrict__ out)
{
    int warp = threadIdx.x >> 5, lane = threadIdx.x & 31;
    if (warp >= CCC) return;
    const float* hr = h + (long long)(SS - 1) * DD;
    float s = 0.f;
    for (int d = lane; d < DD; d += 32) s += hr[d] * Wc[d * CCC + warp];
#pragma unroll
    for (int off = 16; off; off >>= 1) s += __shfl_xor_sync(0xffffffffu, s, off);
    if (lane == 0) out[warp] = s + bc[warp];
}

// ---------------- launch ------------------------------------------------------
extern "C" void kernel_launch(void* const* d_in, const int* in_sizes, int n_in,
                              void* d_out, int out_size)
{
    (void)in_sizes; (void)n_in; (void)out_size;
    const int*   input_ids = (const int*)  d_in[0];
    const int*   rand_attn = (const int*)  d_in[1];
    const float* word_emb  = (const float*)d_in[2];
    const float* pos_emb   = (const float*)d_in[3];
    const float* eln_w     = (const float*)d_in[4];
    const float* eln_b     = (const float*)d_in[5];
    const float* Wq        = (const float*)d_in[6];
    const float* bq        = (const float*)d_in[7];
    const float* Wk        = (const float*)d_in[8];
    const float* bk        = (const float*)d_in[9];
    const float* Wv        = (const float*)d_in[10];
    const float* bv        = (const float*)d_in[11];
    const float* Wo        = (const float*)d_in[12];
    const float* bo        = (const float*)d_in[13];
    const float* ln1_w     = (const float*)d_in[14];
    const float* ln1_b     = (const float*)d_in[15];
    const float* W1        = (const float*)d_in[16];
    const float* b1        = (const float*)d_in[17];
    const float* W2        = (const float*)d_in[18];
    const float* b2        = (const float*)d_in[19];
    const float* ln2_w     = (const float*)d_in[20];
    const float* ln2_b     = (const float*)d_in[21];
    const float* Wc        = (const float*)d_in[22];
    const float* bc        = (const float*)d_in[23];
    float* out = (float*)d_out;

    cudaFuncSetAttribute(gemm_mma<2,2>, cudaFuncAttributeMaxDynamicSharedMemorySize, GEMM_SMEM);
    cudaFuncSetAttribute(gemm_mma<1,3>, cudaFuncAttributeMaxDynamicSharedMemorySize, GEMM_SMEM);
    cudaFuncSetAttribute(attn_mma_kernel, cudaFuncAttributeMaxDynamicSharedMemorySize, ATTN_SMEM);

    float *h, *a, *a2, *pO, *pm, *pl;
    __half *ah, *al, *bh, *bl;
    __half *wqkv[2], *wo[2], *w1[2], *w2[2];
    float  *bias3[2];
    cudaGetSymbolAddress((void**)&h,  g_h);
    cudaGetSymbolAddress((void**)&a,  g_a);
    cudaGetSymbolAddress((void**)&a2, g_a2);
    cudaGetSymbolAddress((void**)&ah, g_ah);
    cudaGetSymbolAddress((void**)&al, g_al);
    cudaGetSymbolAddress((void**)&bh, g_bh);
    cudaGetSymbolAddress((void**)&bl, g_bl);
    cudaGetSymbolAddress((void**)&pO, g_pO);
    cudaGetSymbolAddress((void**)&pm, g_pm);
    cudaGetSymbolAddress((void**)&pl, g_pl);
    {
        __half *p0, *p1, *p2, *p3; float* p4;
        cudaGetSymbolAddress((void**)&p0, g_wqkv);
        cudaGetSymbolAddress((void**)&p1, g_wo);
        cudaGetSymbolAddress((void**)&p2, g_w1);
        cudaGetSymbolAddress((void**)&p3, g_w2);
        cudaGetSymbolAddress((void**)&p4, g_bias3);
        for (int l = 0; l < 2; l++) {
            wqkv[l] = p0 + (size_t)l * 3 * DD * DD;
            wo[l]   = p1 + (size_t)l * DD * DD;
            w1[l]   = p2 + (size_t)l * DD * FFF;
            w2[l]   = p3 + (size_t)l * FFF * DD;
            bias3[l] = p4 + (size_t)l * NQKV;
        }
    }

    // ---- side stream for weight conversion (event-linked for graph capture) --
    static cudaStream_t s2 = nullptr;
    static cudaEvent_t evF, evQ[2], evO[2], ev1[2], ev2[2];
    if (!s2) {
        cudaStreamCreateWithFlags(&s2, cudaStreamNonBlocking);
        cudaEventCreateWithFlags(&evF, cudaEventDisableTiming);
        for (int l = 0; l < 2; l++) {
            cudaEventCreateWithFlags(&evQ[l], cudaEventDisableTiming);
            cudaEventCreateWithFlags(&evO[l], cudaEventDisableTiming);
            cudaEventCreateWithFlags(&ev1[l], cudaEventDisableTiming);
            cudaEventCreateWithFlags(&ev2[l], cudaEventDisableTiming);
        }
    }

    cudaEventRecord(evF, 0);
    cudaStreamWaitEvent(s2, evF, 0);
    for (int l = 0; l < 2; l++) {
        long long wofs = (long long)l * DD * DD;
        conv_wt<<<dim3(DD/32, DD/32), 256, 0, s2>>>(Wq + wofs, wqkv[l],            DD, DD);
        conv_wt<<<dim3(DD/32, DD/32), 256, 0, s2>>>(Wk + wofs, wqkv[l] + DD*DD,    DD, DD);
        conv_wt<<<dim3(DD/32, DD/32), 256, 0, s2>>>(Wv + wofs, wqkv[l] + 2*DD*DD,  DD, DD);
        concat3<<<3, 256, 0, s2>>>(bq + l*DD, bk + l*DD, bv + l*DD, bias3[l]);
        cudaEventRecord(evQ[l], s2);
        conv_wt<<<dim3(DD/32, DD/32), 256, 0, s2>>>(Wo + wofs, wo[l], DD, DD);
        cudaEventRecord(evO[l], s2);
        conv_wt<<<dim3(FFF/32, DD/32), 256, 0, s2>>>(W1 + (long long)l*DD*FFF, w1[l], DD, FFF);
        cudaEventRecord(ev1[l], s2);
        conv_wt<<<dim3(DD/32, FFF/32), 256, 0, s2>>>(W2 + (long long)l*FFF*DD, w2[l], FFF, DD);
        cudaEventRecord(ev2[l], s2);
    }

    embed_ln_split<<<SS, 256>>>(input_ids, word_emb, pos_emb, eln_w, eln_b, h, ah, al);

    for (int l = 0; l < 2; l++) {
        // ---- fused QKV projection (2-pass) -> split fp16 qkv in bh/bl ----
        cudaStreamWaitEvent(0, evQ[l], 0);
        gemm_mma<2,2><<<dim3(NQKV/128, SS/128, 1), 256, GEMM_SMEM>>>(
            ah, al, wqkv[l], bias3[l], nullptr, nullptr, bh, bl, SS, NQKV, DD, 3);

        // ---- MMA flash attention (writes split fp16 into ah/al) ----
        attn_mma_kernel<<<dim3(HH, 78), 128, ATTN_SMEM>>>(
            bh, bl, rand_attn + l*HH*NBB*RRR, ah, al, pO, pm, pl);
        attn_combine<<<dim3(24, 64), 64>>>(pO, pm, pl, ah, al);

        // ---- O projection (2-pass, split-K=2) + LN ----
        cudaStreamWaitEvent(0, evO[l], 0);
        gemm_mma<2,2><<<dim3(DD/128, SS/128, 2), 256, GEMM_SMEM>>>(
            ah, al, wo[l], bo + l*DD, a, a2, nullptr, nullptr, SS, DD, DD, 0);
        add_ln3<<<SS, 256>>>(h, a, a2, ln1_w + l*DD, ln1_b + l*DD, ah, al);

        // ---- FFN (single-pass GEMMs, 3-stage pipeline) ----
        cudaStreamWaitEvent(0, ev1[l], 0);
        gemm_mma<1,3><<<dim3(FFF/128, SS/128, 1), 256, GEMM_SMEM>>>(
            ah, nullptr, w1[l], b1 + l*FFF, nullptr, nullptr, bh, nullptr, SS, FFF, DD, 4);
        cudaStreamWaitEvent(0, ev2[l], 0);
        gemm_mma<1,3><<<dim3(DD/128, SS/128, 2), 256, GEMM_SMEM>>>(
            bh, nullptr, w2[l], b2 + l*DD, a, a2, nullptr, nullptr, SS, DD, FFF, 0);
        add_ln3<<<SS, 256>>>(h, a, a2, ln2_w + l*DD, ln2_b + l*DD, ah, al);
    }

    classifier_kernel<<<1, 256>>>(h, Wc, bc, out);
}

// round 12
// speedup vs baseline: 11.0558x; 1.1781x over previous
#include <cuda_runtime.h>
#include <cuda_fp16.h>
#include <math.h>
#include <stdint.h>

#define SS 4096
#define DD 768
#define HH 12
#define DHH 64
#define NBB 64
#define BSS 64
#define RRR 3
#define FFF 3072
#define CCC 8
#define NQKV 2304

// ---------------- scratch (device globals; no allocation allowed) -----------
__device__ __align__(16) float g_h  [SS*DD];
__device__ __align__(16) float g_a  [SS*DD];
__device__ __align__(16) float g_a2 [SS*DD];
__device__ __align__(16) __half g_ah[SS*FFF];   // activation hi
__device__ __align__(16) __half g_bh[SS*FFF];   // qkv hi / ffn-hidden hi
__device__ __align__(16) __half g_bl[SS*FFF];   // qkv lo (Q-lo used by attention)
// per-layer fp16 weights (hi only)
__device__ __align__(16) __half g_wqkv[2][3*DD*DD];
__device__ __align__(16) __half g_wo  [2][DD*DD];
__device__ __align__(16) __half g_w1  [2][DD*FFF];
__device__ __align__(16) __half g_w2  [2][FFF*DD];
__device__ __align__(16) float  g_bias3[2][NQKV];
// edge-attention partials: 24 (h,e) x 8 chunks x 64 q x 64 d
__device__ __align__(16) float g_pO[24*8*64*64];
__device__ __align__(16) float g_pm[24*8*64];
__device__ __align__(16) float g_pl[24*8*64];

// ---------------- PTX helpers ------------------------------------------------
__device__ __forceinline__ uint32_t smem_addr(const void* p) {
    uint32_t a;
    asm("{ .reg .u64 t; cvta.to.shared.u64 t, %1; cvt.u32.u64 %0, t; }" : "=r"(a) : "l"(p));
    return a;
}
__device__ __forceinline__ void ldsm_x4(uint32_t addr, uint32_t* r) {
    asm volatile("ldmatrix.sync.aligned.m8n8.x4.shared.b16 {%0,%1,%2,%3}, [%4];"
        : "=r"(r[0]), "=r"(r[1]), "=r"(r[2]), "=r"(r[3]) : "r"(addr));
}
__device__ __forceinline__ void ldsm_x4_t(uint32_t addr, uint32_t* r) {
    asm volatile("ldmatrix.sync.aligned.m8n8.x4.trans.shared.b16 {%0,%1,%2,%3}, [%4];"
        : "=r"(r[0]), "=r"(r[1]), "=r"(r[2]), "=r"(r[3]) : "r"(addr));
}
__device__ __forceinline__ void mma_f16(float* c, const uint32_t* a, const uint32_t* b) {
    asm volatile("mma.sync.aligned.m16n8k16.row.col.f32.f16.f16.f32 "
        "{%0,%1,%2,%3}, {%4,%5,%6,%7}, {%8,%9}, {%0,%1,%2,%3};"
        : "+f"(c[0]), "+f"(c[1]), "+f"(c[2]), "+f"(c[3])
        : "r"(a[0]), "r"(a[1]), "r"(a[2]), "r"(a[3]), "r"(b[0]), "r"(b[1]));
}
__device__ __forceinline__ void mma4(float* c, const uint32_t* a, uint32_t b0, uint32_t b1) {
    uint32_t b[2] = {b0, b1};
    mma_f16(c, a, b);
}
#define CP_ASYNC(dst, src) asm volatile("cp.async.cg.shared.global [%0], [%1], 16;" :: "r"(dst), "l"(src))
#define CP_COMMIT()        asm volatile("cp.async.commit_group;")
#define CP_WAIT(n)         asm volatile("cp.async.wait_group %0;" :: "n"(n))

__device__ __forceinline__ uint32_t pack_h2(__half a, __half b) {
    __half2 t; t.x = a; t.y = b;
    return *(uint32_t*)&t;
}
__device__ __forceinline__ void split2h(float a, float b, uint32_t& hi, uint32_t& lo) {
    __half ha = __float2half_rn(a), hb = __float2half_rn(b);
    __half la = __float2half_rn(a - __half2float(ha));
    __half lb = __float2half_rn(b - __half2float(hb));
    hi = pack_h2(ha, hb);
    lo = pack_h2(la, lb);
}

// ---------------- fp16 1-pass GEMM via mma.sync -------------------------------
// C = Ah * Bh^T + bias (fp32 accum). 2 tiles/stage, NS-stage cp.async pipeline.
// Split-K via blockIdx.z: z=0 -> C (+bias), z=1 -> C2 (no bias).
// modes: 0 fp32 out, 3 split fp16 out (hi+lo), 4 gelu + fp16 hi only
#define GEMM_SMEM 98304

template<int NS>
__global__ void __launch_bounds__(256, 1)
gemm_mma(const __half* __restrict__ Ah, const __half* __restrict__ Bh,
         const float* __restrict__ bias, float* __restrict__ C, float* __restrict__ C2,
         __half* __restrict__ Oh, __half* __restrict__ Ol,
         int M, int N, int K, int mode)
{
    constexpr int STAGE = 2 * 16384;
    extern __shared__ __align__(128) char smem[];
    uint32_t sb = smem_addr(smem);
    int tid = threadIdx.x, lane = tid & 31, wid = tid >> 5;
    int wm = wid & 1, wn = wid >> 1;
    int n0 = blockIdx.x * 128, m0 = blockIdx.y * 128;
    int kz = blockIdx.z, nz = gridDim.z;
    const int KT = (K >> 6) / nz;
    const int kbase = kz * KT;
    float* Cout = (kz == 0) ? C : C2;
    float bsc = (kz == 0) ? 1.f : 0.f;

    const __half* srcA = Ah + (size_t)m0 * K;
    const __half* srcB = Bh + (size_t)n0 * K;

    float acc[4][4][4];
#pragma unroll
    for (int i = 0; i < 4; i++)
#pragma unroll
        for (int j = 0; j < 4; j++)
#pragma unroll
            for (int u = 0; u < 4; u++) acc[i][j][u] = 0.f;

    auto load_stage = [&](int S, int ktIdx) {
        uint32_t sbase = sb + S * STAGE;
        int ko = (kbase + ktIdx) * 64;
#pragma unroll
        for (int t = 0; t < 2; t++) {
            const __half* sp = t ? srcB : srcA;
#pragma unroll
            for (int i = 0; i < 4; i++) {
                int id = tid + i * 256;
                int row = id >> 3, c = id & 7;
                const __half* src = sp + (size_t)row * K + ko + c * 8;
                uint32_t dst = sbase + t * 16384 + row * 128 + ((c ^ (row & 7)) << 4);
                CP_ASYNC(dst, src);
            }
        }
        CP_COMMIT();
    };

#pragma unroll
    for (int s = 0; s < NS - 1; s++)
        if (s < KT) load_stage(s, s);

    for (int kt = 0; kt < KT; kt++) {
        if (kt + NS - 1 < KT) { load_stage((kt + NS - 1) % NS, kt + NS - 1); CP_WAIT(NS - 1); }
        else                  { CP_WAIT(0); }
        __syncthreads();
        uint32_t st = sb + (kt % NS) * STAGE;
#pragma unroll
        for (int ks = 0; ks < 4; ks++) {
            uint32_t ahf[4][4], bhf[2][4];
#pragma unroll
            for (int mt = 0; mt < 4; mt++) {
                int row = wm * 64 + mt * 16 + (lane & 15);
                int kc = ks * 2 + (lane >> 4);
                uint32_t off = row * 128 + ((kc ^ (row & 7)) << 4);
                ldsm_x4(st + off, ahf[mt]);
            }
#pragma unroll
            for (int np = 0; np < 2; np++) {
                int row = wn * 32 + np * 16 + ((lane & 7) | ((lane & 16) >> 1));
                int kc = ks * 2 + ((lane >> 3) & 1);
                uint32_t off = row * 128 + ((kc ^ (row & 7)) << 4);
                ldsm_x4(st + 16384 + off, bhf[np]);
            }
#pragma unroll
            for (int mt = 0; mt < 4; mt++)
#pragma unroll
                for (int nt = 0; nt < 4; nt++)
                    mma_f16(acc[mt][nt], ahf[mt], &bhf[nt >> 1][(nt & 1) * 2]);
        }
        __syncthreads();
    }

#pragma unroll
    for (int mt = 0; mt < 4; mt++) {
        int mbase = m0 + wm * 64 + mt * 16 + (lane >> 2);
#pragma unroll
        for (int nt = 0; nt < 4; nt++) {
            int n = n0 + wn * 32 + nt * 8 + (lane & 3) * 2;
            float b0 = bias[n] * bsc, b1 = bias[n + 1] * bsc;
#pragma unroll
            for (int half = 0; half < 2; half++) {
                int m = mbase + half * 8;
                float v0 = acc[mt][nt][half * 2 + 0] + b0;
                float v1 = acc[mt][nt][half * 2 + 1] + b1;
                if (mode == 4) {
                    float u0 = 0.7978845608028654f * (v0 + 0.044715f * v0 * v0 * v0);
                    v0 = 0.5f * v0 * (1.f + tanhf(u0));
                    float u1 = 0.7978845608028654f * (v1 + 0.044715f * v1 * v1 * v1);
                    v1 = 0.5f * v1 * (1.f + tanhf(u1));
                    *(uint32_t*)(Oh + (size_t)m * N + n) = pack_h2(__float2half_rn(v0), __float2half_rn(v1));
                } else if (mode == 3) {
                    uint32_t hi, lo;
                    split2h(v0, v1, hi, lo);
                    *(uint32_t*)(Oh + (size_t)m * N + n) = hi;
                    *(uint32_t*)(Ol + (size_t)m * N + n) = lo;
                } else {
                    float2 o; o.x = v0; o.y = v1;
                    *(float2*)(Cout + (size_t)m * N + n) = o;
                }
            }
        }
    }
}

// ---------------- W[K,N] fp32 -> Wt[N,K] fp16 hi ------------------------------
__global__ __launch_bounds__(256) void conv_wt(const float* __restrict__ W,
    __half* __restrict__ th, int K, int N)
{
    __shared__ float tile[32][33];
    int k0 = blockIdx.y * 32, n0 = blockIdx.x * 32;
    int tx = threadIdx.x & 31, ty = threadIdx.x >> 5;
#pragma unroll
    for (int r = ty; r < 32; r += 8)
        tile[r][tx] = W[(size_t)(k0 + r) * N + n0 + tx];
    __syncthreads();
#pragma unroll
    for (int r = ty; r < 32; r += 8) {
        float v = tile[tx][r];
        th[(size_t)(n0 + r) * K + k0 + tx] = __float2half_rn(v);
    }
}

__global__ __launch_bounds__(256) void concat3(const float* __restrict__ a,
    const float* __restrict__ b, const float* __restrict__ c, float* __restrict__ o)
{
    int i = blockIdx.x * 256 + threadIdx.x;
    if (i < DD) { o[i] = a[i]; o[DD + i] = b[i]; o[2 * DD + i] = c[i]; }
}

// ---------------- reductions -------------------------------------------------
__device__ __forceinline__ void block_reduce2(float &s1v, float &s2v) {
    __shared__ float sa[8], sb2[8];
    int lane = threadIdx.x & 31, w = threadIdx.x >> 5;
#pragma unroll
    for (int off = 16; off; off >>= 1) {
        s1v += __shfl_xor_sync(0xffffffffu, s1v, off);
        s2v += __shfl_xor_sync(0xffffffffu, s2v, off);
    }
    if (lane == 0) { sa[w] = s1v; sb2[w] = s2v; }
    __syncthreads();
    if (w == 0) {
        s1v = (lane < 8) ? sa[lane] : 0.f;
        s2v = (lane < 8) ? sb2[lane] : 0.f;
#pragma unroll
        for (int off = 4; off; off >>= 1) {
            s1v += __shfl_xor_sync(0xffffffffu, s1v, off);
            s2v += __shfl_xor_sync(0xffffffffu, s2v, off);
        }
        if (lane == 0) { sa[0] = s1v; sb2[0] = s2v; }
    }
    __syncthreads();
    s1v = sa[0]; s2v = sb2[0];
}

// ---------------- embedding + LN (hi out) -------------------------------------
__global__ __launch_bounds__(256) void embed_ln_split(
    const int* __restrict__ ids, const float* __restrict__ we,
    const float* __restrict__ pe, const float* __restrict__ w,
    const float* __restrict__ b, float* __restrict__ out,
    __half* __restrict__ oh)
{
    int row = blockIdx.x;
    int id = ids[row];
    float x[3], sum = 0.f, sq = 0.f;
#pragma unroll
    for (int r = 0; r < 3; r++) {
        int i = threadIdx.x + r * 256;
        x[r] = we[(long long)id * DD + i] + pe[row * DD + i];
        sum += x[r]; sq += x[r] * x[r];
    }
    block_reduce2(sum, sq);
    float mean = sum * (1.f / DD);
    float var  = sq * (1.f / DD) - mean * mean;
    float inv  = rsqrtf(var + 1e-12f);
#pragma unroll
    for (int r = 0; r < 3; r++) {
        int i = threadIdx.x + r * 256;
        float y = (x[r] - mean) * inv * w[i] + b[i];
        out[row * DD + i] = y;
        oh[row * DD + i] = __float2half_rn(y);
    }
}

// ---------------- residual (h + a + a2) + LN (hi out) -------------------------
__global__ __launch_bounds__(256) void add_ln3(
    float* __restrict__ h, const float* __restrict__ a, const float* __restrict__ a2,
    const float* __restrict__ w, const float* __restrict__ b,
    __half* __restrict__ oh)
{
    int row = blockIdx.x;
    float x[3], sum = 0.f, sq = 0.f;
#pragma unroll
    for (int r = 0; r < 3; r++) {
        int i = threadIdx.x + r * 256;
        x[r] = h[row * DD + i] + a[row * DD + i] + a2[row * DD + i];
        sum += x[r]; sq += x[r] * x[r];
    }
    block_reduce2(sum, sq);
    float mean = sum * (1.f / DD);
    float var  = sq * (1.f / DD) - mean * mean;
    float inv  = rsqrtf(var + 1e-12f);
#pragma unroll
    for (int r = 0; r < 3; r++) {
        int i = threadIdx.x + r * 256;
        float y = (x[r] - mean) * inv * w[i] + b[i];
        h[row * DD + i] = y;
        oh[row * DD + i] = __float2half_rn(y);
    }
}

// ---------------- MMA flash attention (fp16) ----------------------------------
// sh/sl: split fp16 QKV [S][NQKV]; Q at col h*64, K at DD+h*64, V at 2*DD+h*64.
// S = (Qh+Ql)*Kh (2-pass, K hi only); O = (Ph+Pl)*Vh (2-pass).
// Output: hi only into th.
#define AS_QH 0
#define AS_QL 8192
#define AS_KV 16384
#define KV_STAGE 16384
#define ATTN_SMEM (16384 + 2 * KV_STAGE)

__global__ void __launch_bounds__(128)
attn_mma_kernel(const __half* __restrict__ sh, const __half* __restrict__ sl,
                const int* __restrict__ rnd,
                __half* __restrict__ th,
                float* __restrict__ pO, float* __restrict__ pm, float* __restrict__ pl)
{
    extern __shared__ __align__(128) char smem[];
    uint32_t sb = smem_addr(smem);
    int h = blockIdx.x, y = blockIdx.y;
    int tid = threadIdx.x, lane = tid & 31, w = tid >> 5;

    int qb, e = 0, z = 0;
    bool edge;
    if (y < 62) { qb = y + 1; edge = false; }
    else        { int t = y - 62; e = t >> 3; z = t & 7; qb = e ? (NBB - 1) : 0; edge = true; }

    int blks[8];
    if (edge) {
#pragma unroll
        for (int i = 0; i < 8; i++) blks[i] = z * 8 + i;
    } else {
        blks[0] = 0; blks[1] = NBB - 1; blks[2] = qb - 1; blks[3] = qb; blks[4] = qb + 1;
        const int* rp = rnd + (h * NBB + qb) * RRR;
        blks[5] = rp[0]; blks[6] = rp[1]; blks[7] = rp[2];
    }

    // ---- Q tiles (hi+lo) ----
    {
        int colq = h * DHH;
#pragma unroll
        for (int i = 0; i < 8; i++) {
            int idx = tid + i * 128;
            int t = idx >> 9, rem = idx & 511;
            int row = rem >> 3, cu = rem & 7;
            const __half* src = (t ? sl : sh) + (size_t)(qb * BSS + row) * NQKV + colq + cu * 8;
            uint32_t dst = sb + (t ? AS_QL : AS_QH) + row * 128 + ((cu ^ (row & 7)) << 4);
            CP_ASYNC(dst, src);
        }
    }
    // KV stage: t0 = Kh, t1 = Vh (16KB per stage)
#define LOAD_KV(STG, KB) do {                                                   \
    uint32_t base_ = sb + AS_KV + (STG) * KV_STAGE;                             \
    _Pragma("unroll")                                                           \
    for (int i_ = 0; i_ < 8; i_++) {                                            \
        int idx_ = tid + i_ * 128;                                              \
        int t_ = idx_ >> 9, rem_ = idx_ & 511;                                  \
        int row_ = rem_ >> 3, cu_ = rem_ & 7;                                   \
        int col_ = (t_ + 1) * DD + h * DHH + cu_ * 8;                           \
        const __half* src_ = sh + (size_t)((KB) * BSS + row_) * NQKV + col_;    \
        uint32_t dst_ = base_ + t_ * 8192 + row_ * 128 + ((cu_ ^ (row_ & 7)) << 4); \
        CP_ASYNC(dst_, src_);                                                   \
    }                                                                           \
} while (0)

    LOAD_KV(0, blks[0]);
    CP_COMMIT();
    CP_WAIT(0);
    __syncthreads();

    uint32_t qfh[4][4], qfl[4][4];
#pragma unroll
    for (int ds = 0; ds < 4; ds++) {
        int row = w * 16 + (lane & 15);
        int cu = ds * 2 + (lane >> 4);
        uint32_t off = row * 128 + ((cu ^ (row & 7)) << 4);
        ldsm_x4(sb + AS_QH + off, qfh[ds]);
        ldsm_x4(sb + AS_QL + off, qfl[ds]);
    }

    float o[8][4];
    float m[2] = {-1e30f, -1e30f}, l[2] = {0.f, 0.f};
#pragma unroll
    for (int j = 0; j < 8; j++)
#pragma unroll
        for (int u = 0; u < 4; u++) o[j][u] = 0.f;

    const float sc = 0.125f;

    for (int b = 0; b < 8; b++) {
        if (b + 1 < 8) { LOAD_KV((b + 1) & 1, blks[b + 1]); CP_COMMIT(); }
        uint32_t st = sb + AS_KV + (b & 1) * KV_STAGE;

        // ---- S = (Qh+Ql) Kh^T ----
        float s[8][4];
#pragma unroll
        for (int j = 0; j < 8; j++)
#pragma unroll
            for (int u = 0; u < 4; u++) s[j][u] = 0.f;
#pragma unroll
        for (int kb = 0; kb < 4; kb++) {
#pragma unroll
            for (int ds = 0; ds < 4; ds++) {
                int row = kb * 16 + (lane & 15);
                int cu = ds * 2 + (lane >> 4);
                uint32_t off = st + row * 128 + ((cu ^ (row & 7)) << 4);
                uint32_t kh4[4];
                ldsm_x4(off, kh4);
                mma4(s[2 * kb],     qfh[ds], kh4[0], kh4[2]);
                mma4(s[2 * kb],     qfl[ds], kh4[0], kh4[2]);
                mma4(s[2 * kb + 1], qfh[ds], kh4[1], kh4[3]);
                mma4(s[2 * kb + 1], qfl[ds], kh4[1], kh4[3]);
            }
        }

        // ---- online softmax ----
#pragma unroll
        for (int hf = 0; hf < 2; hf++) {
            float rm = -1e30f;
#pragma unroll
            for (int j = 0; j < 8; j++)
                rm = fmaxf(rm, fmaxf(s[j][hf * 2], s[j][hf * 2 + 1]));
            rm *= sc;
            rm = fmaxf(rm, __shfl_xor_sync(0xffffffffu, rm, 1));
            rm = fmaxf(rm, __shfl_xor_sync(0xffffffffu, rm, 2));
            float mn = fmaxf(m[hf], rm);
            float corr = __expf(m[hf] - mn);
            m[hf] = mn;
            float rs = 0.f;
#pragma unroll
            for (int j = 0; j < 8; j++) {
                s[j][hf * 2]     = __expf(s[j][hf * 2]     * sc - mn);
                s[j][hf * 2 + 1] = __expf(s[j][hf * 2 + 1] * sc - mn);
                rs += s[j][hf * 2] + s[j][hf * 2 + 1];
            }
            rs += __shfl_xor_sync(0xffffffffu, rs, 1);
            rs += __shfl_xor_sync(0xffffffffu, rs, 2);
            l[hf] = l[hf] * corr + rs;
#pragma unroll
            for (int j = 0; j < 8; j++) {
                o[j][hf * 2]     *= corr;
                o[j][hf * 2 + 1] *= corr;
            }
        }

        // ---- O += (Ph+Pl) Vh ----
#pragma unroll
        for (int ks = 0; ks < 4; ks++) {
            uint32_t ph4[4], pl4[4];
            split2h(s[2 * ks][0],     s[2 * ks][1],     ph4[0], pl4[0]);
            split2h(s[2 * ks][2],     s[2 * ks][3],     ph4[1], pl4[1]);
            split2h(s[2 * ks + 1][0], s[2 * ks + 1][1], ph4[2], pl4[2]);
            split2h(s[2 * ks + 1][2], s[2 * ks + 1][3], ph4[3], pl4[3]);
#pragma unroll
            for (int dc = 0; dc < 4; dc++) {
                int row = ks * 16 + (lane & 15);
                int cu = dc * 2 + (lane >> 4);
                uint32_t off = st + 8192 + row * 128 + ((cu ^ (row & 7)) << 4);
                uint32_t vh4[4];
                ldsm_x4_t(off, vh4);
                mma4(o[2 * dc],     ph4, vh4[0], vh4[1]);
                mma4(o[2 * dc],     pl4, vh4[0], vh4[1]);
                mma4(o[2 * dc + 1], ph4, vh4[2], vh4[3]);
                mma4(o[2 * dc + 1], pl4, vh4[2], vh4[3]);
            }
        }

        if (b + 1 < 8) { CP_WAIT(0); __syncthreads(); }
    }

    int g = lane >> 2;
    if (!edge) {
#pragma unroll
        for (int hf = 0; hf < 2; hf++) {
            float inv = 1.f / l[hf];
            int row = qb * BSS + w * 16 + g + hf * 8;
#pragma unroll
            for (int j = 0; j < 8; j++) {
                int col = h * DHH + j * 8 + (lane & 3) * 2;
                *(uint32_t*)(th + (size_t)row * DD + col) =
                    pack_h2(__float2half_rn(o[j][hf * 2] * inv),
                            __float2half_rn(o[j][hf * 2 + 1] * inv));
            }
        }
    } else {
        int cb = (h * 2 + e) * 8 + z;
        float* po = pO + (size_t)cb * 64 * 64;
#pragma unroll
        for (int hf = 0; hf < 2; hf++) {
            int qr = w * 16 + g + hf * 8;
#pragma unroll
            for (int j = 0; j < 8; j++) {
                float2 val; val.x = o[j][hf * 2]; val.y = o[j][hf * 2 + 1];
                *(float2*)(po + qr * 64 + j * 8 + (lane & 3) * 2) = val;
            }
            if ((lane & 3) == 0) {
                pm[cb * 64 + qr] = m[hf];
                pl[cb * 64 + qr] = l[hf];
            }
        }
    }
}

// combine edge partials: grid (24, 64), 64 threads (d); hi out only
__global__ void __launch_bounds__(64)
attn_combine(const float* __restrict__ pO, const float* __restrict__ pm,
             const float* __restrict__ pl, __half* __restrict__ th)
{
    int he = blockIdx.x, q = blockIdx.y, d = threadIdx.x;
    int h = he >> 1, e = he & 1;
    float mv[8], M = -1e30f;
#pragma unroll
    for (int z = 0; z < 8; z++) {
        mv[z] = pm[(he * 8 + z) * 64 + q];
        M = fmaxf(M, mv[z]);
    }
    float L = 0.f, O = 0.f;
#pragma unroll
    for (int z = 0; z < 8; z++) {
        float w = __expf(mv[z] - M);
        L += w * pl[(he * 8 + z) * 64 + q];
        O += w * pO[((size_t)(he * 8 + z) * 64 + q) * 64 + d];
    }
    float r = O / L;
    int row = (e ? (NBB - 1) : 0) * BSS + q;
    th[row * DD + h * DHH + d] = __float2half_rn(r);
}

// ---------------- classifier --------------------------------------------------
__global__ __launch_bounds__(256) void classifier_kernel(
    const float* __restrict__ h, const float* __restrict__ Wc,
    const float* __restrict__ bc, float* __restrict__ out)
{
    int warp = threadIdx.x >> 5, lane = threadIdx.x & 31;
    if (warp >= CCC) return;
    const float* hr = h + (long long)(SS - 1) * DD;
    float s = 0.f;
    for (int d = lane; d < DD; d += 32) s += hr[d] * Wc[d * CCC + warp];
#pragma unroll
    for (int off = 16; off; off >>= 1) s += __shfl_xor_sync(0xffffffffu, s, off);
    if (lane == 0) out[warp] = s + bc[warp];
}

// ---------------- launch ------------------------------------------------------
extern "C" void kernel_launch(void* const* d_in, const int* in_sizes, int n_in,
                              void* d_out, int out_size)
{
    (void)in_sizes; (void)n_in; (void)out_size;
    const int*   input_ids = (const int*)  d_in[0];
    const int*   rand_attn = (const int*)  d_in[1];
    const float* word_emb  = (const float*)d_in[2];
    const float* pos_emb   = (const float*)d_in[3];
    const float* eln_w     = (const float*)d_in[4];
    const float* eln_b     = (const float*)d_in[5];
    const float* Wq        = (const float*)d_in[6];
    const float* bq        = (const float*)d_in[7];
    const float* Wk        = (const float*)d_in[8];
    const float* bk        = (const float*)d_in[9];
    const float* Wv        = (const float*)d_in[10];
    const float* bv        = (const float*)d_in[11];
    const float* Wo        = (const float*)d_in[12];
    const float* bo        = (const float*)d_in[13];
    const float* ln1_w     = (const float*)d_in[14];
    const float* ln1_b     = (const float*)d_in[15];
    const float* W1        = (const float*)d_in[16];
    const float* b1        = (const float*)d_in[17];
    const float* W2        = (const float*)d_in[18];
    const float* b2        = (const float*)d_in[19];
    const float* ln2_w     = (const float*)d_in[20];
    const float* ln2_b     = (const float*)d_in[21];
    const float* Wc        = (const float*)d_in[22];
    const float* bc        = (const float*)d_in[23];
    float* out = (float*)d_out;

    cudaFuncSetAttribute(gemm_mma<3>, cudaFuncAttributeMaxDynamicSharedMemorySize, GEMM_SMEM);
    cudaFuncSetAttribute(attn_mma_kernel, cudaFuncAttributeMaxDynamicSharedMemorySize, ATTN_SMEM);

    float *h, *a, *a2, *pO, *pm, *pl;
    __half *ah, *bh, *bl;
    __half *wqkv[2], *wo[2], *w1[2], *w2[2];
    float  *bias3[2];
    cudaGetSymbolAddress((void**)&h,  g_h);
    cudaGetSymbolAddress((void**)&a,  g_a);
    cudaGetSymbolAddress((void**)&a2, g_a2);
    cudaGetSymbolAddress((void**)&ah, g_ah);
    cudaGetSymbolAddress((void**)&bh, g_bh);
    cudaGetSymbolAddress((void**)&bl, g_bl);
    cudaGetSymbolAddress((void**)&pO, g_pO);
    cudaGetSymbolAddress((void**)&pm, g_pm);
    cudaGetSymbolAddress((void**)&pl, g_pl);
    {
        __half *p0, *p1, *p2, *p3; float* p4;
        cudaGetSymbolAddress((void**)&p0, g_wqkv);
        cudaGetSymbolAddress((void**)&p1, g_wo);
        cudaGetSymbolAddress((void**)&p2, g_w1);
        cudaGetSymbolAddress((void**)&p3, g_w2);
        cudaGetSymbolAddress((void**)&p4, g_bias3);
        for (int l = 0; l < 2; l++) {
            wqkv[l] = p0 + (size_t)l * 3 * DD * DD;
            wo[l]   = p1 + (size_t)l * DD * DD;
            w1[l]   = p2 + (size_t)l * DD * FFF;
            w2[l]   = p3 + (size_t)l * FFF * DD;
            bias3[l] = p4 + (size_t)l * NQKV;
        }
    }

    // ---- side stream for weight conversion (event-linked for graph capture) --
    static cudaStream_t s2 = nullptr;
    static cudaEvent_t evF, evQ[2], evO[2], ev1[2], ev2[2];
    if (!s2) {
        cudaStreamCreateWithFlags(&s2, cudaStreamNonBlocking);
        cudaEventCreateWithFlags(&evF, cudaEventDisableTiming);
        for (int l = 0; l < 2; l++) {
            cudaEventCreateWithFlags(&evQ[l], cudaEventDisableTiming);
            cudaEventCreateWithFlags(&evO[l], cudaEventDisableTiming);
            cudaEventCreateWithFlags(&ev1[l], cudaEventDisableTiming);
            cudaEventCreateWithFlags(&ev2[l], cudaEventDisableTiming);
        }
    }

    cudaEventRecord(evF, 0);
    cudaStreamWaitEvent(s2, evF, 0);
    for (int l = 0; l < 2; l++) {
        long long wofs = (long long)l * DD * DD;
        conv_wt<<<dim3(DD/32, DD/32), 256, 0, s2>>>(Wq + wofs, wqkv[l],            DD, DD);
        conv_wt<<<dim3(DD/32, DD/32), 256, 0, s2>>>(Wk + wofs, wqkv[l] + DD*DD,    DD, DD);
        conv_wt<<<dim3(DD/32, DD/32), 256, 0, s2>>>(Wv + wofs, wqkv[l] + 2*DD*DD,  DD, DD);
        concat3<<<3, 256, 0, s2>>>(bq + l*DD, bk + l*DD, bv + l*DD, bias3[l]);
        cudaEventRecord(evQ[l], s2);
        conv_wt<<<dim3(DD/32, DD/32), 256, 0, s2>>>(Wo + wofs, wo[l], DD, DD);
        cudaEventRecord(evO[l], s2);
        conv_wt<<<dim3(FFF/32, DD/32), 256, 0, s2>>>(W1 + (long long)l*DD*FFF, w1[l], DD, FFF);
        cudaEventRecord(ev1[l], s2);
        conv_wt<<<dim3(DD/32, FFF/32), 256, 0, s2>>>(W2 + (long long)l*FFF*DD, w2[l], FFF, DD);
        cudaEventRecord(ev2[l], s2);
    }

    embed_ln_split<<<SS, 256>>>(input_ids, word_emb, pos_emb, eln_w, eln_b, h, ah);

    for (int l = 0; l < 2; l++) {
        // ---- fused QKV projection (1-pass) -> split fp16 qkv in bh/bl ----
        cudaStreamWaitEvent(0, evQ[l], 0);
        gemm_mma<3><<<dim3(NQKV/128, SS/128, 1), 256, GEMM_SMEM>>>(
            ah, wqkv[l], bias3[l], nullptr, nullptr, bh, bl, SS, NQKV, DD, 3);

        // ---- MMA flash attention (writes fp16 hi into ah) ----
        attn_mma_kernel<<<dim3(HH, 78), 128, ATTN_SMEM>>>(
            bh, bl, rand_attn + l*HH*NBB*RRR, ah, pO, pm, pl);
        attn_combine<<<dim3(24, 64), 64>>>(pO, pm, pl, ah);

        // ---- O projection (1-pass, split-K=2) + LN ----
        cudaStreamWaitEvent(0, evO[l], 0);
        gemm_mma<3><<<dim3(DD/128, SS/128, 2), 256, GEMM_SMEM>>>(
            ah, wo[l], bo + l*DD, a, a2, nullptr, nullptr, SS, DD, DD, 0);
        add_ln3<<<SS, 256>>>(h, a, a2, ln1_w + l*DD, ln1_b + l*DD, ah);

        // ---- FFN (1-pass GEMMs) ----
        cudaStreamWaitEvent(0, ev1[l], 0);
        gemm_mma<3><<<dim3(FFF/128, SS/128, 1), 256, GEMM_SMEM>>>(
            ah, w1[l], b1 + l*FFF, nullptr, nullptr, bh, nullptr, SS, FFF, DD, 4);
        cudaStreamWaitEvent(0, ev2[l], 0);
        gemm_mma<3><<<dim3(DD/128, SS/128, 2), 256, GEMM_SMEM>>>(
            bh, w2[l], b2 + l*DD, a, a2, nullptr, nullptr, SS, DD, FFF, 0);
        add_ln3<<<SS, 256>>>(h, a, a2, ln2_w + l*DD, ln2_b + l*DD, ah);
    }

    classifier_kernel<<<1, 256>>>(h, Wc, bc, out);
}

// round 13
// speedup vs baseline: 13.5413x; 1.2248x over previous
#include <cuda_runtime.h>
#include <cuda_fp16.h>
#include <math.h>
#include <stdint.h>

#define SS 4096
#define DD 768
#define HH 12
#define DHH 64
#define NBB 64
#define BSS 64
#define RRR 3
#define FFF 3072
#define CCC 8
#define NQKV 2304

// ---------------- scratch (device globals; no allocation allowed) -----------
__device__ __align__(16) float g_h  [SS*DD];
__device__ __align__(16) float g_a  [SS*DD];
__device__ __align__(16) float g_a2 [SS*DD];
__device__ __align__(16) __half g_ah[SS*FFF];   // activation hi
__device__ __align__(16) __half g_bh[SS*FFF];   // qkv hi / ffn-hidden hi
// per-layer fp16 weights (hi only)
__device__ __align__(16) __half g_wqkv[2][3*DD*DD];
__device__ __align__(16) __half g_wo  [2][DD*DD];
__device__ __align__(16) __half g_w1  [2][DD*FFF];
__device__ __align__(16) __half g_w2  [2][FFF*DD];
__device__ __align__(16) float  g_bias3[2][NQKV];
// edge-attention partials: 24 (h,e) x 8 chunks x 64 q x 64 d
__device__ __align__(16) float g_pO[24*8*64*64];
__device__ __align__(16) float g_pm[24*8*64];
__device__ __align__(16) float g_pl[24*8*64];

// ---------------- PTX helpers ------------------------------------------------
__device__ __forceinline__ uint32_t smem_addr(const void* p) {
    uint32_t a;
    asm("{ .reg .u64 t; cvta.to.shared.u64 t, %1; cvt.u32.u64 %0, t; }" : "=r"(a) : "l"(p));
    return a;
}
__device__ __forceinline__ void ldsm_x4(uint32_t addr, uint32_t* r) {
    asm volatile("ldmatrix.sync.aligned.m8n8.x4.shared.b16 {%0,%1,%2,%3}, [%4];"
        : "=r"(r[0]), "=r"(r[1]), "=r"(r[2]), "=r"(r[3]) : "r"(addr));
}
__device__ __forceinline__ void ldsm_x4_t(uint32_t addr, uint32_t* r) {
    asm volatile("ldmatrix.sync.aligned.m8n8.x4.trans.shared.b16 {%0,%1,%2,%3}, [%4];"
        : "=r"(r[0]), "=r"(r[1]), "=r"(r[2]), "=r"(r[3]) : "r"(addr));
}
__device__ __forceinline__ void mma_f16(float* c, const uint32_t* a, const uint32_t* b) {
    asm volatile("mma.sync.aligned.m16n8k16.row.col.f32.f16.f16.f32 "
        "{%0,%1,%2,%3}, {%4,%5,%6,%7}, {%8,%9}, {%0,%1,%2,%3};"
        : "+f"(c[0]), "+f"(c[1]), "+f"(c[2]), "+f"(c[3])
        : "r"(a[0]), "r"(a[1]), "r"(a[2]), "r"(a[3]), "r"(b[0]), "r"(b[1]));
}
__device__ __forceinline__ void mma4(float* c, const uint32_t* a, uint32_t b0, uint32_t b1) {
    uint32_t b[2] = {b0, b1};
    mma_f16(c, a, b);
}
#define CP_ASYNC(dst, src) asm volatile("cp.async.cg.shared.global [%0], [%1], 16;" :: "r"(dst), "l"(src))
#define CP_COMMIT()        asm volatile("cp.async.commit_group;")
#define CP_WAIT(n)         asm volatile("cp.async.wait_group %0;" :: "n"(n))

__device__ __forceinline__ uint32_t pack_h2(__half a, __half b) {
    __half2 t; t.x = a; t.y = b;
    return *(uint32_t*)&t;
}

// ---------------- fp16 1-pass GEMM via mma.sync -------------------------------
// C = Ah * Bh^T + bias (fp32 accum). 2 tiles/stage, NS-stage cp.async pipeline.
// Split-K via blockIdx.z: z=0 -> C (+bias), z=1 -> C2 (no bias).
// modes: 0 fp32 out, 4 gelu + fp16 hi, 5 fp16 hi (no gelu)
#define GEMM_SMEM 98304

template<int NS>
__global__ void __launch_bounds__(256, 2)
gemm_mma(const __half* __restrict__ Ah, const __half* __restrict__ Bh,
         const float* __restrict__ bias, float* __restrict__ C, float* __restrict__ C2,
         __half* __restrict__ Oh,
         int M, int N, int K, int mode)
{
    constexpr int STAGE = 2 * 16384;
    extern __shared__ __align__(128) char smem[];
    uint32_t sb = smem_addr(smem);
    int tid = threadIdx.x, lane = tid & 31, wid = tid >> 5;
    int wm = wid & 1, wn = wid >> 1;
    int n0 = blockIdx.x * 128, m0 = blockIdx.y * 128;
    int kz = blockIdx.z, nz = gridDim.z;
    const int KT = (K >> 6) / nz;
    const int kbase = kz * KT;
    float* Cout = (kz == 0) ? C : C2;
    float bsc = (kz == 0) ? 1.f : 0.f;

    const __half* srcA = Ah + (size_t)m0 * K;
    const __half* srcB = Bh + (size_t)n0 * K;

    float acc[4][4][4];
#pragma unroll
    for (int i = 0; i < 4; i++)
#pragma unroll
        for (int j = 0; j < 4; j++)
#pragma unroll
            for (int u = 0; u < 4; u++) acc[i][j][u] = 0.f;

    auto load_stage = [&](int S, int ktIdx) {
        uint32_t sbase = sb + S * STAGE;
        int ko = (kbase + ktIdx) * 64;
#pragma unroll
        for (int t = 0; t < 2; t++) {
            const __half* sp = t ? srcB : srcA;
#pragma unroll
            for (int i = 0; i < 4; i++) {
                int id = tid + i * 256;
                int row = id >> 3, c = id & 7;
                const __half* src = sp + (size_t)row * K + ko + c * 8;
                uint32_t dst = sbase + t * 16384 + row * 128 + ((c ^ (row & 7)) << 4);
                CP_ASYNC(dst, src);
            }
        }
        CP_COMMIT();
    };

#pragma unroll
    for (int s = 0; s < NS - 1; s++)
        if (s < KT) load_stage(s, s);

    for (int kt = 0; kt < KT; kt++) {
        if (kt + NS - 1 < KT) { load_stage((kt + NS - 1) % NS, kt + NS - 1); CP_WAIT(NS - 1); }
        else                  { CP_WAIT(0); }
        __syncthreads();
        uint32_t st = sb + (kt % NS) * STAGE;
#pragma unroll
        for (int ks = 0; ks < 4; ks++) {
            uint32_t ahf[4][4], bhf[2][4];
#pragma unroll
            for (int mt = 0; mt < 4; mt++) {
                int row = wm * 64 + mt * 16 + (lane & 15);
                int kc = ks * 2 + (lane >> 4);
                uint32_t off = row * 128 + ((kc ^ (row & 7)) << 4);
                ldsm_x4(st + off, ahf[mt]);
            }
#pragma unroll
            for (int np = 0; np < 2; np++) {
                int row = wn * 32 + np * 16 + ((lane & 7) | ((lane & 16) >> 1));
                int kc = ks * 2 + ((lane >> 3) & 1);
                uint32_t off = row * 128 + ((kc ^ (row & 7)) << 4);
                ldsm_x4(st + 16384 + off, bhf[np]);
            }
#pragma unroll
            for (int mt = 0; mt < 4; mt++)
#pragma unroll
                for (int nt = 0; nt < 4; nt++)
                    mma_f16(acc[mt][nt], ahf[mt], &bhf[nt >> 1][(nt & 1) * 2]);
        }
        __syncthreads();
    }

#pragma unroll
    for (int mt = 0; mt < 4; mt++) {
        int mbase = m0 + wm * 64 + mt * 16 + (lane >> 2);
#pragma unroll
        for (int nt = 0; nt < 4; nt++) {
            int n = n0 + wn * 32 + nt * 8 + (lane & 3) * 2;
            float b0 = bias[n] * bsc, b1 = bias[n + 1] * bsc;
#pragma unroll
            for (int half = 0; half < 2; half++) {
                int m = mbase + half * 8;
                float v0 = acc[mt][nt][half * 2 + 0] + b0;
                float v1 = acc[mt][nt][half * 2 + 1] + b1;
                if (mode == 4) {
                    float u0 = 0.7978845608028654f * (v0 + 0.044715f * v0 * v0 * v0);
                    v0 = 0.5f * v0 * (1.f + tanhf(u0));
                    float u1 = 0.7978845608028654f * (v1 + 0.044715f * v1 * v1 * v1);
                    v1 = 0.5f * v1 * (1.f + tanhf(u1));
                }
                if (mode >= 4) {
                    *(uint32_t*)(Oh + (size_t)m * N + n) = pack_h2(__float2half_rn(v0), __float2half_rn(v1));
                } else {
                    float2 o; o.x = v0; o.y = v1;
                    *(float2*)(Cout + (size_t)m * N + n) = o;
                }
            }
        }
    }
}

// ---------------- W[K,N] fp32 -> Wt[N,K] fp16 hi ------------------------------
__global__ __launch_bounds__(256) void conv_wt(const float* __restrict__ W,
    __half* __restrict__ th, int K, int N)
{
    __shared__ float tile[32][33];
    int k0 = blockIdx.y * 32, n0 = blockIdx.x * 32;
    int tx = threadIdx.x & 31, ty = threadIdx.x >> 5;
#pragma unroll
    for (int r = ty; r < 32; r += 8)
        tile[r][tx] = W[(size_t)(k0 + r) * N + n0 + tx];
    __syncthreads();
#pragma unroll
    for (int r = ty; r < 32; r += 8) {
        float v = tile[tx][r];
        th[(size_t)(n0 + r) * K + k0 + tx] = __float2half_rn(v);
    }
}

__global__ __launch_bounds__(256) void concat3(const float* __restrict__ a,
    const float* __restrict__ b, const float* __restrict__ c, float* __restrict__ o)
{
    int i = blockIdx.x * 256 + threadIdx.x;
    if (i < DD) { o[i] = a[i]; o[DD + i] = b[i]; o[2 * DD + i] = c[i]; }
}

// ---------------- reductions -------------------------------------------------
__device__ __forceinline__ void block_reduce2(float &s1v, float &s2v) {
    __shared__ float sa[8], sb2[8];
    int lane = threadIdx.x & 31, w = threadIdx.x >> 5;
#pragma unroll
    for (int off = 16; off; off >>= 1) {
        s1v += __shfl_xor_sync(0xffffffffu, s1v, off);
        s2v += __shfl_xor_sync(0xffffffffu, s2v, off);
    }
    if (lane == 0) { sa[w] = s1v; sb2[w] = s2v; }
    __syncthreads();
    if (w == 0) {
        s1v = (lane < 8) ? sa[lane] : 0.f;
        s2v = (lane < 8) ? sb2[lane] : 0.f;
#pragma unroll
        for (int off = 4; off; off >>= 1) {
            s1v += __shfl_xor_sync(0xffffffffu, s1v, off);
            s2v += __shfl_xor_sync(0xffffffffu, s2v, off);
        }
        if (lane == 0) { sa[0] = s1v; sb2[0] = s2v; }
    }
    __syncthreads();
    s1v = sa[0]; s2v = sb2[0];
}

// ---------------- embedding + LN (hi out) -------------------------------------
__global__ __launch_bounds__(256) void embed_ln_split(
    const int* __restrict__ ids, const float* __restrict__ we,
    const float* __restrict__ pe, const float* __restrict__ w,
    const float* __restrict__ b, float* __restrict__ out,
    __half* __restrict__ oh)
{
    int row = blockIdx.x;
    int id = ids[row];
    float x[3], sum = 0.f, sq = 0.f;
#pragma unroll
    for (int r = 0; r < 3; r++) {
        int i = threadIdx.x + r * 256;
        x[r] = we[(long long)id * DD + i] + pe[row * DD + i];
        sum += x[r]; sq += x[r] * x[r];
    }
    block_reduce2(sum, sq);
    float mean = sum * (1.f / DD);
    float var  = sq * (1.f / DD) - mean * mean;
    float inv  = rsqrtf(var + 1e-12f);
#pragma unroll
    for (int r = 0; r < 3; r++) {
        int i = threadIdx.x + r * 256;
        float y = (x[r] - mean) * inv * w[i] + b[i];
        out[row * DD + i] = y;
        oh[row * DD + i] = __float2half_rn(y);
    }
}

// ---------------- residual (h + a + a2) + LN (hi out) -------------------------
__global__ __launch_bounds__(256) void add_ln3(
    float* __restrict__ h, const float* __restrict__ a, const float* __restrict__ a2,
    const float* __restrict__ w, const float* __restrict__ b,
    __half* __restrict__ oh)
{
    int row = blockIdx.x;
    float x[3], sum = 0.f, sq = 0.f;
#pragma unroll
    for (int r = 0; r < 3; r++) {
        int i = threadIdx.x + r * 256;
        x[r] = h[row * DD + i] + a[row * DD + i] + a2[row * DD + i];
        sum += x[r]; sq += x[r] * x[r];
    }
    block_reduce2(sum, sq);
    float mean = sum * (1.f / DD);
    float var  = sq * (1.f / DD) - mean * mean;
    float inv  = rsqrtf(var + 1e-12f);
#pragma unroll
    for (int r = 0; r < 3; r++) {
        int i = threadIdx.x + r * 256;
        float y = (x[r] - mean) * inv * w[i] + b[i];
        h[row * DD + i] = y;
        oh[row * DD + i] = __float2half_rn(y);
    }
}

// ---------------- MMA flash attention (fp16, 1-pass) ---------------------------
// sh: fp16 QKV [S][NQKV]; Q at col h*64, K at DD+h*64, V at 2*DD+h*64.
// S = Qh*Kh; O = Ph*Vh. Output: hi only into th.
#define AS_Q 0
#define AS_KV 8192
#define KV_STAGE 16384
#define ATTN_SMEM (8192 + 2 * KV_STAGE)

__global__ void __launch_bounds__(128)
attn_mma_kernel(const __half* __restrict__ sh, const int* __restrict__ rnd,
                __half* __restrict__ th,
                float* __restrict__ pO, float* __restrict__ pm, float* __restrict__ pl)
{
    extern __shared__ __align__(128) char smem[];
    uint32_t sb = smem_addr(smem);
    int h = blockIdx.x, y = blockIdx.y;
    int tid = threadIdx.x, lane = tid & 31, w = tid >> 5;

    int qb, e = 0, z = 0;
    bool edge;
    if (y < 62) { qb = y + 1; edge = false; }
    else        { int t = y - 62; e = t >> 3; z = t & 7; qb = e ? (NBB - 1) : 0; edge = true; }

    int blks[8];
    if (edge) {
#pragma unroll
        for (int i = 0; i < 8; i++) blks[i] = z * 8 + i;
    } else {
        blks[0] = 0; blks[1] = NBB - 1; blks[2] = qb - 1; blks[3] = qb; blks[4] = qb + 1;
        const int* rp = rnd + (h * NBB + qb) * RRR;
        blks[5] = rp[0]; blks[6] = rp[1]; blks[7] = rp[2];
    }

    // ---- Q tile (hi) ----
    {
        int colq = h * DHH;
#pragma unroll
        for (int i = 0; i < 4; i++) {
            int idx = tid + i * 128;
            int row = idx >> 3, cu = idx & 7;
            const __half* src = sh + (size_t)(qb * BSS + row) * NQKV + colq + cu * 8;
            uint32_t dst = sb + AS_Q + row * 128 + ((cu ^ (row & 7)) << 4);
            CP_ASYNC(dst, src);
        }
    }
    // KV stage: t0 = Kh, t1 = Vh (16KB per stage)
#define LOAD_KV(STG, KB) do {                                                   \
    uint32_t base_ = sb + AS_KV + (STG) * KV_STAGE;                             \
    _Pragma("unroll")                                                           \
    for (int i_ = 0; i_ < 8; i_++) {                                            \
        int idx_ = tid + i_ * 128;                                              \
        int t_ = idx_ >> 9, rem_ = idx_ & 511;                                  \
        int row_ = rem_ >> 3, cu_ = rem_ & 7;                                   \
        int col_ = (t_ + 1) * DD + h * DHH + cu_ * 8;                           \
        const __half* src_ = sh + (size_t)((KB) * BSS + row_) * NQKV + col_;    \
        uint32_t dst_ = base_ + t_ * 8192 + row_ * 128 + ((cu_ ^ (row_ & 7)) << 4); \
        CP_ASYNC(dst_, src_);                                                   \
    }                                                                           \
} while (0)

    LOAD_KV(0, blks[0]);
    CP_COMMIT();
    CP_WAIT(0);
    __syncthreads();

    uint32_t qfh[4][4];
#pragma unroll
    for (int ds = 0; ds < 4; ds++) {
        int row = w * 16 + (lane & 15);
        int cu = ds * 2 + (lane >> 4);
        uint32_t off = row * 128 + ((cu ^ (row & 7)) << 4);
        ldsm_x4(sb + AS_Q + off, qfh[ds]);
    }

    float o[8][4];
    float m[2] = {-1e30f, -1e30f}, l[2] = {0.f, 0.f};
#pragma unroll
    for (int j = 0; j < 8; j++)
#pragma unroll
        for (int u = 0; u < 4; u++) o[j][u] = 0.f;

    const float sc = 0.125f;

    for (int b = 0; b < 8; b++) {
        if (b + 1 < 8) { LOAD_KV((b + 1) & 1, blks[b + 1]); CP_COMMIT(); }
        uint32_t st = sb + AS_KV + (b & 1) * KV_STAGE;

        // ---- S = Qh Kh^T ----
        float s[8][4];
#pragma unroll
        for (int j = 0; j < 8; j++)
#pragma unroll
            for (int u = 0; u < 4; u++) s[j][u] = 0.f;
#pragma unroll
        for (int kb = 0; kb < 4; kb++) {
#pragma unroll
            for (int ds = 0; ds < 4; ds++) {
                int row = kb * 16 + (lane & 15);
                int cu = ds * 2 + (lane >> 4);
                uint32_t off = st + row * 128 + ((cu ^ (row & 7)) << 4);
                uint32_t kh4[4];
                ldsm_x4(off, kh4);
                mma4(s[2 * kb],     qfh[ds], kh4[0], kh4[2]);
                mma4(s[2 * kb + 1], qfh[ds], kh4[1], kh4[3]);
            }
        }

        // ---- online softmax ----
#pragma unroll
        for (int hf = 0; hf < 2; hf++) {
            float rm = -1e30f;
#pragma unroll
            for (int j = 0; j < 8; j++)
                rm = fmaxf(rm, fmaxf(s[j][hf * 2], s[j][hf * 2 + 1]));
            rm *= sc;
            rm = fmaxf(rm, __shfl_xor_sync(0xffffffffu, rm, 1));
            rm = fmaxf(rm, __shfl_xor_sync(0xffffffffu, rm, 2));
            float mn = fmaxf(m[hf], rm);
            float corr = __expf(m[hf] - mn);
            m[hf] = mn;
            float rs = 0.f;
#pragma unroll
            for (int j = 0; j < 8; j++) {
                s[j][hf * 2]     = __expf(s[j][hf * 2]     * sc - mn);
                s[j][hf * 2 + 1] = __expf(s[j][hf * 2 + 1] * sc - mn);
                rs += s[j][hf * 2] + s[j][hf * 2 + 1];
            }
            rs += __shfl_xor_sync(0xffffffffu, rs, 1);
            rs += __shfl_xor_sync(0xffffffffu, rs, 2);
            l[hf] = l[hf] * corr + rs;
#pragma unroll
            for (int j = 0; j < 8; j++) {
                o[j][hf * 2]     *= corr;
                o[j][hf * 2 + 1] *= corr;
            }
        }

        // ---- O += Ph Vh ----
#pragma unroll
        for (int ks = 0; ks < 4; ks++) {
            uint32_t ph4[4];
            ph4[0] = pack_h2(__float2half_rn(s[2 * ks][0]),     __float2half_rn(s[2 * ks][1]));
            ph4[1] = pack_h2(__float2half_rn(s[2 * ks][2]),     __float2half_rn(s[2 * ks][3]));
            ph4[2] = pack_h2(__float2half_rn(s[2 * ks + 1][0]), __float2half_rn(s[2 * ks + 1][1]));
            ph4[3] = pack_h2(__float2half_rn(s[2 * ks + 1][2]), __float2half_rn(s[2 * ks + 1][3]));
#pragma unroll
            for (int dc = 0; dc < 4; dc++) {
                int row = ks * 16 + (lane & 15);
                int cu = dc * 2 + (lane >> 4);
                uint32_t off = st + 8192 + row * 128 + ((cu ^ (row & 7)) << 4);
                uint32_t vh4[4];
                ldsm_x4_t(off, vh4);
                mma4(o[2 * dc],     ph4, vh4[0], vh4[1]);
                mma4(o[2 * dc + 1], ph4, vh4[2], vh4[3]);
            }
        }

        if (b + 1 < 8) { CP_WAIT(0); __syncthreads(); }
    }

    int g = lane >> 2;
    if (!edge) {
#pragma unroll
        for (int hf = 0; hf < 2; hf++) {
            float inv = 1.f / l[hf];
            int row = qb * BSS + w * 16 + g + hf * 8;
#pragma unroll
            for (int j = 0; j < 8; j++) {
                int col = h * DHH + j * 8 + (lane & 3) * 2;
                *(uint32_t*)(th + (size_t)row * DD + col) =
                    pack_h2(__float2half_rn(o[j][hf * 2] * inv),
                            __float2half_rn(o[j][hf * 2 + 1] * inv));
            }
        }
    } else {
        int cb = (h * 2 + e) * 8 + z;
        float* po = pO + (size_t)cb * 64 * 64;
#pragma unroll
        for (int hf = 0; hf < 2; hf++) {
            int qr = w * 16 + g + hf * 8;
#pragma unroll
            for (int j = 0; j < 8; j++) {
                float2 val; val.x = o[j][hf * 2]; val.y = o[j][hf * 2 + 1];
                *(float2*)(po + qr * 64 + j * 8 + (lane & 3) * 2) = val;
            }
            if ((lane & 3) == 0) {
                pm[cb * 64 + qr] = m[hf];
                pl[cb * 64 + qr] = l[hf];
            }
        }
    }
}

// combine edge partials: grid (24, 64), 64 threads (d); hi out only
__global__ void __launch_bounds__(64)
attn_combine(const float* __restrict__ pO, const float* __restrict__ pm,
             const float* __restrict__ pl, __half* __restrict__ th)
{
    int he = blockIdx.x, q = blockIdx.y, d = threadIdx.x;
    int h = he >> 1, e = he & 1;
    float mv[8], M = -1e30f;
#pragma unroll
    for (int z = 0; z < 8; z++) {
        mv[z] = pm[(he * 8 + z) * 64 + q];
        M = fmaxf(M, mv[z]);
    }
    float L = 0.f, O = 0.f;
#pragma unroll
    for (int z = 0; z < 8; z++) {
        float w = __expf(mv[z] - M);
        L += w * pl[(he * 8 + z) * 64 + q];
        O += w * pO[((size_t)(he * 8 + z) * 64 + q) * 64 + d];
    }
    float r = O / L;
    int row = (e ? (NBB - 1) : 0) * BSS + q;
    th[row * DD + h * DHH + d] = __float2half_rn(r);
}

// ---------------- classifier --------------------------------------------------
__global__ __launch_bounds__(256) void classifier_kernel(
    const float* __restrict__ h, const float* __restrict__ Wc,
    const float* __restrict__ bc, float* __restrict__ out)
{
    int warp = threadIdx.x >> 5, lane = threadIdx.x & 31;
    if (warp >= CCC) return;
    const float* hr = h + (long long)(SS - 1) * DD;
    float s = 0.f;
    for (int d = lane; d < DD; d += 32) s += hr[d] * Wc[d * CCC + warp];
#pragma unroll
    for (int off = 16; off; off >>= 1) s += __shfl_xor_sync(0xffffffffu, s, off);
    if (lane == 0) out[warp] = s + bc[warp];
}

// ---------------- launch ------------------------------------------------------
extern "C" void kernel_launch(void* const* d_in, const int* in_sizes, int n_in,
                              void* d_out, int out_size)
{
    (void)in_sizes; (void)n_in; (void)out_size;
    const int*   input_ids = (const int*)  d_in[0];
    const int*   rand_attn = (const int*)  d_in[1];
    const float* word_emb  = (const float*)d_in[2];
    const float* pos_emb   = (const float*)d_in[3];
    const float* eln_w     = (const float*)d_in[4];
    const float* eln_b     = (const float*)d_in[5];
    const float* Wq        = (const float*)d_in[6];
    const float* bq        = (const float*)d_in[7];
    const float* Wk        = (const float*)d_in[8];
    const float* bk        = (const float*)d_in[9];
    const float* Wv        = (const float*)d_in[10];
    const float* bv        = (const float*)d_in[11];
    const float* Wo        = (const float*)d_in[12];
    const float* bo        = (const float*)d_in[13];
    const float* ln1_w     = (const float*)d_in[14];
    const float* ln1_b     = (const float*)d_in[15];
    const float* W1        = (const float*)d_in[16];
    const float* b1        = (const float*)d_in[17];
    const float* W2        = (const float*)d_in[18];
    const float* b2        = (const float*)d_in[19];
    const float* ln2_w     = (const float*)d_in[20];
    const float* ln2_b     = (const float*)d_in[21];
    const float* Wc        = (const float*)d_in[22];
    const float* bc        = (const float*)d_in[23];
    float* out = (float*)d_out;

    cudaFuncSetAttribute(gemm_mma<3>, cudaFuncAttributeMaxDynamicSharedMemorySize, GEMM_SMEM);
    cudaFuncSetAttribute(attn_mma_kernel, cudaFuncAttributeMaxDynamicSharedMemorySize, ATTN_SMEM);

    float *h, *a, *a2, *pO, *pm, *pl;
    __half *ah, *bh;
    __half *wqkv[2], *wo[2], *w1[2], *w2[2];
    float  *bias3[2];
    cudaGetSymbolAddress((void**)&h,  g_h);
    cudaGetSymbolAddress((void**)&a,  g_a);
    cudaGetSymbolAddress((void**)&a2, g_a2);
    cudaGetSymbolAddress((void**)&ah, g_ah);
    cudaGetSymbolAddress((void**)&bh, g_bh);
    cudaGetSymbolAddress((void**)&pO, g_pO);
    cudaGetSymbolAddress((void**)&pm, g_pm);
    cudaGetSymbolAddress((void**)&pl, g_pl);
    {
        __half *p0, *p1, *p2, *p3; float* p4;
        cudaGetSymbolAddress((void**)&p0, g_wqkv);
        cudaGetSymbolAddress((void**)&p1, g_wo);
        cudaGetSymbolAddress((void**)&p2, g_w1);
        cudaGetSymbolAddress((void**)&p3, g_w2);
        cudaGetSymbolAddress((void**)&p4, g_bias3);
        for (int l = 0; l < 2; l++) {
            wqkv[l] = p0 + (size_t)l * 3 * DD * DD;
            wo[l]   = p1 + (size_t)l * DD * DD;
            w1[l]   = p2 + (size_t)l * DD * FFF;
            w2[l]   = p3 + (size_t)l * FFF * DD;
            bias3[l] = p4 + (size_t)l * NQKV;
        }
    }

    // ---- side stream for weight conversion (event-linked for graph capture) --
    static cudaStream_t s2 = nullptr;
    static cudaEvent_t evF, evQ[2], evO[2], ev1[2], ev2[2];
    if (!s2) {
        cudaStreamCreateWithFlags(&s2, cudaStreamNonBlocking);
        cudaEventCreateWithFlags(&evF, cudaEventDisableTiming);
        for (int l = 0; l < 2; l++) {
            cudaEventCreateWithFlags(&evQ[l], cudaEventDisableTiming);
            cudaEventCreateWithFlags(&evO[l], cudaEventDisableTiming);
            cudaEventCreateWithFlags(&ev1[l], cudaEventDisableTiming);
            cudaEventCreateWithFlags(&ev2[l], cudaEventDisableTiming);
        }
    }

    cudaEventRecord(evF, 0);
    cudaStreamWaitEvent(s2, evF, 0);
    for (int l = 0; l < 2; l++) {
        long long wofs = (long long)l * DD * DD;
        conv_wt<<<dim3(DD/32, DD/32), 256, 0, s2>>>(Wq + wofs, wqkv[l],            DD, DD);
        conv_wt<<<dim3(DD/32, DD/32), 256, 0, s2>>>(Wk + wofs, wqkv[l] + DD*DD,    DD, DD);
        conv_wt<<<dim3(DD/32, DD/32), 256, 0, s2>>>(Wv + wofs, wqkv[l] + 2*DD*DD,  DD, DD);
        concat3<<<3, 256, 0, s2>>>(bq + l*DD, bk + l*DD, bv + l*DD, bias3[l]);
        cudaEventRecord(evQ[l], s2);
        conv_wt<<<dim3(DD/32, DD/32), 256, 0, s2>>>(Wo + wofs, wo[l], DD, DD);
        cudaEventRecord(evO[l], s2);
        conv_wt<<<dim3(FFF/32, DD/32), 256, 0, s2>>>(W1 + (long long)l*DD*FFF, w1[l], DD, FFF);
        cudaEventRecord(ev1[l], s2);
        conv_wt<<<dim3(DD/32, FFF/32), 256, 0, s2>>>(W2 + (long long)l*FFF*DD, w2[l], FFF, DD);
        cudaEventRecord(ev2[l], s2);
    }

    embed_ln_split<<<SS, 256>>>(input_ids, word_emb, pos_emb, eln_w, eln_b, h, ah);

    for (int l = 0; l < 2; l++) {
        // ---- fused QKV projection (1-pass, fp16 hi out) ----
        cudaStreamWaitEvent(0, evQ[l], 0);
        gemm_mma<3><<<dim3(NQKV/128, SS/128, 1), 256, GEMM_SMEM>>>(
            ah, wqkv[l], bias3[l], nullptr, nullptr, bh, SS, NQKV, DD, 5);

        // ---- MMA flash attention (writes fp16 hi into ah) ----
        attn_mma_kernel<<<dim3(HH, 78), 128, ATTN_SMEM>>>(
            bh, rand_attn + l*HH*NBB*RRR, ah, pO, pm, pl);
        attn_combine<<<dim3(24, 64), 64>>>(pO, pm, pl, ah);

        // ---- O projection (split-K=2) + LN ----
        cudaStreamWaitEvent(0, evO[l], 0);
        gemm_mma<3><<<dim3(DD/128, SS/128, 2), 256, GEMM_SMEM>>>(
            ah, wo[l], bo + l*DD, a, a2, nullptr, SS, DD, DD, 0);
        add_ln3<<<SS, 256>>>(h, a, a2, ln1_w + l*DD, ln1_b + l*DD, ah);

        // ---- FFN ----
        cudaStreamWaitEvent(0, ev1[l], 0);
        gemm_mma<3><<<dim3(FFF/128, SS/128, 1), 256, GEMM_SMEM>>>(
            ah, w1[l], b1 + l*FFF, nullptr, nullptr, bh, SS, FFF, DD, 4);
        cudaStreamWaitEvent(0, ev2[l], 0);
        gemm_mma<3><<<dim3(DD/128, SS/128, 2), 256, GEMM_SMEM>>>(
            bh, w2[l], b2 + l*DD, a, a2, nullptr, SS, DD, FFF, 0);
        add_ln3<<<SS, 256>>>(h, a, a2, ln2_w + l*DD, ln2_b + l*DD, ah);
    }

    classifier_kernel<<<1, 256>>>(h, Wc, bc, out);
}

// round 14
// speedup vs baseline: 18.1846x; 1.3429x over previous
#include <cuda_runtime.h>
#include <cuda_fp16.h>
#include <math.h>
#include <stdint.h>

#define SS 4096
#define DD 768
#define HH 12
#define DHH 64
#define NBB 64
#define BSS 64
#define RRR 3
#define FFF 3072
#define CCC 8
#define NQKV 2304
#define MTAIL 128                  // last-rows tile for layer-2 pruned path
#define ROW0 (SS - MTAIL)          // 3968

// ---------------- scratch (device globals; no allocation allowed) -----------
__device__ __align__(16) float g_h  [SS*DD];
__device__ __align__(16) float g_a  [SS*DD];
__device__ __align__(16) float g_a2 [SS*DD];
__device__ __align__(16) __half g_ah[SS*FFF];   // activation hi
__device__ __align__(16) __half g_bh[SS*FFF];   // qkv hi / ffn-hidden hi
// per-layer fp16 weights (hi only)
__device__ __align__(16) __half g_wqkv[2][3*DD*DD];
__device__ __align__(16) __half g_wo  [2][DD*DD];
__device__ __align__(16) __half g_w1  [2][DD*FFF];
__device__ __align__(16) __half g_w2  [2][FFF*DD];
__device__ __align__(16) float  g_bias3[2][NQKV];
// edge-attention partials: 24 (h,e) x 8 chunks x 64 q x 64 d
__device__ __align__(16) float g_pO[24*8*64*64];
__device__ __align__(16) float g_pm[24*8*64];
__device__ __align__(16) float g_pl[24*8*64];

// ---------------- PTX helpers ------------------------------------------------
__device__ __forceinline__ uint32_t smem_addr(const void* p) {
    uint32_t a;
    asm("{ .reg .u64 t; cvta.to.shared.u64 t, %1; cvt.u32.u64 %0, t; }" : "=r"(a) : "l"(p));
    return a;
}
__device__ __forceinline__ void ldsm_x4(uint32_t addr, uint32_t* r) {
    asm volatile("ldmatrix.sync.aligned.m8n8.x4.shared.b16 {%0,%1,%2,%3}, [%4];"
        : "=r"(r[0]), "=r"(r[1]), "=r"(r[2]), "=r"(r[3]) : "r"(addr));
}
__device__ __forceinline__ void ldsm_x4_t(uint32_t addr, uint32_t* r) {
    asm volatile("ldmatrix.sync.aligned.m8n8.x4.trans.shared.b16 {%0,%1,%2,%3}, [%4];"
        : "=r"(r[0]), "=r"(r[1]), "=r"(r[2]), "=r"(r[3]) : "r"(addr));
}
__device__ __forceinline__ void mma_f16(float* c, const uint32_t* a, const uint32_t* b) {
    asm volatile("mma.sync.aligned.m16n8k16.row.col.f32.f16.f16.f32 "
        "{%0,%1,%2,%3}, {%4,%5,%6,%7}, {%8,%9}, {%0,%1,%2,%3};"
        : "+f"(c[0]), "+f"(c[1]), "+f"(c[2]), "+f"(c[3])
        : "r"(a[0]), "r"(a[1]), "r"(a[2]), "r"(a[3]), "r"(b[0]), "r"(b[1]));
}
__device__ __forceinline__ void mma4(float* c, const uint32_t* a, uint32_t b0, uint32_t b1) {
    uint32_t b[2] = {b0, b1};
    mma_f16(c, a, b);
}
#define CP_ASYNC(dst, src) asm volatile("cp.async.cg.shared.global [%0], [%1], 16;" :: "r"(dst), "l"(src))
#define CP_COMMIT()        asm volatile("cp.async.commit_group;")
#define CP_WAIT(n)         asm volatile("cp.async.wait_group %0;" :: "n"(n))

__device__ __forceinline__ uint32_t pack_h2(__half a, __half b) {
    __half2 t; t.x = a; t.y = b;
    return *(uint32_t*)&t;
}

// ---------------- fp16 1-pass GEMM via mma.sync -------------------------------
// C = Ah * Bh^T + bias (fp32 accum). 2 tiles/stage, NS-stage cp.async pipeline.
// Split-K via blockIdx.z: z=0 -> C (+bias), z=1 -> C2 (no bias).
// modes: 0 fp32 out, 4 gelu + fp16 hi, 5 fp16 hi (no gelu)
#define GEMM_SMEM 98304

template<int NS>
__global__ void __launch_bounds__(256, 2)
gemm_mma(const __half* __restrict__ Ah, const __half* __restrict__ Bh,
         const float* __restrict__ bias, float* __restrict__ C, float* __restrict__ C2,
         __half* __restrict__ Oh,
         int M, int N, int K, int mode)
{
    constexpr int STAGE = 2 * 16384;
    extern __shared__ __align__(128) char smem[];
    uint32_t sb = smem_addr(smem);
    int tid = threadIdx.x, lane = tid & 31, wid = tid >> 5;
    int wm = wid & 1, wn = wid >> 1;
    int n0 = blockIdx.x * 128, m0 = blockIdx.y * 128;
    int kz = blockIdx.z, nz = gridDim.z;
    const int KT = (K >> 6) / nz;
    const int kbase = kz * KT;
    float* Cout = (kz == 0) ? C : C2;
    float bsc = (kz == 0) ? 1.f : 0.f;

    const __half* srcA = Ah + (size_t)m0 * K;
    const __half* srcB = Bh + (size_t)n0 * K;

    float acc[4][4][4];
#pragma unroll
    for (int i = 0; i < 4; i++)
#pragma unroll
        for (int j = 0; j < 4; j++)
#pragma unroll
            for (int u = 0; u < 4; u++) acc[i][j][u] = 0.f;

    auto load_stage = [&](int S, int ktIdx) {
        uint32_t sbase = sb + S * STAGE;
        int ko = (kbase + ktIdx) * 64;
#pragma unroll
        for (int t = 0; t < 2; t++) {
            const __half* sp = t ? srcB : srcA;
#pragma unroll
            for (int i = 0; i < 4; i++) {
                int id = tid + i * 256;
                int row = id >> 3, c = id & 7;
                const __half* src = sp + (size_t)row * K + ko + c * 8;
                uint32_t dst = sbase + t * 16384 + row * 128 + ((c ^ (row & 7)) << 4);
                CP_ASYNC(dst, src);
            }
        }
        CP_COMMIT();
    };

#pragma unroll
    for (int s = 0; s < NS - 1; s++)
        if (s < KT) load_stage(s, s);

    for (int kt = 0; kt < KT; kt++) {
        if (kt + NS - 1 < KT) { load_stage((kt + NS - 1) % NS, kt + NS - 1); CP_WAIT(NS - 1); }
        else                  { CP_WAIT(0); }
        __syncthreads();
        uint32_t st = sb + (kt % NS) * STAGE;
#pragma unroll
        for (int ks = 0; ks < 4; ks++) {
            uint32_t ahf[4][4], bhf[2][4];
#pragma unroll
            for (int mt = 0; mt < 4; mt++) {
                int row = wm * 64 + mt * 16 + (lane & 15);
                int kc = ks * 2 + (lane >> 4);
                uint32_t off = row * 128 + ((kc ^ (row & 7)) << 4);
                ldsm_x4(st + off, ahf[mt]);
            }
#pragma unroll
            for (int np = 0; np < 2; np++) {
                int row = wn * 32 + np * 16 + ((lane & 7) | ((lane & 16) >> 1));
                int kc = ks * 2 + ((lane >> 3) & 1);
                uint32_t off = row * 128 + ((kc ^ (row & 7)) << 4);
                ldsm_x4(st + 16384 + off, bhf[np]);
            }
#pragma unroll
            for (int mt = 0; mt < 4; mt++)
#pragma unroll
                for (int nt = 0; nt < 4; nt++)
                    mma_f16(acc[mt][nt], ahf[mt], &bhf[nt >> 1][(nt & 1) * 2]);
        }
        __syncthreads();
    }

#pragma unroll
    for (int mt = 0; mt < 4; mt++) {
        int mbase = m0 + wm * 64 + mt * 16 + (lane >> 2);
#pragma unroll
        for (int nt = 0; nt < 4; nt++) {
            int n = n0 + wn * 32 + nt * 8 + (lane & 3) * 2;
            float b0 = bias[n] * bsc, b1 = bias[n + 1] * bsc;
#pragma unroll
            for (int half = 0; half < 2; half++) {
                int m = mbase + half * 8;
                float v0 = acc[mt][nt][half * 2 + 0] + b0;
                float v1 = acc[mt][nt][half * 2 + 1] + b1;
                if (mode == 4) {
                    float u0 = 0.7978845608028654f * (v0 + 0.044715f * v0 * v0 * v0);
                    v0 = 0.5f * v0 * (1.f + tanhf(u0));
                    float u1 = 0.7978845608028654f * (v1 + 0.044715f * v1 * v1 * v1);
                    v1 = 0.5f * v1 * (1.f + tanhf(u1));
                }
                if (mode >= 4) {
                    *(uint32_t*)(Oh + (size_t)m * N + n) = pack_h2(__float2half_rn(v0), __float2half_rn(v1));
                } else {
                    float2 o; o.x = v0; o.y = v1;
                    *(float2*)(Cout + (size_t)m * N + n) = o;
                }
            }
        }
    }
}

// ---------------- W[K,N] fp32 -> Wt[N,K] fp16 hi ------------------------------
__global__ __launch_bounds__(256) void conv_wt(const float* __restrict__ W,
    __half* __restrict__ th, int K, int N)
{
    __shared__ float tile[32][33];
    int k0 = blockIdx.y * 32, n0 = blockIdx.x * 32;
    int tx = threadIdx.x & 31, ty = threadIdx.x >> 5;
#pragma unroll
    for (int r = ty; r < 32; r += 8)
        tile[r][tx] = W[(size_t)(k0 + r) * N + n0 + tx];
    __syncthreads();
#pragma unroll
    for (int r = ty; r < 32; r += 8) {
        float v = tile[tx][r];
        th[(size_t)(n0 + r) * K + k0 + tx] = __float2half_rn(v);
    }
}

__global__ __launch_bounds__(256) void concat3(const float* __restrict__ a,
    const float* __restrict__ b, const float* __restrict__ c, float* __restrict__ o)
{
    int i = blockIdx.x * 256 + threadIdx.x;
    if (i < DD) { o[i] = a[i]; o[DD + i] = b[i]; o[2 * DD + i] = c[i]; }
}

// ---------------- reductions -------------------------------------------------
__device__ __forceinline__ void block_reduce2(float &s1v, float &s2v) {
    __shared__ float sa[8], sb2[8];
    int lane = threadIdx.x & 31, w = threadIdx.x >> 5;
#pragma unroll
    for (int off = 16; off; off >>= 1) {
        s1v += __shfl_xor_sync(0xffffffffu, s1v, off);
        s2v += __shfl_xor_sync(0xffffffffu, s2v, off);
    }
    if (lane == 0) { sa[w] = s1v; sb2[w] = s2v; }
    __syncthreads();
    if (w == 0) {
        s1v = (lane < 8) ? sa[lane] : 0.f;
        s2v = (lane < 8) ? sb2[lane] : 0.f;
#pragma unroll
        for (int off = 4; off; off >>= 1) {
            s1v += __shfl_xor_sync(0xffffffffu, s1v, off);
            s2v += __shfl_xor_sync(0xffffffffu, s2v, off);
        }
        if (lane == 0) { sa[0] = s1v; sb2[0] = s2v; }
    }
    __syncthreads();
    s1v = sa[0]; s2v = sb2[0];
}

// ---------------- embedding + LN (hi out) -------------------------------------
__global__ __launch_bounds__(256) void embed_ln_split(
    const int* __restrict__ ids, const float* __restrict__ we,
    const float* __restrict__ pe, const float* __restrict__ w,
    const float* __restrict__ b, float* __restrict__ out,
    __half* __restrict__ oh)
{
    int row = blockIdx.x;
    int id = ids[row];
    float x[3], sum = 0.f, sq = 0.f;
#pragma unroll
    for (int r = 0; r < 3; r++) {
        int i = threadIdx.x + r * 256;
        x[r] = we[(long long)id * DD + i] + pe[row * DD + i];
        sum += x[r]; sq += x[r] * x[r];
    }
    block_reduce2(sum, sq);
    float mean = sum * (1.f / DD);
    float var  = sq * (1.f / DD) - mean * mean;
    float inv  = rsqrtf(var + 1e-12f);
#pragma unroll
    for (int r = 0; r < 3; r++) {
        int i = threadIdx.x + r * 256;
        float y = (x[r] - mean) * inv * w[i] + b[i];
        out[row * DD + i] = y;
        oh[row * DD + i] = __float2half_rn(y);
    }
}

// ---------------- residual (h + a + a2) + LN (hi out) -------------------------
__global__ __launch_bounds__(256) void add_ln3(
    float* __restrict__ h, const float* __restrict__ a, const float* __restrict__ a2,
    const float* __restrict__ w, const float* __restrict__ b,
    __half* __restrict__ oh)
{
    int row = blockIdx.x;
    float x[3], sum = 0.f, sq = 0.f;
#pragma unroll
    for (int r = 0; r < 3; r++) {
        int i = threadIdx.x + r * 256;
        x[r] = h[row * DD + i] + a[row * DD + i] + a2[row * DD + i];
        sum += x[r]; sq += x[r] * x[r];
    }
    block_reduce2(sum, sq);
    float mean = sum * (1.f / DD);
    float var  = sq * (1.f / DD) - mean * mean;
    float inv  = rsqrtf(var + 1e-12f);
#pragma unroll
    for (int r = 0; r < 3; r++) {
        int i = threadIdx.x + r * 256;
        float y = (x[r] - mean) * inv * w[i] + b[i];
        h[row * DD + i] = y;
        oh[row * DD + i] = __float2half_rn(y);
    }
}

// ---------------- MMA flash attention (fp16, 1-pass) ---------------------------
// sh: fp16 QKV [S][NQKV]; Q at col h*64, K at DD+h*64, V at 2*DD+h*64.
// S = Qh*Kh; O = Ph*Vh. Output: hi only into th.
// y index (after +ybase): y<62 -> mid q-block y+1; y>=62 -> edge t=y-62: e=t>>3, z=t&7.
#define AS_Q 0
#define AS_KV 8192
#define KV_STAGE 16384
#define ATTN_SMEM (8192 + 2 * KV_STAGE)

__global__ void __launch_bounds__(128)
attn_mma_kernel(const __half* __restrict__ sh, const int* __restrict__ rnd,
                __half* __restrict__ th,
                float* __restrict__ pO, float* __restrict__ pm, float* __restrict__ pl,
                int ybase)
{
    extern __shared__ __align__(128) char smem[];
    uint32_t sb = smem_addr(smem);
    int h = blockIdx.x, y = blockIdx.y + ybase;
    int tid = threadIdx.x, lane = tid & 31, w = tid >> 5;

    int qb, e = 0, z = 0;
    bool edge;
    if (y < 62) { qb = y + 1; edge = false; }
    else        { int t = y - 62; e = t >> 3; z = t & 7; qb = e ? (NBB - 1) : 0; edge = true; }

    int blks[8];
    if (edge) {
#pragma unroll
        for (int i = 0; i < 8; i++) blks[i] = z * 8 + i;
    } else {
        blks[0] = 0; blks[1] = NBB - 1; blks[2] = qb - 1; blks[3] = qb; blks[4] = qb + 1;
        const int* rp = rnd + (h * NBB + qb) * RRR;
        blks[5] = rp[0]; blks[6] = rp[1]; blks[7] = rp[2];
    }

    // ---- Q tile (hi) ----
    {
        int colq = h * DHH;
#pragma unroll
        for (int i = 0; i < 4; i++) {
            int idx = tid + i * 128;
            int row = idx >> 3, cu = idx & 7;
            const __half* src = sh + (size_t)(qb * BSS + row) * NQKV + colq + cu * 8;
            uint32_t dst = sb + AS_Q + row * 128 + ((cu ^ (row & 7)) << 4);
            CP_ASYNC(dst, src);
        }
    }
    // KV stage: t0 = Kh, t1 = Vh (16KB per stage)
#define LOAD_KV(STG, KB) do {                                                   \
    uint32_t base_ = sb + AS_KV + (STG) * KV_STAGE;                             \
    _Pragma("unroll")                                                           \
    for (int i_ = 0; i_ < 8; i_++) {                                            \
        int idx_ = tid + i_ * 128;                                              \
        int t_ = idx_ >> 9, rem_ = idx_ & 511;                                  \
        int row_ = rem_ >> 3, cu_ = rem_ & 7;                                   \
        int col_ = (t_ + 1) * DD + h * DHH + cu_ * 8;                           \
        const __half* src_ = sh + (size_t)((KB) * BSS + row_) * NQKV + col_;    \
        uint32_t dst_ = base_ + t_ * 8192 + row_ * 128 + ((cu_ ^ (row_ & 7)) << 4); \
        CP_ASYNC(dst_, src_);                                                   \
    }                                                                           \
} while (0)

    LOAD_KV(0, blks[0]);
    CP_COMMIT();
    CP_WAIT(0);
    __syncthreads();

    uint32_t qfh[4][4];
#pragma unroll
    for (int ds = 0; ds < 4; ds++) {
        int row = w * 16 + (lane & 15);
        int cu = ds * 2 + (lane >> 4);
        uint32_t off = row * 128 + ((cu ^ (row & 7)) << 4);
        ldsm_x4(sb + AS_Q + off, qfh[ds]);
    }

    float o[8][4];
    float m[2] = {-1e30f, -1e30f}, l[2] = {0.f, 0.f};
#pragma unroll
    for (int j = 0; j < 8; j++)
#pragma unroll
        for (int u = 0; u < 4; u++) o[j][u] = 0.f;

    const float sc = 0.125f;

    for (int b = 0; b < 8; b++) {
        if (b + 1 < 8) { LOAD_KV((b + 1) & 1, blks[b + 1]); CP_COMMIT(); }
        uint32_t st = sb + AS_KV + (b & 1) * KV_STAGE;

        // ---- S = Qh Kh^T ----
        float s[8][4];
#pragma unroll
        for (int j = 0; j < 8; j++)
#pragma unroll
            for (int u = 0; u < 4; u++) s[j][u] = 0.f;
#pragma unroll
        for (int kb = 0; kb < 4; kb++) {
#pragma unroll
            for (int ds = 0; ds < 4; ds++) {
                int row = kb * 16 + (lane & 15);
                int cu = ds * 2 + (lane >> 4);
                uint32_t off = st + row * 128 + ((cu ^ (row & 7)) << 4);
                uint32_t kh4[4];
                ldsm_x4(off, kh4);
                mma4(s[2 * kb],     qfh[ds], kh4[0], kh4[2]);
                mma4(s[2 * kb + 1], qfh[ds], kh4[1], kh4[3]);
            }
        }

        // ---- online softmax ----
#pragma unroll
        for (int hf = 0; hf < 2; hf++) {
            float rm = -1e30f;
#pragma unroll
            for (int j = 0; j < 8; j++)
                rm = fmaxf(rm, fmaxf(s[j][hf * 2], s[j][hf * 2 + 1]));
            rm *= sc;
            rm = fmaxf(rm, __shfl_xor_sync(0xffffffffu, rm, 1));
            rm = fmaxf(rm, __shfl_xor_sync(0xffffffffu, rm, 2));
            float mn = fmaxf(m[hf], rm);
            float corr = __expf(m[hf] - mn);
            m[hf] = mn;
            float rs = 0.f;
#pragma unroll
            for (int j = 0; j < 8; j++) {
                s[j][hf * 2]     = __expf(s[j][hf * 2]     * sc - mn);
                s[j][hf * 2 + 1] = __expf(s[j][hf * 2 + 1] * sc - mn);
                rs += s[j][hf * 2] + s[j][hf * 2 + 1];
            }
            rs += __shfl_xor_sync(0xffffffffu, rs, 1);
            rs += __shfl_xor_sync(0xffffffffu, rs, 2);
            l[hf] = l[hf] * corr + rs;
#pragma unroll
            for (int j = 0; j < 8; j++) {
                o[j][hf * 2]     *= corr;
                o[j][hf * 2 + 1] *= corr;
            }
        }

        // ---- O += Ph Vh ----
#pragma unroll
        for (int ks = 0; ks < 4; ks++) {
            uint32_t ph4[4];
            ph4[0] = pack_h2(__float2half_rn(s[2 * ks][0]),     __float2half_rn(s[2 * ks][1]));
            ph4[1] = pack_h2(__float2half_rn(s[2 * ks][2]),     __float2half_rn(s[2 * ks][3]));
            ph4[2] = pack_h2(__float2half_rn(s[2 * ks + 1][0]), __float2half_rn(s[2 * ks + 1][1]));
            ph4[3] = pack_h2(__float2half_rn(s[2 * ks + 1][2]), __float2half_rn(s[2 * ks + 1][3]));
#pragma unroll
            for (int dc = 0; dc < 4; dc++) {
                int row = ks * 16 + (lane & 15);
                int cu = dc * 2 + (lane >> 4);
                uint32_t off = st + 8192 + row * 128 + ((cu ^ (row & 7)) << 4);
                uint32_t vh4[4];
                ldsm_x4_t(off, vh4);
                mma4(o[2 * dc],     ph4, vh4[0], vh4[1]);
                mma4(o[2 * dc + 1], ph4, vh4[2], vh4[3]);
            }
        }

        if (b + 1 < 8) { CP_WAIT(0); __syncthreads(); }
    }

    int g = lane >> 2;
    if (!edge) {
#pragma unroll
        for (int hf = 0; hf < 2; hf++) {
            float inv = 1.f / l[hf];
            int row = qb * BSS + w * 16 + g + hf * 8;
#pragma unroll
            for (int j = 0; j < 8; j++) {
                int col = h * DHH + j * 8 + (lane & 3) * 2;
                *(uint32_t*)(th + (size_t)row * DD + col) =
                    pack_h2(__float2half_rn(o[j][hf * 2] * inv),
                            __float2half_rn(o[j][hf * 2 + 1] * inv));
            }
        }
    } else {
        int cb = (h * 2 + e) * 8 + z;
        float* po = pO + (size_t)cb * 64 * 64;
#pragma unroll
        for (int hf = 0; hf < 2; hf++) {
            int qr = w * 16 + g + hf * 8;
#pragma unroll
            for (int j = 0; j < 8; j++) {
                float2 val; val.x = o[j][hf * 2]; val.y = o[j][hf * 2 + 1];
                *(float2*)(po + qr * 64 + j * 8 + (lane & 3) * 2) = val;
            }
            if ((lane & 3) == 0) {
                pm[cb * 64 + qr] = m[hf];
                pl[cb * 64 + qr] = l[hf];
            }
        }
    }
}

// combine edge partials: grid (nhe, 64), 64 threads (d); he = x*hestep + heoff
__global__ void __launch_bounds__(64)
attn_combine(const float* __restrict__ pO, const float* __restrict__ pm,
             const float* __restrict__ pl, __half* __restrict__ th,
             int hestep, int heoff)
{
    int he = blockIdx.x * hestep + heoff, q = blockIdx.y, d = threadIdx.x;
    int h = he >> 1, e = he & 1;
    float mv[8], M = -1e30f;
#pragma unroll
    for (int z = 0; z < 8; z++) {
        mv[z] = pm[(he * 8 + z) * 64 + q];
        M = fmaxf(M, mv[z]);
    }
    float L = 0.f, O = 0.f;
#pragma unroll
    for (int z = 0; z < 8; z++) {
        float w = __expf(mv[z] - M);
        L += w * pl[(he * 8 + z) * 64 + q];
        O += w * pO[((size_t)(he * 8 + z) * 64 + q) * 64 + d];
    }
    float r = O / L;
    int row = (e ? (NBB - 1) : 0) * BSS + q;
    th[row * DD + h * DHH + d] = __float2half_rn(r);
}

// ---------------- classifier --------------------------------------------------
__global__ __launch_bounds__(256) void classifier_kernel(
    const float* __restrict__ h, const float* __restrict__ Wc,
    const float* __restrict__ bc, float* __restrict__ out)
{
    int warp = threadIdx.x >> 5, lane = threadIdx.x & 31;
    if (warp >= CCC) return;
    const float* hr = h + (long long)(SS - 1) * DD;
    float s = 0.f;
    for (int d = lane; d < DD; d += 32) s += hr[d] * Wc[d * CCC + warp];
#pragma unroll
    for (int off = 16; off; off >>= 1) s += __shfl_xor_sync(0xffffffffu, s, off);
    if (lane == 0) out[warp] = s + bc[warp];
}

// ---------------- launch ------------------------------------------------------
extern "C" void kernel_launch(void* const* d_in, const int* in_sizes, int n_in,
                              void* d_out, int out_size)
{
    (void)in_sizes; (void)n_in; (void)out_size;
    const int*   input_ids = (const int*)  d_in[0];
    const int*   rand_attn = (const int*)  d_in[1];
    const float* word_emb  = (const float*)d_in[2];
    const float* pos_emb   = (const float*)d_in[3];
    const float* eln_w     = (const float*)d_in[4];
    const float* eln_b     = (const float*)d_in[5];
    const float* Wq        = (const float*)d_in[6];
    const float* bq        = (const float*)d_in[7];
    const float* Wk        = (const float*)d_in[8];
    const float* bk        = (const float*)d_in[9];
    const float* Wv        = (const float*)d_in[10];
    const float* bv        = (const float*)d_in[11];
    const float* Wo        = (const float*)d_in[12];
    const float* bo        = (const float*)d_in[13];
    const float* ln1_w     = (const float*)d_in[14];
    const float* ln1_b     = (const float*)d_in[15];
    const float* W1        = (const float*)d_in[16];
    const float* b1        = (const float*)d_in[17];
    const float* W2        = (const float*)d_in[18];
    const float* b2        = (const float*)d_in[19];
    const float* ln2_w     = (const float*)d_in[20];
    const float* ln2_b     = (const float*)d_in[21];
    const float* Wc        = (const float*)d_in[22];
    const float* bc        = (const float*)d_in[23];
    float* out = (float*)d_out;

    cudaFuncSetAttribute(gemm_mma<3>, cudaFuncAttributeMaxDynamicSharedMemorySize, GEMM_SMEM);
    cudaFuncSetAttribute(attn_mma_kernel, cudaFuncAttributeMaxDynamicSharedMemorySize, ATTN_SMEM);

    float *h, *a, *a2, *pO, *pm, *pl;
    __half *ah, *bh;
    __half *wqkv[2], *wo[2], *w1[2], *w2[2];
    float  *bias3[2];
    cudaGetSymbolAddress((void**)&h,  g_h);
    cudaGetSymbolAddress((void**)&a,  g_a);
    cudaGetSymbolAddress((void**)&a2, g_a2);
    cudaGetSymbolAddress((void**)&ah, g_ah);
    cudaGetSymbolAddress((void**)&bh, g_bh);
    cudaGetSymbolAddress((void**)&pO, g_pO);
    cudaGetSymbolAddress((void**)&pm, g_pm);
    cudaGetSymbolAddress((void**)&pl, g_pl);
    {
        __half *p0, *p1, *p2, *p3; float* p4;
        cudaGetSymbolAddress((void**)&p0, g_wqkv);
        cudaGetSymbolAddress((void**)&p1, g_wo);
        cudaGetSymbolAddress((void**)&p2, g_w1);
        cudaGetSymbolAddress((void**)&p3, g_w2);
        cudaGetSymbolAddress((void**)&p4, g_bias3);
        for (int l = 0; l < 2; l++) {
            wqkv[l] = p0 + (size_t)l * 3 * DD * DD;
            wo[l]   = p1 + (size_t)l * DD * DD;
            w1[l]   = p2 + (size_t)l * DD * FFF;
            w2[l]   = p3 + (size_t)l * FFF * DD;
            bias3[l] = p4 + (size_t)l * NQKV;
        }
    }

    // ---- side stream for weight conversion (event-linked for graph capture) --
    static cudaStream_t s2 = nullptr;
    static cudaEvent_t evF, evQ[2], evO[2], ev1[2], ev2[2];
    if (!s2) {
        cudaStreamCreateWithFlags(&s2, cudaStreamNonBlocking);
        cudaEventCreateWithFlags(&evF, cudaEventDisableTiming);
        for (int l = 0; l < 2; l++) {
            cudaEventCreateWithFlags(&evQ[l], cudaEventDisableTiming);
            cudaEventCreateWithFlags(&evO[l], cudaEventDisableTiming);
            cudaEventCreateWithFlags(&ev1[l], cudaEventDisableTiming);
            cudaEventCreateWithFlags(&ev2[l], cudaEventDisableTiming);
        }
    }

    cudaEventRecord(evF, 0);
    cudaStreamWaitEvent(s2, evF, 0);
    for (int l = 0; l < 2; l++) {
        long long wofs = (long long)l * DD * DD;
        conv_wt<<<dim3(DD/32, DD/32), 256, 0, s2>>>(Wq + wofs, wqkv[l],            DD, DD);
        conv_wt<<<dim3(DD/32, DD/32), 256, 0, s2>>>(Wk + wofs, wqkv[l] + DD*DD,    DD, DD);
        conv_wt<<<dim3(DD/32, DD/32), 256, 0, s2>>>(Wv + wofs, wqkv[l] + 2*DD*DD,  DD, DD);
        concat3<<<3, 256, 0, s2>>>(bq + l*DD, bk + l*DD, bv + l*DD, bias3[l]);
        cudaEventRecord(evQ[l], s2);
        conv_wt<<<dim3(DD/32, DD/32), 256, 0, s2>>>(Wo + wofs, wo[l], DD, DD);
        cudaEventRecord(evO[l], s2);
        conv_wt<<<dim3(FFF/32, DD/32), 256, 0, s2>>>(W1 + (long long)l*DD*FFF, w1[l], DD, FFF);
        cudaEventRecord(ev1[l], s2);
        conv_wt<<<dim3(DD/32, FFF/32), 256, 0, s2>>>(W2 + (long long)l*FFF*DD, w2[l], FFF, DD);
        cudaEventRecord(ev2[l], s2);
    }

    embed_ln_split<<<SS, 256>>>(input_ids, word_emb, pos_emb, eln_w, eln_b, h, ah);

    // =========================== layer 0 (full) ===========================
    {
        int l = 0;
        cudaStreamWaitEvent(0, evQ[l], 0);
        gemm_mma<3><<<dim3(NQKV/128, SS/128, 1), 256, GEMM_SMEM>>>(
            ah, wqkv[l], bias3[l], nullptr, nullptr, bh, SS, NQKV, DD, 5);

        attn_mma_kernel<<<dim3(HH, 78), 128, ATTN_SMEM>>>(
            bh, rand_attn + l*HH*NBB*RRR, ah, pO, pm, pl, 0);
        attn_combine<<<dim3(24, 64), 64>>>(pO, pm, pl, ah, 1, 0);

        cudaStreamWaitEvent(0, evO[l], 0);
        gemm_mma<3><<<dim3(DD/128, SS/128, 2), 256, GEMM_SMEM>>>(
            ah, wo[l], bo + l*DD, a, a2, nullptr, SS, DD, DD, 0);
        add_ln3<<<SS, 256>>>(h, a, a2, ln1_w + l*DD, ln1_b + l*DD, ah);

        cudaStreamWaitEvent(0, ev1[l], 0);
        gemm_mma<3><<<dim3(FFF/128, SS/128, 1), 256, GEMM_SMEM>>>(
            ah, w1[l], b1 + l*FFF, nullptr, nullptr, bh, SS, FFF, DD, 4);
        cudaStreamWaitEvent(0, ev2[l], 0);
        gemm_mma<3><<<dim3(DD/128, SS/128, 2), 256, GEMM_SMEM>>>(
            bh, w2[l], b2 + l*DD, a, a2, nullptr, SS, DD, FFF, 0);
        add_ln3<<<SS, 256>>>(h, a, a2, ln2_w + l*DD, ln2_b + l*DD, ah);
    }

    // ================= layer 1 (pruned: only last row matters) =============
    {
        int l = 1;
        const size_t ro768  = (size_t)ROW0 * DD;    // offset into [S][768] arrays
        const size_t ro3072 = (size_t)ROW0 * FFF;   // offset into [S][3072] arrays

        // QKV: full (K/V of all rows feed edge-block attention)
        cudaStreamWaitEvent(0, evQ[l], 0);
        gemm_mma<3><<<dim3(NQKV/128, SS/128, 1), 256, GEMM_SMEM>>>(
            ah, wqkv[l], bias3[l], nullptr, nullptr, bh, SS, NQKV, DD, 5);

        // attention: only edge e=1 (q-block 63) chunks -> y = 70..77
        attn_mma_kernel<<<dim3(HH, 8), 128, ATTN_SMEM>>>(
            bh, rand_attn + l*HH*NBB*RRR, ah, pO, pm, pl, 70);
        attn_combine<<<dim3(12, 64), 64>>>(pO, pm, pl, ah, 2, 1);

        // Wo: last 128 rows only
        cudaStreamWaitEvent(0, evO[l], 0);
        gemm_mma<3><<<dim3(DD/128, 1, 2), 256, GEMM_SMEM>>>(
            ah + ro768, wo[l], bo + l*DD, a + ro768, a2 + ro768, nullptr,
            MTAIL, DD, DD, 0);
        add_ln3<<<MTAIL, 256>>>(h + ro768, a + ro768, a2 + ro768,
                                ln1_w + l*DD, ln1_b + l*DD, ah + ro768);

        // FFN: last 128 rows only
        cudaStreamWaitEvent(0, ev1[l], 0);
        gemm_mma<3><<<dim3(FFF/128, 1, 1), 256, GEMM_SMEM>>>(
            ah + ro768, w1[l], b1 + l*FFF, nullptr, nullptr, bh + ro3072,
            MTAIL, FFF, DD, 4);
        cudaStreamWaitEvent(0, ev2[l], 0);
        gemm_mma<3><<<dim3(DD/128, 1, 2), 256, GEMM_SMEM>>>(
            bh + ro3072, w2[l], b2 + l*DD, a + ro768, a2 + ro768, nullptr,
            MTAIL, DD, FFF, 0);
        add_ln3<<<MTAIL, 256>>>(h + ro768, a + ro768, a2 + ro768,
                                ln2_w + l*DD, ln2_b + l*DD, ah + ro768);
    }

    classifier_kernel<<<1, 256>>>(h, Wc, bc, out);
}

// round 15
// speedup vs baseline: 18.5206x; 1.0185x over previous
#include <cuda_runtime.h>
#include <cuda_fp16.h>
#include <math.h>
#include <stdint.h>

#define SS 4096
#define DD 768
#define HH 12
#define DHH 64
#define NBB 64
#define BSS 64
#define RRR 3
#define FFF 3072
#define CCC 8
#define NQKV 2304
#define MTAIL 128                  // last-rows tile for layer-2 pruned path
#define ROW0 (SS - MTAIL)          // 3968

// ---------------- scratch (device globals; no allocation allowed) -----------
__device__ __align__(16) float g_h  [SS*DD];
__device__ __align__(16) float g_a  [SS*DD];
__device__ __align__(16) float g_a2 [SS*DD];
__device__ __align__(16) __half g_ah[SS*FFF];   // activation hi
__device__ __align__(16) __half g_bh[SS*FFF];   // qkv hi / ffn-hidden hi
// per-layer fp16 weights (hi only)
__device__ __align__(16) __half g_wqkv[2][3*DD*DD];
__device__ __align__(16) __half g_wo  [2][DD*DD];
__device__ __align__(16) __half g_w1  [2][DD*FFF];
__device__ __align__(16) __half g_w2  [2][FFF*DD];
__device__ __align__(16) float  g_bias3[2][NQKV];
// edge-attention partials: 24 (h,e) x 8 chunks x 64 q x 64 d
__device__ __align__(16) float g_pO[24*8*64*64];
__device__ __align__(16) float g_pm[24*8*64];
__device__ __align__(16) float g_pl[24*8*64];

// ---------------- PTX helpers ------------------------------------------------
__device__ __forceinline__ uint32_t smem_addr(const void* p) {
    uint32_t a;
    asm("{ .reg .u64 t; cvta.to.shared.u64 t, %1; cvt.u32.u64 %0, t; }" : "=r"(a) : "l"(p));
    return a;
}
__device__ __forceinline__ void ldsm_x4(uint32_t addr, uint32_t* r) {
    asm volatile("ldmatrix.sync.aligned.m8n8.x4.shared.b16 {%0,%1,%2,%3}, [%4];"
        : "=r"(r[0]), "=r"(r[1]), "=r"(r[2]), "=r"(r[3]) : "r"(addr));
}
__device__ __forceinline__ void ldsm_x4_t(uint32_t addr, uint32_t* r) {
    asm volatile("ldmatrix.sync.aligned.m8n8.x4.trans.shared.b16 {%0,%1,%2,%3}, [%4];"
        : "=r"(r[0]), "=r"(r[1]), "=r"(r[2]), "=r"(r[3]) : "r"(addr));
}
__device__ __forceinline__ void mma_f16(float* c, const uint32_t* a, const uint32_t* b) {
    asm volatile("mma.sync.aligned.m16n8k16.row.col.f32.f16.f16.f32 "
        "{%0,%1,%2,%3}, {%4,%5,%6,%7}, {%8,%9}, {%0,%1,%2,%3};"
        : "+f"(c[0]), "+f"(c[1]), "+f"(c[2]), "+f"(c[3])
        : "r"(a[0]), "r"(a[1]), "r"(a[2]), "r"(a[3]), "r"(b[0]), "r"(b[1]));
}
__device__ __forceinline__ void mma4(float* c, const uint32_t* a, uint32_t b0, uint32_t b1) {
    uint32_t b[2] = {b0, b1};
    mma_f16(c, a, b);
}
#define CP_ASYNC(dst, src) asm volatile("cp.async.cg.shared.global [%0], [%1], 16;" :: "r"(dst), "l"(src))
#define CP_COMMIT()        asm volatile("cp.async.commit_group;")
#define CP_WAIT(n)         asm volatile("cp.async.wait_group %0;" :: "n"(n))

__device__ __forceinline__ uint32_t pack_h2(__half a, __half b) {
    __half2 t; t.x = a; t.y = b;
    return *(uint32_t*)&t;
}

// ---------------- fp16 1-pass GEMM via mma.sync -------------------------------
// C = Ah * Bh^T + bias (fp32 accum). 2 tiles/stage, NS-stage cp.async pipeline.
// Split-K via blockIdx.z: z=0 -> C (+bias), z=1 -> C2 (no bias).
// ldo: output row stride (may exceed N for strided column writes).
// modes: 0 fp32 out, 4 gelu + fp16 hi, 5 fp16 hi (no gelu)
#define GEMM_SMEM 98304

template<int NS>
__global__ void __launch_bounds__(256, 2)
gemm_mma(const __half* __restrict__ Ah, const __half* __restrict__ Bh,
         const float* __restrict__ bias, float* __restrict__ C, float* __restrict__ C2,
         __half* __restrict__ Oh,
         int M, int N, int K, int ldo, int mode)
{
    constexpr int STAGE = 2 * 16384;
    extern __shared__ __align__(128) char smem[];
    uint32_t sb = smem_addr(smem);
    int tid = threadIdx.x, lane = tid & 31, wid = tid >> 5;
    int wm = wid & 1, wn = wid >> 1;
    int n0 = blockIdx.x * 128, m0 = blockIdx.y * 128;
    int kz = blockIdx.z, nz = gridDim.z;
    const int KT = (K >> 6) / nz;
    const int kbase = kz * KT;
    float* Cout = (kz == 0) ? C : C2;
    float bsc = (kz == 0) ? 1.f : 0.f;

    const __half* srcA = Ah + (size_t)m0 * K;
    const __half* srcB = Bh + (size_t)n0 * K;

    float acc[4][4][4];
#pragma unroll
    for (int i = 0; i < 4; i++)
#pragma unroll
        for (int j = 0; j < 4; j++)
#pragma unroll
            for (int u = 0; u < 4; u++) acc[i][j][u] = 0.f;

    auto load_stage = [&](int S, int ktIdx) {
        uint32_t sbase = sb + S * STAGE;
        int ko = (kbase + ktIdx) * 64;
#pragma unroll
        for (int t = 0; t < 2; t++) {
            const __half* sp = t ? srcB : srcA;
#pragma unroll
            for (int i = 0; i < 4; i++) {
                int id = tid + i * 256;
                int row = id >> 3, c = id & 7;
                const __half* src = sp + (size_t)row * K + ko + c * 8;
                uint32_t dst = sbase + t * 16384 + row * 128 + ((c ^ (row & 7)) << 4);
                CP_ASYNC(dst, src);
            }
        }
        CP_COMMIT();
    };

#pragma unroll
    for (int s = 0; s < NS - 1; s++)
        if (s < KT) load_stage(s, s);

    for (int kt = 0; kt < KT; kt++) {
        if (kt + NS - 1 < KT) { load_stage((kt + NS - 1) % NS, kt + NS - 1); CP_WAIT(NS - 1); }
        else                  { CP_WAIT(0); }
        __syncthreads();
        uint32_t st = sb + (kt % NS) * STAGE;
#pragma unroll
        for (int ks = 0; ks < 4; ks++) {
            uint32_t ahf[4][4], bhf[2][4];
#pragma unroll
            for (int mt = 0; mt < 4; mt++) {
                int row = wm * 64 + mt * 16 + (lane & 15);
                int kc = ks * 2 + (lane >> 4);
                uint32_t off = row * 128 + ((kc ^ (row & 7)) << 4);
                ldsm_x4(st + off, ahf[mt]);
            }
#pragma unroll
            for (int np = 0; np < 2; np++) {
                int row = wn * 32 + np * 16 + ((lane & 7) | ((lane & 16) >> 1));
                int kc = ks * 2 + ((lane >> 3) & 1);
                uint32_t off = row * 128 + ((kc ^ (row & 7)) << 4);
                ldsm_x4(st + 16384 + off, bhf[np]);
            }
#pragma unroll
            for (int mt = 0; mt < 4; mt++)
#pragma unroll
                for (int nt = 0; nt < 4; nt++)
                    mma_f16(acc[mt][nt], ahf[mt], &bhf[nt >> 1][(nt & 1) * 2]);
        }
        __syncthreads();
    }

#pragma unroll
    for (int mt = 0; mt < 4; mt++) {
        int mbase = m0 + wm * 64 + mt * 16 + (lane >> 2);
#pragma unroll
        for (int nt = 0; nt < 4; nt++) {
            int n = n0 + wn * 32 + nt * 8 + (lane & 3) * 2;
            float b0 = bias[n] * bsc, b1 = bias[n + 1] * bsc;
#pragma unroll
            for (int half = 0; half < 2; half++) {
                int m = mbase + half * 8;
                float v0 = acc[mt][nt][half * 2 + 0] + b0;
                float v1 = acc[mt][nt][half * 2 + 1] + b1;
                if (mode == 4) {
                    float u0 = 0.7978845608028654f * (v0 + 0.044715f * v0 * v0 * v0);
                    v0 = 0.5f * v0 * (1.f + tanhf(u0));
                    float u1 = 0.7978845608028654f * (v1 + 0.044715f * v1 * v1 * v1);
                    v1 = 0.5f * v1 * (1.f + tanhf(u1));
                }
                if (mode >= 4) {
                    *(uint32_t*)(Oh + (size_t)m * ldo + n) = pack_h2(__float2half_rn(v0), __float2half_rn(v1));
                } else {
                    float2 o; o.x = v0; o.y = v1;
                    *(float2*)(Cout + (size_t)m * ldo + n) = o;
                }
            }
        }
    }
}

// ---------------- W[K,N] fp32 -> Wt[N,K] fp16 hi ------------------------------
__global__ __launch_bounds__(256) void conv_wt(const float* __restrict__ W,
    __half* __restrict__ th, int K, int N)
{
    __shared__ float tile[32][33];
    int k0 = blockIdx.y * 32, n0 = blockIdx.x * 32;
    int tx = threadIdx.x & 31, ty = threadIdx.x >> 5;
#pragma unroll
    for (int r = ty; r < 32; r += 8)
        tile[r][tx] = W[(size_t)(k0 + r) * N + n0 + tx];
    __syncthreads();
#pragma unroll
    for (int r = ty; r < 32; r += 8) {
        float v = tile[tx][r];
        th[(size_t)(n0 + r) * K + k0 + tx] = __float2half_rn(v);
    }
}

__global__ __launch_bounds__(256) void concat3(const float* __restrict__ a,
    const float* __restrict__ b, const float* __restrict__ c, float* __restrict__ o)
{
    int i = blockIdx.x * 256 + threadIdx.x;
    if (i < DD) { o[i] = a[i]; o[DD + i] = b[i]; o[2 * DD + i] = c[i]; }
}

// ---------------- reductions -------------------------------------------------
__device__ __forceinline__ void block_reduce2(float &s1v, float &s2v) {
    __shared__ float sa[8], sb2[8];
    int lane = threadIdx.x & 31, w = threadIdx.x >> 5;
#pragma unroll
    for (int off = 16; off; off >>= 1) {
        s1v += __shfl_xor_sync(0xffffffffu, s1v, off);
        s2v += __shfl_xor_sync(0xffffffffu, s2v, off);
    }
    if (lane == 0) { sa[w] = s1v; sb2[w] = s2v; }
    __syncthreads();
    if (w == 0) {
        s1v = (lane < 8) ? sa[lane] : 0.f;
        s2v = (lane < 8) ? sb2[lane] : 0.f;
#pragma unroll
        for (int off = 4; off; off >>= 1) {
            s1v += __shfl_xor_sync(0xffffffffu, s1v, off);
            s2v += __shfl_xor_sync(0xffffffffu, s2v, off);
        }
        if (lane == 0) { sa[0] = s1v; sb2[0] = s2v; }
    }
    __syncthreads();
    s1v = sa[0]; s2v = sb2[0];
}

// ---------------- embedding + LN (hi out) -------------------------------------
__global__ __launch_bounds__(256) void embed_ln_split(
    const int* __restrict__ ids, const float* __restrict__ we,
    const float* __restrict__ pe, const float* __restrict__ w,
    const float* __restrict__ b, float* __restrict__ out,
    __half* __restrict__ oh)
{
    int row = blockIdx.x;
    int id = ids[row];
    float x[3], sum = 0.f, sq = 0.f;
#pragma unroll
    for (int r = 0; r < 3; r++) {
        int i = threadIdx.x + r * 256;
        x[r] = we[(long long)id * DD + i] + pe[row * DD + i];
        sum += x[r]; sq += x[r] * x[r];
    }
    block_reduce2(sum, sq);
    float mean = sum * (1.f / DD);
    float var  = sq * (1.f / DD) - mean * mean;
    float inv  = rsqrtf(var + 1e-12f);
#pragma unroll
    for (int r = 0; r < 3; r++) {
        int i = threadIdx.x + r * 256;
        float y = (x[r] - mean) * inv * w[i] + b[i];
        out[row * DD + i] = y;
        oh[row * DD + i] = __float2half_rn(y);
    }
}

// ---------------- residual (h + a + a2) + LN (hi out) -------------------------
__global__ __launch_bounds__(256) void add_ln3(
    float* __restrict__ h, const float* __restrict__ a, const float* __restrict__ a2,
    const float* __restrict__ w, const float* __restrict__ b,
    __half* __restrict__ oh)
{
    int row = blockIdx.x;
    float x[3], sum = 0.f, sq = 0.f;
#pragma unroll
    for (int r = 0; r < 3; r++) {
        int i = threadIdx.x + r * 256;
        x[r] = h[row * DD + i] + a[row * DD + i] + a2[row * DD + i];
        sum += x[r]; sq += x[r] * x[r];
    }
    block_reduce2(sum, sq);
    float mean = sum * (1.f / DD);
    float var  = sq * (1.f / DD) - mean * mean;
    float inv  = rsqrtf(var + 1e-12f);
#pragma unroll
    for (int r = 0; r < 3; r++) {
        int i = threadIdx.x + r * 256;
        float y = (x[r] - mean) * inv * w[i] + b[i];
        h[row * DD + i] = y;
        oh[row * DD + i] = __float2half_rn(y);
    }
}

// ---------------- MMA flash attention (fp16, 1-pass) ---------------------------
// sh: fp16 QKV [S][NQKV]; Q at col h*64, K at DD+h*64, V at 2*DD+h*64.
// S = Qh*Kh; O = Ph*Vh. Output: hi only into th.
// y index (after +ybase): y<62 -> mid q-block y+1; y>=62 -> edge t=y-62: e=t>>3, z=t&7.
#define AS_Q 0
#define AS_KV 8192
#define KV_STAGE 16384
#define ATTN_SMEM (8192 + 2 * KV_STAGE)

__global__ void __launch_bounds__(128)
attn_mma_kernel(const __half* __restrict__ sh, const int* __restrict__ rnd,
                __half* __restrict__ th,
                float* __restrict__ pO, float* __restrict__ pm, float* __restrict__ pl,
                int ybase)
{
    extern __shared__ __align__(128) char smem[];
    uint32_t sb = smem_addr(smem);
    int h = blockIdx.x, y = blockIdx.y + ybase;
    int tid = threadIdx.x, lane = tid & 31, w = tid >> 5;

    int qb, e = 0, z = 0;
    bool edge;
    if (y < 62) { qb = y + 1; edge = false; }
    else        { int t = y - 62; e = t >> 3; z = t & 7; qb = e ? (NBB - 1) : 0; edge = true; }

    int blks[8];
    if (edge) {
#pragma unroll
        for (int i = 0; i < 8; i++) blks[i] = z * 8 + i;
    } else {
        blks[0] = 0; blks[1] = NBB - 1; blks[2] = qb - 1; blks[3] = qb; blks[4] = qb + 1;
        const int* rp = rnd + (h * NBB + qb) * RRR;
        blks[5] = rp[0]; blks[6] = rp[1]; blks[7] = rp[2];
    }

    // ---- Q tile (hi) ----
    {
        int colq = h * DHH;
#pragma unroll
        for (int i = 0; i < 4; i++) {
            int idx = tid + i * 128;
            int row = idx >> 3, cu = idx & 7;
            const __half* src = sh + (size_t)(qb * BSS + row) * NQKV + colq + cu * 8;
            uint32_t dst = sb + AS_Q + row * 128 + ((cu ^ (row & 7)) << 4);
            CP_ASYNC(dst, src);
        }
    }
    // KV stage: t0 = Kh, t1 = Vh (16KB per stage)
#define LOAD_KV(STG, KB) do {                                                   \
    uint32_t base_ = sb + AS_KV + (STG) * KV_STAGE;                             \
    _Pragma("unroll")                                                           \
    for (int i_ = 0; i_ < 8; i_++) {                                            \
        int idx_ = tid + i_ * 128;                                              \
        int t_ = idx_ >> 9, rem_ = idx_ & 511;                                  \
        int row_ = rem_ >> 3, cu_ = rem_ & 7;                                   \
        int col_ = (t_ + 1) * DD + h * DHH + cu_ * 8;                           \
        const __half* src_ = sh + (size_t)((KB) * BSS + row_) * NQKV + col_;    \
        uint32_t dst_ = base_ + t_ * 8192 + row_ * 128 + ((cu_ ^ (row_ & 7)) << 4); \
        CP_ASYNC(dst_, src_);                                                   \
    }                                                                           \
} while (0)

    LOAD_KV(0, blks[0]);
    CP_COMMIT();
    CP_WAIT(0);
    __syncthreads();

    uint32_t qfh[4][4];
#pragma unroll
    for (int ds = 0; ds < 4; ds++) {
        int row = w * 16 + (lane & 15);
        int cu = ds * 2 + (lane >> 4);
        uint32_t off = row * 128 + ((cu ^ (row & 7)) << 4);
        ldsm_x4(sb + AS_Q + off, qfh[ds]);
    }

    float o[8][4];
    float m[2] = {-1e30f, -1e30f}, l[2] = {0.f, 0.f};
#pragma unroll
    for (int j = 0; j < 8; j++)
#pragma unroll
        for (int u = 0; u < 4; u++) o[j][u] = 0.f;

    const float sc = 0.125f;

    for (int b = 0; b < 8; b++) {
        if (b + 1 < 8) { LOAD_KV((b + 1) & 1, blks[b + 1]); CP_COMMIT(); }
        uint32_t st = sb + AS_KV + (b & 1) * KV_STAGE;

        // ---- S = Qh Kh^T ----
        float s[8][4];
#pragma unroll
        for (int j = 0; j < 8; j++)
#pragma unroll
            for (int u = 0; u < 4; u++) s[j][u] = 0.f;
#pragma unroll
        for (int kb = 0; kb < 4; kb++) {
#pragma unroll
            for (int ds = 0; ds < 4; ds++) {
                int row = kb * 16 + (lane & 15);
                int cu = ds * 2 + (lane >> 4);
                uint32_t off = st + row * 128 + ((cu ^ (row & 7)) << 4);
                uint32_t kh4[4];
                ldsm_x4(off, kh4);
                mma4(s[2 * kb],     qfh[ds], kh4[0], kh4[2]);
                mma4(s[2 * kb + 1], qfh[ds], kh4[1], kh4[3]);
            }
        }

        // ---- online softmax ----
#pragma unroll
        for (int hf = 0; hf < 2; hf++) {
            float rm = -1e30f;
#pragma unroll
            for (int j = 0; j < 8; j++)
                rm = fmaxf(rm, fmaxf(s[j][hf * 2], s[j][hf * 2 + 1]));
            rm *= sc;
            rm = fmaxf(rm, __shfl_xor_sync(0xffffffffu, rm, 1));
            rm = fmaxf(rm, __shfl_xor_sync(0xffffffffu, rm, 2));
            float mn = fmaxf(m[hf], rm);
            float corr = __expf(m[hf] - mn);
            m[hf] = mn;
            float rs = 0.f;
#pragma unroll
            for (int j = 0; j < 8; j++) {
                s[j][hf * 2]     = __expf(s[j][hf * 2]     * sc - mn);
                s[j][hf * 2 + 1] = __expf(s[j][hf * 2 + 1] * sc - mn);
                rs += s[j][hf * 2] + s[j][hf * 2 + 1];
            }
            rs += __shfl_xor_sync(0xffffffffu, rs, 1);
            rs += __shfl_xor_sync(0xffffffffu, rs, 2);
            l[hf] = l[hf] * corr + rs;
#pragma unroll
            for (int j = 0; j < 8; j++) {
                o[j][hf * 2]     *= corr;
                o[j][hf * 2 + 1] *= corr;
            }
        }

        // ---- O += Ph Vh ----
#pragma unroll
        for (int ks = 0; ks < 4; ks++) {
            uint32_t ph4[4];
            ph4[0] = pack_h2(__float2half_rn(s[2 * ks][0]),     __float2half_rn(s[2 * ks][1]));
            ph4[1] = pack_h2(__float2half_rn(s[2 * ks][2]),     __float2half_rn(s[2 * ks][3]));
            ph4[2] = pack_h2(__float2half_rn(s[2 * ks + 1][0]), __float2half_rn(s[2 * ks + 1][1]));
            ph4[3] = pack_h2(__float2half_rn(s[2 * ks + 1][2]), __float2half_rn(s[2 * ks + 1][3]));
#pragma unroll
            for (int dc = 0; dc < 4; dc++) {
                int row = ks * 16 + (lane & 15);
                int cu = dc * 2 + (lane >> 4);
                uint32_t off = st + 8192 + row * 128 + ((cu ^ (row & 7)) << 4);
                uint32_t vh4[4];
                ldsm_x4_t(off, vh4);
                mma4(o[2 * dc],     ph4, vh4[0], vh4[1]);
                mma4(o[2 * dc + 1], ph4, vh4[2], vh4[3]);
            }
        }

        if (b + 1 < 8) { CP_WAIT(0); __syncthreads(); }
    }

    int g = lane >> 2;
    if (!edge) {
#pragma unroll
        for (int hf = 0; hf < 2; hf++) {
            float inv = 1.f / l[hf];
            int row = qb * BSS + w * 16 + g + hf * 8;
#pragma unroll
            for (int j = 0; j < 8; j++) {
                int col = h * DHH + j * 8 + (lane & 3) * 2;
                *(uint32_t*)(th + (size_t)row * DD + col) =
                    pack_h2(__float2half_rn(o[j][hf * 2] * inv),
                            __float2half_rn(o[j][hf * 2 + 1] * inv));
            }
        }
    } else {
        int cb = (h * 2 + e) * 8 + z;
        float* po = pO + (size_t)cb * 64 * 64;
#pragma unroll
        for (int hf = 0; hf < 2; hf++) {
            int qr = w * 16 + g + hf * 8;
#pragma unroll
            for (int j = 0; j < 8; j++) {
                float2 val; val.x = o[j][hf * 2]; val.y = o[j][hf * 2 + 1];
                *(float2*)(po + qr * 64 + j * 8 + (lane & 3) * 2) = val;
            }
            if ((lane & 3) == 0) {
                pm[cb * 64 + qr] = m[hf];
                pl[cb * 64 + qr] = l[hf];
            }
        }
    }
}

// combine edge partials: grid (nhe, 64), 64 threads (d); he = x*hestep + heoff
__global__ void __launch_bounds__(64)
attn_combine(const float* __restrict__ pO, const float* __restrict__ pm,
             const float* __restrict__ pl, __half* __restrict__ th,
             int hestep, int heoff)
{
    int he = blockIdx.x * hestep + heoff, q = blockIdx.y, d = threadIdx.x;
    int h = he >> 1, e = he & 1;
    float mv[8], M = -1e30f;
#pragma unroll
    for (int z = 0; z < 8; z++) {
        mv[z] = pm[(he * 8 + z) * 64 + q];
        M = fmaxf(M, mv[z]);
    }
    float L = 0.f, O = 0.f;
#pragma unroll
    for (int z = 0; z < 8; z++) {
        float w = __expf(mv[z] - M);
        L += w * pl[(he * 8 + z) * 64 + q];
        O += w * pO[((size_t)(he * 8 + z) * 64 + q) * 64 + d];
    }
    float r = O / L;
    int row = (e ? (NBB - 1) : 0) * BSS + q;
    th[row * DD + h * DHH + d] = __float2half_rn(r);
}

// ---------------- classifier --------------------------------------------------
__global__ __launch_bounds__(256) void classifier_kernel(
    const float* __restrict__ h, const float* __restrict__ Wc,
    const float* __restrict__ bc, float* __restrict__ out)
{
    int warp = threadIdx.x >> 5, lane = threadIdx.x & 31;
    if (warp >= CCC) return;
    const float* hr = h + (long long)(SS - 1) * DD;
    float s = 0.f;
    for (int d = lane; d < DD; d += 32) s += hr[d] * Wc[d * CCC + warp];
#pragma unroll
    for (int off = 16; off; off >>= 1) s += __shfl_xor_sync(0xffffffffu, s, off);
    if (lane == 0) out[warp] = s + bc[warp];
}

// ---------------- launch ------------------------------------------------------
extern "C" void kernel_launch(void* const* d_in, const int* in_sizes, int n_in,
                              void* d_out, int out_size)
{
    (void)in_sizes; (void)n_in; (void)out_size;
    const int*   input_ids = (const int*)  d_in[0];
    const int*   rand_attn = (const int*)  d_in[1];
    const float* word_emb  = (const float*)d_in[2];
    const float* pos_emb   = (const float*)d_in[3];
    const float* eln_w     = (const float*)d_in[4];
    const float* eln_b     = (const float*)d_in[5];
    const float* Wq        = (const float*)d_in[6];
    const float* bq        = (const float*)d_in[7];
    const float* Wk        = (const float*)d_in[8];
    const float* bk        = (const float*)d_in[9];
    const float* Wv        = (const float*)d_in[10];
    const float* bv        = (const float*)d_in[11];
    const float* Wo        = (const float*)d_in[12];
    const float* bo        = (const float*)d_in[13];
    const float* ln1_w     = (const float*)d_in[14];
    const float* ln1_b     = (const float*)d_in[15];
    const float* W1        = (const float*)d_in[16];
    const float* b1        = (const float*)d_in[17];
    const float* W2        = (const float*)d_in[18];
    const float* b2        = (const float*)d_in[19];
    const float* ln2_w     = (const float*)d_in[20];
    const float* ln2_b     = (const float*)d_in[21];
    const float* Wc        = (const float*)d_in[22];
    const float* bc        = (const float*)d_in[23];
    float* out = (float*)d_out;

    cudaFuncSetAttribute(gemm_mma<3>, cudaFuncAttributeMaxDynamicSharedMemorySize, GEMM_SMEM);
    cudaFuncSetAttribute(attn_mma_kernel, cudaFuncAttributeMaxDynamicSharedMemorySize, ATTN_SMEM);

    float *h, *a, *a2, *pO, *pm, *pl;
    __half *ah, *bh;
    __half *wqkv[2], *wo[2], *w1[2], *w2[2];
    float  *bias3[2];
    cudaGetSymbolAddress((void**)&h,  g_h);
    cudaGetSymbolAddress((void**)&a,  g_a);
    cudaGetSymbolAddress((void**)&a2, g_a2);
    cudaGetSymbolAddress((void**)&ah, g_ah);
    cudaGetSymbolAddress((void**)&bh, g_bh);
    cudaGetSymbolAddress((void**)&pO, g_pO);
    cudaGetSymbolAddress((void**)&pm, g_pm);
    cudaGetSymbolAddress((void**)&pl, g_pl);
    {
        __half *p0, *p1, *p2, *p3; float* p4;
        cudaGetSymbolAddress((void**)&p0, g_wqkv);
        cudaGetSymbolAddress((void**)&p1, g_wo);
        cudaGetSymbolAddress((void**)&p2, g_w1);
        cudaGetSymbolAddress((void**)&p3, g_w2);
        cudaGetSymbolAddress((void**)&p4, g_bias3);
        for (int l = 0; l < 2; l++) {
            wqkv[l] = p0 + (size_t)l * 3 * DD * DD;
            wo[l]   = p1 + (size_t)l * DD * DD;
            w1[l]   = p2 + (size_t)l * DD * FFF;
            w2[l]   = p3 + (size_t)l * FFF * DD;
            bias3[l] = p4 + (size_t)l * NQKV;
        }
    }

    // ---- side stream for weight conversion + layer-1 Q-tail GEMM -------------
    static cudaStream_t s2 = nullptr;
    static cudaEvent_t evF, evQ[2], evO[2], ev1[2], ev2[2], evA, evQd;
    if (!s2) {
        cudaStreamCreateWithFlags(&s2, cudaStreamNonBlocking);
        cudaEventCreateWithFlags(&evF, cudaEventDisableTiming);
        cudaEventCreateWithFlags(&evA, cudaEventDisableTiming);
        cudaEventCreateWithFlags(&evQd, cudaEventDisableTiming);
        for (int l = 0; l < 2; l++) {
            cudaEventCreateWithFlags(&evQ[l], cudaEventDisableTiming);
            cudaEventCreateWithFlags(&evO[l], cudaEventDisableTiming);
            cudaEventCreateWithFlags(&ev1[l], cudaEventDisableTiming);
            cudaEventCreateWithFlags(&ev2[l], cudaEventDisableTiming);
        }
    }

    cudaEventRecord(evF, 0);
    cudaStreamWaitEvent(s2, evF, 0);
    for (int l = 0; l < 2; l++) {
        long long wofs = (long long)l * DD * DD;
        conv_wt<<<dim3(DD/32, DD/32), 256, 0, s2>>>(Wq + wofs, wqkv[l],            DD, DD);
        conv_wt<<<dim3(DD/32, DD/32), 256, 0, s2>>>(Wk + wofs, wqkv[l] + DD*DD,    DD, DD);
        conv_wt<<<dim3(DD/32, DD/32), 256, 0, s2>>>(Wv + wofs, wqkv[l] + 2*DD*DD,  DD, DD);
        concat3<<<3, 256, 0, s2>>>(bq + l*DD, bk + l*DD, bv + l*DD, bias3[l]);
        cudaEventRecord(evQ[l], s2);
        conv_wt<<<dim3(DD/32, DD/32), 256, 0, s2>>>(Wo + wofs, wo[l], DD, DD);
        cudaEventRecord(evO[l], s2);
        conv_wt<<<dim3(FFF/32, DD/32), 256, 0, s2>>>(W1 + (long long)l*DD*FFF, w1[l], DD, FFF);
        cudaEventRecord(ev1[l], s2);
        conv_wt<<<dim3(DD/32, FFF/32), 256, 0, s2>>>(W2 + (long long)l*FFF*DD, w2[l], FFF, DD);
        cudaEventRecord(ev2[l], s2);
    }

    embed_ln_split<<<SS, 256>>>(input_ids, word_emb, pos_emb, eln_w, eln_b, h, ah);

    // =========================== layer 0 (full) ===========================
    {
        int l = 0;
        cudaStreamWaitEvent(0, evQ[l], 0);
        gemm_mma<3><<<dim3(NQKV/128, SS/128, 1), 256, GEMM_SMEM>>>(
            ah, wqkv[l], bias3[l], nullptr, nullptr, bh, SS, NQKV, DD, NQKV, 5);

        attn_mma_kernel<<<dim3(HH, 78), 128, ATTN_SMEM>>>(
            bh, rand_attn + l*HH*NBB*RRR, ah, pO, pm, pl, 0);
        attn_combine<<<dim3(24, 64), 64>>>(pO, pm, pl, ah, 1, 0);

        cudaStreamWaitEvent(0, evO[l], 0);
        gemm_mma<3><<<dim3(DD/128, SS/128, 2), 256, GEMM_SMEM>>>(
            ah, wo[l], bo + l*DD, a, a2, nullptr, SS, DD, DD, DD, 0);
        add_ln3<<<SS, 256>>>(h, a, a2, ln1_w + l*DD, ln1_b + l*DD, ah);

        cudaStreamWaitEvent(0, ev1[l], 0);
        gemm_mma<3><<<dim3(FFF/128, SS/128, 1), 256, GEMM_SMEM>>>(
            ah, w1[l], b1 + l*FFF, nullptr, nullptr, bh, SS, FFF, DD, FFF, 4);
        cudaStreamWaitEvent(0, ev2[l], 0);
        gemm_mma<3><<<dim3(DD/128, SS/128, 2), 256, GEMM_SMEM>>>(
            bh, w2[l], b2 + l*DD, a, a2, nullptr, SS, DD, FFF, DD, 0);
        add_ln3<<<SS, 256>>>(h, a, a2, ln2_w + l*DD, ln2_b + l*DD, ah);
    }

    // ================= layer 1 (pruned: only last row matters) =============
    {
        int l = 1;
        const size_t ro768  = (size_t)ROW0 * DD;
        const size_t ro3072 = (size_t)ROW0 * FFF;
        const size_t roqkv  = (size_t)ROW0 * NQKV;

        // ah (layer-0 output) ready on stream 0 here
        cudaEventRecord(evA, 0);

        // Q projection for last 128 rows only -> bh cols [0,768) at rows ROW0..
        cudaStreamWaitEvent(s2, evA, 0);          // s2 already finished all convs
        gemm_mma<3><<<dim3(DD/128, 1, 1), 256, GEMM_SMEM, s2>>>(
            ah + ro768, wqkv[l], bias3[l], nullptr, nullptr, bh + roqkv,
            MTAIL, DD, DD, NQKV, 5);
        cudaEventRecord(evQd, s2);

        // K,V projection for all rows -> bh cols [768,2304)
        cudaStreamWaitEvent(0, evQ[l], 0);
        gemm_mma<3><<<dim3((2*DD)/128, SS/128, 1), 256, GEMM_SMEM>>>(
            ah, wqkv[l] + (size_t)DD * DD, bias3[l] + DD, nullptr, nullptr, bh + DD,
            SS, 2*DD, DD, NQKV, 5);

        // attention: only edge e=1 (q-block 63) chunks -> y = 70..77
        cudaStreamWaitEvent(0, evQd, 0);
        attn_mma_kernel<<<dim3(HH, 8), 128, ATTN_SMEM>>>(
            bh, rand_attn + l*HH*NBB*RRR, ah, pO, pm, pl, 70);
        attn_combine<<<dim3(12, 64), 64>>>(pO, pm, pl, ah, 2, 1);

        // Wo: last 128 rows only
        cudaStreamWaitEvent(0, evO[l], 0);
        gemm_mma<3><<<dim3(DD/128, 1, 2), 256, GEMM_SMEM>>>(
            ah + ro768, wo[l], bo + l*DD, a + ro768, a2 + ro768, nullptr,
            MTAIL, DD, DD, DD, 0);
        add_ln3<<<MTAIL, 256>>>(h + ro768, a + ro768, a2 + ro768,
                                ln1_w + l*DD, ln1_b + l*DD, ah + ro768);

        // FFN: last 128 rows only
        cudaStreamWaitEvent(0, ev1[l], 0);
        gemm_mma<3><<<dim3(FFF/128, 1, 1), 256, GEMM_SMEM>>>(
            ah + ro768, w1[l], b1 + l*FFF, nullptr, nullptr, bh + ro3072,
            MTAIL, FFF, DD, FFF, 4);
        cudaStreamWaitEvent(0, ev2[l], 0);
        gemm_mma<3><<<dim3(DD/128, 1, 2), 256, GEMM_SMEM>>>(
            bh + ro3072, w2[l], b2 + l*DD, a + ro768, a2 + ro768, nullptr,
            MTAIL, DD, FFF, DD, 0);
        add_ln3<<<MTAIL, 256>>>(h + ro768, a + ro768, a2 + ro768,
                                ln2_w + l*DD, ln2_b + l*DD, ah + ro768);
    }

    classifier_kernel<<<1, 256>>>(h, Wc, bc, out);
}